// round 1
// baseline (speedup 1.0000x reference)
#include <cuda_runtime.h>
#include <math.h>

#define BB 8
#define TT 1024
#define IND 80
#define DM 256
#define NH 4
#define DKK 64
#define FFD 2048
#define NL 6
#define PP (2*TT-1)

// ---------------- device scratch (allocation-free) ----------------
__device__ float g_x[BB*TT*DM];          // activations (B,T,256)
__device__ float g_qkv[BB*TT*3*DM];      // (B,T,768)
__device__ float g_pe[PP*DM];            // rel pos encoding (2T-1,256)
__device__ float g_p[PP*DM];             // pe @ pos_W^T       (2T-1,256)
__device__ float g_att[BB*TT*DM];        // attention output   (B,T,256)
__device__ float g_h[BB*TT*FFD];         // ffn hidden         (B,T,2048)
__device__ float g_w[(size_t)BB*NH*TT*TT]; // attn probs (B,H,T,T)

// ---------------- relative positional encoding ----------------
__global__ void pe_kernel() {
    int r = blockIdx.x;       // 0..2T-2
    int d = threadIdx.x;      // 0..255
    float pos, sign;
    if (r < TT) { pos = (float)(TT - 1 - r); sign = 1.f; }
    else        { pos = (float)(r - TT + 1); sign = -1.f; }
    int j2 = (d >> 1) << 1;   // 2*(d/2)
    float div = expf(-(float)j2 * (logf(10000.f) / (float)DM));
    float ang = sign * pos * div;
    g_pe[r * DM + d] = (d & 1) ? cosf(ang) : sinf(ang);
}

// ---------------- generic SGEMM: C = A(MxK) @ W(NxK)^T [+bias][act][+res] ----------------
// act: 0 = none, 1 = double_swish
__global__ __launch_bounds__(256) void gemm_kernel(
    const float* __restrict__ A, const float* __restrict__ W,
    const float* __restrict__ bias, const float* __restrict__ res,
    float* __restrict__ C, int M, int N, int K, int act)
{
    __shared__ float As[16][128];
    __shared__ float Bs[16][128];
    const int bm = blockIdx.y * 128;
    const int bn = blockIdx.x * 128;
    const int tid = threadIdx.x;
    const int tm = tid >> 4, tn = tid & 15;

    float acc[8][8];
#pragma unroll
    for (int i = 0; i < 8; i++)
#pragma unroll
        for (int j = 0; j < 8; j++) acc[i][j] = 0.f;

    for (int k0 = 0; k0 < K; k0 += 16) {
#pragma unroll
        for (int e = 0; e < 8; e++) {
            int flat = tid + e * 256;          // 0..2047
            int row = flat >> 4, kk = flat & 15;
            int ar = bm + row;
            As[kk][row] = (ar < M) ? A[(size_t)ar * K + k0 + kk] : 0.f;
            int wr = bn + row;
            Bs[kk][row] = (wr < N) ? W[(size_t)wr * K + k0 + kk] : 0.f;
        }
        __syncthreads();
#pragma unroll
        for (int kk = 0; kk < 16; kk++) {
            float4 a0 = *(const float4*)&As[kk][tm * 8];
            float4 a1 = *(const float4*)&As[kk][tm * 8 + 4];
            float4 b0 = *(const float4*)&Bs[kk][tn * 8];
            float4 b1 = *(const float4*)&Bs[kk][tn * 8 + 4];
            float a[8] = {a0.x,a0.y,a0.z,a0.w,a1.x,a1.y,a1.z,a1.w};
            float b[8] = {b0.x,b0.y,b0.z,b0.w,b1.x,b1.y,b1.z,b1.w};
#pragma unroll
            for (int i = 0; i < 8; i++)
#pragma unroll
                for (int j = 0; j < 8; j++) acc[i][j] += a[i] * b[j];
        }
        __syncthreads();
    }
#pragma unroll
    for (int i = 0; i < 8; i++) {
        int row = bm + tm * 8 + i;
        if (row >= M) continue;
#pragma unroll
        for (int j = 0; j < 8; j++) {
            int col = bn + tn * 8 + j;
            float c = acc[i][j];
            if (bias) c += bias[col];
            if (act == 1) c = c / (1.f + expf(1.f - c));   // x*sigmoid(x-1)
            if (res) c += res[(size_t)row * N + col];
            C[(size_t)row * N + col] = c;
        }
    }
}

// ---------------- BasicNorm: x * rsqrt(mean(x^2)+0.25) over last dim (256) ----------------
__global__ __launch_bounds__(DM) void norm_kernel(float* __restrict__ x) {
    int row = blockIdx.x, tid = threadIdx.x;
    float v = x[(size_t)row * DM + tid];
    float s = v * v;
#pragma unroll
    for (int o = 16; o; o >>= 1) s += __shfl_xor_sync(0xffffffffu, s, o);
    __shared__ float sm[8];
    int warp = tid >> 5, lane = tid & 31;
    if (lane == 0) sm[warp] = s;
    __syncthreads();
    if (warp == 0) {
        float t = (lane < 8) ? sm[lane] : 0.f;
#pragma unroll
        for (int o = 4; o; o >>= 1) t += __shfl_xor_sync(0xffffffffu, t, o);
        if (lane == 0) sm[0] = t;
    }
    __syncthreads();
    float scale = rsqrtf(sm[0] / (float)DM + 0.25f);
    x[(size_t)row * DM + tid] = v * scale;
}

// ---------------- fused scores + rel-shift + mask + softmax ----------------
// block = (i-row); 128 threads; writes probs for valid j in [0, min(i, len-1)]
__global__ __launch_bounds__(128) void attn_kernel(
    const float* __restrict__ qkv, const float* __restrict__ p,
    const float* __restrict__ ub, const float* __restrict__ vb,
    const int* __restrict__ lens, float* __restrict__ w)
{
    const int i = blockIdx.x, h = blockIdx.y, b = blockIdx.z;
    const int tid = threadIdx.x;
    __shared__ float qu[DKK], qv[DKK];
    __shared__ float sred[4], sred2[4];
    if (tid < DKK) {
        float q = qkv[((size_t)(b * TT + i)) * 768 + h * DKK + tid];
        qu[tid] = q + ub[h * DKK + tid];
        qv[tid] = q + vb[h * DKK + tid];
    }
    __syncthreads();
    const int len = lens[b];
    const int nJ = min(i, len - 1) + 1;

    float s[8];
    float mx = -3.4e38f;
#pragma unroll
    for (int it = 0; it < 8; it++) {
        int j = tid + it * 128;
        float sc = -3.4e38f;
        if (j < nJ) {
            const float4* k4 = (const float4*)(qkv + ((size_t)(b * TT + j)) * 768 + DM + h * DKK);
            const float4* p4 = (const float4*)(p + (size_t)(TT - 1 - i + j) * DM + h * DKK);
            float a = 0.f, c = 0.f;
#pragma unroll
            for (int d = 0; d < 16; d++) {
                float4 kv = k4[d], pv = p4[d];
                a += qu[4*d+0]*kv.x + qu[4*d+1]*kv.y + qu[4*d+2]*kv.z + qu[4*d+3]*kv.w;
                c += qv[4*d+0]*pv.x + qv[4*d+1]*pv.y + qv[4*d+2]*pv.z + qv[4*d+3]*pv.w;
            }
            sc = (a + c) * 0.125f;   // DK^-0.5
            mx = fmaxf(mx, sc);
        }
        s[it] = sc;
    }
    const int lane = tid & 31, warp = tid >> 5;
#pragma unroll
    for (int o = 16; o; o >>= 1) mx = fmaxf(mx, __shfl_xor_sync(0xffffffffu, mx, o));
    if (lane == 0) sred[warp] = mx;
    __syncthreads();
    mx = fmaxf(fmaxf(sred[0], sred[1]), fmaxf(sred[2], sred[3]));

    float sum = 0.f;
#pragma unroll
    for (int it = 0; it < 8; it++) {
        int j = tid + it * 128;
        if (j < nJ) { s[it] = expf(s[it] - mx); sum += s[it]; }
    }
#pragma unroll
    for (int o = 16; o; o >>= 1) sum += __shfl_xor_sync(0xffffffffu, sum, o);
    if (lane == 0) sred2[warp] = sum;
    __syncthreads();
    float inv = 1.f / (sred2[0] + sred2[1] + sred2[2] + sred2[3]);

    float* wrow = w + (((size_t)b * NH + h) * TT + i) * TT;
#pragma unroll
    for (int it = 0; it < 8; it++) {
        int j = tid + it * 128;
        if (j < nJ) wrow[j] = s[it] * inv;
    }
}

// ---------------- att = probs @ V ----------------
__global__ __launch_bounds__(256) void av_kernel(
    const float* __restrict__ qkv, const float* __restrict__ w,
    const int* __restrict__ lens, float* __restrict__ att)
{
    const int i = blockIdx.x, h = blockIdx.y, b = blockIdx.z;
    const int tid = threadIdx.x;
    const int d = tid & 63, g = tid >> 6;    // 4 j-groups x 64 dims
    const int len = lens[b];
    const int nJ = min(i, len - 1) + 1;
    const float* wrow = w + (((size_t)b * NH + h) * TT + i) * TT;
    float acc = 0.f;
    for (int j = g; j < nJ; j += 4)
        acc += wrow[j] * qkv[((size_t)(b * TT + j)) * 768 + 2 * DM + h * DKK + d];
    __shared__ float sm[256];
    sm[tid] = acc;
    __syncthreads();
    if (g == 0)
        att[((size_t)(b * TT + i)) * DM + h * DKK + d] =
            acc + sm[d + 64] + sm[d + 128] + sm[d + 192];
}

// ---------------- final copy (+ x_lens as float if present) ----------------
__global__ void out_kernel(const float* __restrict__ x, const int* __restrict__ lens,
                           float* __restrict__ out, int out_size) {
    int idx = blockIdx.x * 256 + threadIdx.x;
    const int n = BB * TT * DM;
    if (idx < n) out[idx] = x[idx];
    if (idx < BB && out_size >= n + BB) out[n + idx] = (float)lens[idx];
}

extern "C" void kernel_launch(void* const* d_in, const int* in_sizes, int n_in,
                              void* d_out, int out_size) {
    const float* x        = (const float*)d_in[0];
    const int*   lens     = (const int*)  d_in[1];
    const float* embed_W  = (const float*)d_in[2];
    const float* embed_b  = (const float*)d_in[3];
    const float* in_projW = (const float*)d_in[4];
    const float* in_projb = (const float*)d_in[5];
    const float* pos_W    = (const float*)d_in[6];
    const float* pbu      = (const float*)d_in[7];
    const float* pbv      = (const float*)d_in[8];
    const float* out_W    = (const float*)d_in[9];
    const float* out_b    = (const float*)d_in[10];
    const float* ff1_W    = (const float*)d_in[11];
    const float* ff1_b    = (const float*)d_in[12];
    const float* ff2_W    = (const float*)d_in[13];
    const float* ff2_b    = (const float*)d_in[14];

    float *xbuf, *qkvb, *peb, *pbuf, *attb, *hbuf, *wbuf;
    cudaGetSymbolAddress((void**)&xbuf, g_x);
    cudaGetSymbolAddress((void**)&qkvb, g_qkv);
    cudaGetSymbolAddress((void**)&peb,  g_pe);
    cudaGetSymbolAddress((void**)&pbuf, g_p);
    cudaGetSymbolAddress((void**)&attb, g_att);
    cudaGetSymbolAddress((void**)&hbuf, g_h);
    cudaGetSymbolAddress((void**)&wbuf, g_w);

    const int M = BB * TT;           // 8192 rows

    pe_kernel<<<PP, DM>>>();

    // embed + norm_before
    gemm_kernel<<<dim3(DM/128, M/128), 256>>>(x, embed_W, embed_b, nullptr, xbuf, M, DM, IND, 0);
    norm_kernel<<<M, DM>>>(xbuf);

    for (int l = 0; l < NL; l++) {
        // qkv projection
        gemm_kernel<<<dim3(768/128, M/128), 256>>>(
            xbuf, in_projW + (size_t)l*3*DM*DM, in_projb + (size_t)l*3*DM,
            nullptr, qkvb, M, 3*DM, DM, 0);
        // p = pe @ pos_W^T  (no bias)
        gemm_kernel<<<dim3(DM/128, (PP+127)/128), 256>>>(
            peb, pos_W + (size_t)l*DM*DM, nullptr, nullptr, pbuf, PP, DM, DM, 0);
        // scores + softmax
        attn_kernel<<<dim3(TT, NH, BB), 128>>>(
            qkvb, pbuf, pbu + (size_t)l*NH*DKK, pbv + (size_t)l*NH*DKK, lens, wbuf);
        // att = w @ v
        av_kernel<<<dim3(TT, NH, BB), 256>>>(qkvb, wbuf, lens, attb);
        // out projection + residual (in-place into x)
        gemm_kernel<<<dim3(DM/128, M/128), 256>>>(
            attb, out_W + (size_t)l*DM*DM, out_b + (size_t)l*DM, xbuf, xbuf, M, DM, DM, 0);
        // ff1 + double_swish
        gemm_kernel<<<dim3(FFD/128, M/128), 256>>>(
            xbuf, ff1_W + (size_t)l*FFD*DM, ff1_b + (size_t)l*FFD, nullptr, hbuf, M, FFD, DM, 1);
        // ff2 + residual
        gemm_kernel<<<dim3(DM/128, M/128), 256>>>(
            hbuf, ff2_W + (size_t)l*DM*FFD, ff2_b + (size_t)l*DM, xbuf, xbuf, M, DM, FFD, 0);
        // norm_final
        norm_kernel<<<M, DM>>>(xbuf);
    }

    int n = BB * TT * DM;
    out_kernel<<<(n + 255)/256, 256>>>(xbuf, lens, (float*)d_out, out_size);
}

// round 2
// speedup vs baseline: 1.6913x; 1.6913x over previous
#include <cuda_runtime.h>
#include <math.h>

#define BB 8
#define TT 1024
#define IND 80
#define DM 256
#define NH 4
#define DKK 64
#define FFD 2048
#define NL 6
#define PP (2*TT-1)

// ---------------- device scratch (allocation-free) ----------------
__device__ float g_x[BB*TT*DM];          // activations (B,T,256)
__device__ float g_qkv[BB*TT*3*DM];      // (B,T,768)
__device__ float g_pe[PP*DM];            // rel pos encoding (2T-1,256)
__device__ float g_p[PP*DM];             // pe @ pos_W^T       (2T-1,256)
__device__ float g_att[BB*TT*DM];        // attention output   (B,T,256)
__device__ float g_h[BB*TT*FFD];         // ffn hidden         (B,T,2048)

// ---------------- relative positional encoding ----------------
__global__ void pe_kernel() {
    int r = blockIdx.x;
    int d = threadIdx.x;
    float pos, sign;
    if (r < TT) { pos = (float)(TT - 1 - r); sign = 1.f; }
    else        { pos = (float)(r - TT + 1); sign = -1.f; }
    int j2 = (d >> 1) << 1;
    float div = expf(-(float)j2 * (logf(10000.f) / (float)DM));
    float ang = sign * pos * div;
    g_pe[r * DM + d] = (d & 1) ? cosf(ang) : sinf(ang);
}

// ---------------- generic SGEMM: C = A(MxK) @ W(NxK)^T [+bias][act][+res] ----------------
__global__ __launch_bounds__(256) void gemm_kernel(
    const float* __restrict__ A, const float* __restrict__ W,
    const float* __restrict__ bias, const float* __restrict__ res,
    float* __restrict__ C, int M, int N, int K, int act)
{
    __shared__ float As[16][128];
    __shared__ float Bs[16][128];
    const int bm = blockIdx.y * 128;
    const int bn = blockIdx.x * 128;
    const int tid = threadIdx.x;
    const int tm = tid >> 4, tn = tid & 15;

    float acc[8][8];
#pragma unroll
    for (int i = 0; i < 8; i++)
#pragma unroll
        for (int j = 0; j < 8; j++) acc[i][j] = 0.f;

    for (int k0 = 0; k0 < K; k0 += 16) {
#pragma unroll
        for (int e = 0; e < 8; e++) {
            int flat = tid + e * 256;
            int row = flat >> 4, kk = flat & 15;
            int ar = bm + row;
            As[kk][row] = (ar < M) ? A[(size_t)ar * K + k0 + kk] : 0.f;
            int wr = bn + row;
            Bs[kk][row] = (wr < N) ? W[(size_t)wr * K + k0 + kk] : 0.f;
        }
        __syncthreads();
#pragma unroll
        for (int kk = 0; kk < 16; kk++) {
            float4 a0 = *(const float4*)&As[kk][tm * 8];
            float4 a1 = *(const float4*)&As[kk][tm * 8 + 4];
            float4 b0 = *(const float4*)&Bs[kk][tn * 8];
            float4 b1 = *(const float4*)&Bs[kk][tn * 8 + 4];
            float a[8] = {a0.x,a0.y,a0.z,a0.w,a1.x,a1.y,a1.z,a1.w};
            float b[8] = {b0.x,b0.y,b0.z,b0.w,b1.x,b1.y,b1.z,b1.w};
#pragma unroll
            for (int i = 0; i < 8; i++)
#pragma unroll
                for (int j = 0; j < 8; j++) acc[i][j] += a[i] * b[j];
        }
        __syncthreads();
    }
#pragma unroll
    for (int i = 0; i < 8; i++) {
        int row = bm + tm * 8 + i;
        if (row >= M) continue;
#pragma unroll
        for (int j = 0; j < 8; j++) {
            int col = bn + tn * 8 + j;
            float c = acc[i][j];
            if (bias) c += bias[col];
            if (act == 1) c = c / (1.f + expf(1.f - c));
            if (res) c += res[(size_t)row * N + col];
            C[(size_t)row * N + col] = c;
        }
    }
}

// ---------------- BasicNorm ----------------
__global__ __launch_bounds__(DM) void norm_kernel(float* __restrict__ x) {
    int row = blockIdx.x, tid = threadIdx.x;
    float v = x[(size_t)row * DM + tid];
    float s = v * v;
#pragma unroll
    for (int o = 16; o; o >>= 1) s += __shfl_xor_sync(0xffffffffu, s, o);
    __shared__ float sm[8];
    int warp = tid >> 5, lane = tid & 31;
    if (lane == 0) sm[warp] = s;
    __syncthreads();
    if (warp == 0) {
        float t = (lane < 8) ? sm[lane] : 0.f;
#pragma unroll
        for (int o = 4; o; o >>= 1) t += __shfl_xor_sync(0xffffffffu, t, o);
        if (lane == 0) sm[0] = t;
    }
    __syncthreads();
    float scale = rsqrtf(sm[0] / (float)DM + 0.25f);
    x[(size_t)row * DM + tid] = v * scale;
}

// ================= fused flash attention =================
// grid (T/64, NH, BB), 256 threads. i-tile 64, j-tile 64.
// smem layout (floats):
#define SQ_U   0                      // qu[64][68]
#define SQ_V   (SQ_U + 64*68)         // qv[64][68]
#define SK_T   (SQ_V + 64*68)         // Kt_T[64 d][68] (cols j)
#define SV_T   (SK_T + 64*68)         // Vt[64 j][68]   (cols d)
#define SP_T   (SV_T + 64*68)         // Pt_T[64 d][128] (cols r, 127 used)
#define SQP    (SP_T + 64*128)        // QP[64 i][128]
#define SS     (SQP + 64*128)         // S[64][68]
#define SMR    (SS + 64*68)           // mrow[64]
#define SLR    (SMR + 64)             // lrow[64]
#define SFR    (SLR + 64)             // frow[64]
#define FL_SMEM ((SFR + 64) * 4)

__global__ __launch_bounds__(256) void flash_kernel(
    const float* __restrict__ qkv, const float* __restrict__ p,
    const float* __restrict__ ub, const float* __restrict__ vb,
    const int* __restrict__ lens, float* __restrict__ att)
{
    extern __shared__ float sm[];
    const int i0 = blockIdx.x * 64;
    const int h  = blockIdx.y;
    const int b  = blockIdx.z;
    const int tid = threadIdx.x;
    const int len = lens[b];

    // ---- prologue: load qu = q + ub, qv = q + vb; init stats ----
#pragma unroll
    for (int e = 0; e < 4; e++) {
        int f4 = tid + e * 256;            // 0..1023
        int row = f4 >> 4, c = (f4 & 15) * 4;
        float4 q4 = *(const float4*)&qkv[((size_t)(b * TT + i0 + row)) * 768 + h * DKK + c];
        float4 u4 = *(const float4*)&ub[h * DKK + c];
        float4 v4 = *(const float4*)&vb[h * DKK + c];
        float4 a; a.x = q4.x + u4.x; a.y = q4.y + u4.y; a.z = q4.z + u4.z; a.w = q4.w + u4.w;
        float4 bb2; bb2.x = q4.x + v4.x; bb2.y = q4.y + v4.y; bb2.z = q4.z + v4.z; bb2.w = q4.w + v4.w;
        *(float4*)&sm[SQ_U + row * 68 + c] = a;
        *(float4*)&sm[SQ_V + row * 68 + c] = bb2;
    }
    if (tid < 64) { sm[SMR + tid] = -3.4e38f; sm[SLR + tid] = 0.f; }

    float o[16];
#pragma unroll
    for (int q = 0; q < 16; q++) o[q] = 0.f;

    const int ti = tid >> 4, tj = tid & 15;     // gemm maps
    const int rg = tid >> 2, dg = tid & 3;      // row/softmax/AV maps

    for (int j0 = 0; j0 <= i0; j0 += 64) {
        __syncthreads();   // prev AV done / prologue done
        // ---- load K (transposed), V ----
#pragma unroll
        for (int e = 0; e < 4; e++) {
            int f4 = tid + e * 256;
            int j = f4 >> 4, c = (f4 & 15) * 4;
            const float* base = &qkv[((size_t)(b * TT + j0 + j)) * 768 + h * DKK + c];
            float4 k4 = *(const float4*)(base + DM);
            float4 v4 = *(const float4*)(base + 2 * DM);
            sm[SK_T + (c + 0) * 68 + j] = k4.x;
            sm[SK_T + (c + 1) * 68 + j] = k4.y;
            sm[SK_T + (c + 2) * 68 + j] = k4.z;
            sm[SK_T + (c + 3) * 68 + j] = k4.w;
            *(float4*)&sm[SV_T + j * 68 + c] = v4;
        }
        // ---- load P rows (transposed): 127 rows ----
        const int pbase = TT - 1 - (i0 + 63) + j0;
#pragma unroll
        for (int e = 0; e < 8; e++) {
            int f4 = tid + e * 256;
            if (f4 < 127 * 16) {
                int r = f4 >> 4, c = (f4 & 15) * 4;
                float4 p4 = *(const float4*)&p[(size_t)(pbase + r) * DM + h * DKK + c];
                sm[SP_T + (c + 0) * 128 + r] = p4.x;
                sm[SP_T + (c + 1) * 128 + r] = p4.y;
                sm[SP_T + (c + 2) * 128 + r] = p4.z;
                sm[SP_T + (c + 3) * 128 + r] = p4.w;
            }
        }
        __syncthreads();

        // ---- gemm2: QP[ii][r] = qv[ii] . P[r], ii=4ti+iq, r=8tj+k ----
        {
            float acc[4][8];
#pragma unroll
            for (int iq = 0; iq < 4; iq++)
#pragma unroll
                for (int k = 0; k < 8; k++) acc[iq][k] = 0.f;
            for (int d4 = 0; d4 < 64; d4 += 4) {
                float qa[4][4];
#pragma unroll
                for (int iq = 0; iq < 4; iq++)
                    *(float4*)&qa[iq][0] = *(const float4*)&sm[SQ_V + (ti * 4 + iq) * 68 + d4];
#pragma unroll
                for (int dq = 0; dq < 4; dq++) {
                    float4 p0 = *(const float4*)&sm[SP_T + (d4 + dq) * 128 + tj * 8];
                    float4 p1 = *(const float4*)&sm[SP_T + (d4 + dq) * 128 + tj * 8 + 4];
#pragma unroll
                    for (int iq = 0; iq < 4; iq++) {
                        float a = qa[iq][dq];
                        acc[iq][0] += a * p0.x; acc[iq][1] += a * p0.y;
                        acc[iq][2] += a * p0.z; acc[iq][3] += a * p0.w;
                        acc[iq][4] += a * p1.x; acc[iq][5] += a * p1.y;
                        acc[iq][6] += a * p1.z; acc[iq][7] += a * p1.w;
                    }
                }
            }
#pragma unroll
            for (int iq = 0; iq < 4; iq++) {
                *(float4*)&sm[SQP + (ti * 4 + iq) * 128 + tj * 8]     = *(float4*)&acc[iq][0];
                *(float4*)&sm[SQP + (ti * 4 + iq) * 128 + tj * 8 + 4] = *(float4*)&acc[iq][4];
            }
        }
        __syncthreads();

        // ---- gemm1: S = (qu . K^T + QP-shift) * scale ----
        {
            float acc[4][4];
#pragma unroll
            for (int iq = 0; iq < 4; iq++)
#pragma unroll
                for (int jq = 0; jq < 4; jq++) acc[iq][jq] = 0.f;
            for (int d4 = 0; d4 < 64; d4 += 4) {
                float qa[4][4];
#pragma unroll
                for (int iq = 0; iq < 4; iq++)
                    *(float4*)&qa[iq][0] = *(const float4*)&sm[SQ_U + (ti * 4 + iq) * 68 + d4];
#pragma unroll
                for (int dq = 0; dq < 4; dq++) {
                    float4 kv = *(const float4*)&sm[SK_T + (d4 + dq) * 68 + tj * 4];
#pragma unroll
                    for (int iq = 0; iq < 4; iq++) {
                        float a = qa[iq][dq];
                        acc[iq][0] += a * kv.x; acc[iq][1] += a * kv.y;
                        acc[iq][2] += a * kv.z; acc[iq][3] += a * kv.w;
                    }
                }
            }
#pragma unroll
            for (int iq = 0; iq < 4; iq++) {
                int ii = ti * 4 + iq;
                float4 sv;
                sv.x = (acc[iq][0] + sm[SQP + ii * 128 + 63 - ii + tj * 4 + 0]) * 0.125f;
                sv.y = (acc[iq][1] + sm[SQP + ii * 128 + 63 - ii + tj * 4 + 1]) * 0.125f;
                sv.z = (acc[iq][2] + sm[SQP + ii * 128 + 63 - ii + tj * 4 + 2]) * 0.125f;
                sv.w = (acc[iq][3] + sm[SQP + ii * 128 + 63 - ii + tj * 4 + 3]) * 0.125f;
                *(float4*)&sm[SS + ii * 68 + tj * 4] = sv;
            }
        }
        __syncthreads();

        // ---- online softmax update (4 threads per row) ----
        {
            const int i = i0 + rg;
            float mloc = -3.4e38f;
#pragma unroll
            for (int k = 0; k < 16; k++) {
                int jj = dg + k * 4;
                int j = j0 + jj;
                bool ok = (j <= i) && (j < len);
                float v = ok ? sm[SS + rg * 68 + jj] : -3.4e38f;
                mloc = fmaxf(mloc, v);
            }
            mloc = fmaxf(mloc, __shfl_xor_sync(0xffffffffu, mloc, 1));
            mloc = fmaxf(mloc, __shfl_xor_sync(0xffffffffu, mloc, 2));
            float mold = sm[SMR + rg];
            float mnew = fmaxf(mold, mloc);
            float fac = expf(mold - mnew);
            float ssum = 0.f;
#pragma unroll
            for (int k = 0; k < 16; k++) {
                int jj = dg + k * 4;
                int j = j0 + jj;
                bool ok = (j <= i) && (j < len);
                float e = ok ? expf(sm[SS + rg * 68 + jj] - mnew) : 0.f;
                sm[SS + rg * 68 + jj] = e;
                ssum += e;
            }
            ssum += __shfl_xor_sync(0xffffffffu, ssum, 1);
            ssum += __shfl_xor_sync(0xffffffffu, ssum, 2);
            if (dg == 0) {
                sm[SMR + rg] = mnew;
                sm[SLR + rg] = sm[SLR + rg] * fac + ssum;
                sm[SFR + rg] = fac;
            }
        }
        __syncthreads();

        // ---- AV accumulate: O[rg][d] = O*fac + S[rg][:] @ V ----
        {
            float fac = sm[SFR + rg];
#pragma unroll
            for (int q = 0; q < 16; q++) o[q] *= fac;
            for (int j = 0; j < 64; j++) {
                float w = sm[SS + rg * 68 + j];
                float4 v0 = *(const float4*)&sm[SV_T + j * 68 + dg * 16 + 0];
                float4 v1 = *(const float4*)&sm[SV_T + j * 68 + dg * 16 + 4];
                float4 v2 = *(const float4*)&sm[SV_T + j * 68 + dg * 16 + 8];
                float4 v3 = *(const float4*)&sm[SV_T + j * 68 + dg * 16 + 12];
                o[0]  += w * v0.x; o[1]  += w * v0.y; o[2]  += w * v0.z; o[3]  += w * v0.w;
                o[4]  += w * v1.x; o[5]  += w * v1.y; o[6]  += w * v1.z; o[7]  += w * v1.w;
                o[8]  += w * v2.x; o[9]  += w * v2.y; o[10] += w * v2.z; o[11] += w * v2.w;
                o[12] += w * v3.x; o[13] += w * v3.y; o[14] += w * v3.z; o[15] += w * v3.w;
            }
        }
    }

    // ---- epilogue: normalize and write ----
    float inv = 1.f / sm[SLR + rg];
    float* dst = &att[((size_t)(b * TT + i0 + rg)) * DM + h * DKK + dg * 16];
#pragma unroll
    for (int q4 = 0; q4 < 4; q4++) {
        float4 w;
        w.x = o[q4 * 4 + 0] * inv; w.y = o[q4 * 4 + 1] * inv;
        w.z = o[q4 * 4 + 2] * inv; w.w = o[q4 * 4 + 3] * inv;
        *(float4*)(dst + q4 * 4) = w;
    }
}

// ---------------- final copy ----------------
__global__ void out_kernel(const float* __restrict__ x, const int* __restrict__ lens,
                           float* __restrict__ out, int out_size) {
    int idx = blockIdx.x * 256 + threadIdx.x;
    const int n = BB * TT * DM;
    if (idx < n) out[idx] = x[idx];
    if (idx < BB && out_size >= n + BB) out[n + idx] = (float)lens[idx];
}

extern "C" void kernel_launch(void* const* d_in, const int* in_sizes, int n_in,
                              void* d_out, int out_size) {
    const float* x        = (const float*)d_in[0];
    const int*   lens     = (const int*)  d_in[1];
    const float* embed_W  = (const float*)d_in[2];
    const float* embed_b  = (const float*)d_in[3];
    const float* in_projW = (const float*)d_in[4];
    const float* in_projb = (const float*)d_in[5];
    const float* pos_W    = (const float*)d_in[6];
    const float* pbu      = (const float*)d_in[7];
    const float* pbv      = (const float*)d_in[8];
    const float* out_W    = (const float*)d_in[9];
    const float* out_b    = (const float*)d_in[10];
    const float* ff1_W    = (const float*)d_in[11];
    const float* ff1_b    = (const float*)d_in[12];
    const float* ff2_W    = (const float*)d_in[13];
    const float* ff2_b    = (const float*)d_in[14];

    float *xbuf, *qkvb, *peb, *pbuf, *attb, *hbuf;
    cudaGetSymbolAddress((void**)&xbuf, g_x);
    cudaGetSymbolAddress((void**)&qkvb, g_qkv);
    cudaGetSymbolAddress((void**)&peb,  g_pe);
    cudaGetSymbolAddress((void**)&pbuf, g_p);
    cudaGetSymbolAddress((void**)&attb, g_att);
    cudaGetSymbolAddress((void**)&hbuf, g_h);

    cudaFuncSetAttribute(flash_kernel, cudaFuncAttributeMaxDynamicSharedMemorySize, FL_SMEM);

    const int M = BB * TT;

    pe_kernel<<<PP, DM>>>();
    gemm_kernel<<<dim3(DM/128, M/128), 256>>>(x, embed_W, embed_b, nullptr, xbuf, M, DM, IND, 0);
    norm_kernel<<<M, DM>>>(xbuf);

    for (int l = 0; l < NL; l++) {
        gemm_kernel<<<dim3(768/128, M/128), 256>>>(
            xbuf, in_projW + (size_t)l*3*DM*DM, in_projb + (size_t)l*3*DM,
            nullptr, qkvb, M, 3*DM, DM, 0);
        gemm_kernel<<<dim3(DM/128, (PP+127)/128), 256>>>(
            peb, pos_W + (size_t)l*DM*DM, nullptr, nullptr, pbuf, PP, DM, DM, 0);
        flash_kernel<<<dim3(TT/64, NH, BB), 256, FL_SMEM>>>(
            qkvb, pbuf, pbu + (size_t)l*NH*DKK, pbv + (size_t)l*NH*DKK, lens, attb);
        gemm_kernel<<<dim3(DM/128, M/128), 256>>>(
            attb, out_W + (size_t)l*DM*DM, out_b + (size_t)l*DM, xbuf, xbuf, M, DM, DM, 0);
        gemm_kernel<<<dim3(FFD/128, M/128), 256>>>(
            xbuf, ff1_W + (size_t)l*FFD*DM, ff1_b + (size_t)l*FFD, nullptr, hbuf, M, FFD, DM, 1);
        gemm_kernel<<<dim3(DM/128, M/128), 256>>>(
            hbuf, ff2_W + (size_t)l*DM*FFD, ff2_b + (size_t)l*DM, xbuf, xbuf, M, DM, FFD, 0);
        norm_kernel<<<M, DM>>>(xbuf);
    }

    int n = BB * TT * DM;
    out_kernel<<<(n + 255)/256, 256>>>(xbuf, lens, (float*)d_out, out_size);
}

// round 8
// speedup vs baseline: 2.3643x; 1.3979x over previous
#include <cuda_runtime.h>
#include <math.h>
#include <stdint.h>

#define BB 8
#define TT 1024
#define IND 80
#define DM 256
#define NH 4
#define DKK 64
#define FFD 2048
#define NL 6
#define PP (2*TT-1)

// ---------------- device scratch (allocation-free) ----------------
__device__ float g_x[BB*TT*DM];
__device__ float g_qkv[BB*TT*3*DM];
__device__ float g_pe[PP*DM];
__device__ float g_p[PP*DM];
__device__ float g_att[BB*TT*DM];
__device__ float g_h[BB*TT*FFD];

// ================= helpers =================
__device__ __forceinline__ uint32_t smem_u32(const void* p) {
    uint32_t a;
    asm("{ .reg .u64 t; cvta.to.shared.u64 t, %1; cvt.u32.u64 %0, t; }" : "=r"(a) : "l"(p));
    return a;
}
__device__ __forceinline__ float tf32r(float x) {
    uint32_t u;
    asm("cvt.rna.tf32.f32 %0, %1;" : "=r"(u) : "f"(x));
    return __uint_as_float(u);
}
__device__ __forceinline__ void ldsm4(uint32_t* r, uint32_t addr) {
    asm volatile("ldmatrix.sync.aligned.m8n8.x4.shared.b16 {%0,%1,%2,%3}, [%4];"
        : "=r"(r[0]), "=r"(r[1]), "=r"(r[2]), "=r"(r[3]) : "r"(addr));
}
__device__ __forceinline__ void mma_tf32(float* c, const uint32_t* a, const uint32_t* b) {
    asm volatile(
        "mma.sync.aligned.m16n8k8.row.col.f32.tf32.tf32.f32 "
        "{%0,%1,%2,%3}, {%4,%5,%6,%7}, {%8,%9}, {%0,%1,%2,%3};"
        : "+f"(c[0]), "+f"(c[1]), "+f"(c[2]), "+f"(c[3])
        : "r"(a[0]), "r"(a[1]), "r"(a[2]), "r"(a[3]), "r"(b[0]), "r"(b[1]));
}
#define STS4(addr, v) asm volatile("st.shared.v4.b32 [%0], {%1,%2,%3,%4};" :: "r"(addr), \
    "r"(__float_as_uint((v).x)), "r"(__float_as_uint((v).y)), \
    "r"(__float_as_uint((v).z)), "r"(__float_as_uint((v).w)) : "memory")

// ================= mma.sync tf32x3 GEMM: C = A(MxK) @ W(NxK)^T =================
// M,N multiples of 128; K multiple of 32. act: 0 none, 1 double_swish.
// smem tiles: [128 rows][36 floats] (32 k + 4 pad), 4 tiles (Ah, Al, Bh, Bl)
#define TROW 36
#define TCS_A_HI 0
#define TCS_A_LO (128*TROW)
#define TCS_B_HI (2*128*TROW)
#define TCS_B_LO (3*128*TROW)
#define MMA_SMEM (4*128*TROW*4)

__global__ __launch_bounds__(256) void mma_gemm(
    const float* __restrict__ A, const float* __restrict__ W,
    const float* __restrict__ bias, const float* __restrict__ res,
    float* __restrict__ C, int M, int N, int K, int act)
{
    extern __shared__ float dsm[];
    const uint32_t sb = smem_u32(dsm);
    const int tid = threadIdx.x;
    const int wid = tid >> 5, lane = tid & 31;
    const int wm = wid >> 2, wn = wid & 3;          // warp grid 2x4
    const int bm = blockIdx.y * 128, bn = blockIdx.x * 128;

    float c[4][4][4];
#pragma unroll
    for (int mt = 0; mt < 4; mt++)
#pragma unroll
        for (int nt = 0; nt < 4; nt++)
#pragma unroll
            for (int q = 0; q < 4; q++) c[mt][nt][q] = 0.f;

    // ldmatrix lane addressing
    const int quad = lane >> 3, r8 = lane & 7;
    const int a_row = wm * 64 + r8 + (quad & 1) * 8;   // + mt*16
    const int a_col = (quad >> 1) * 4;
    const int b_row = wn * 32 + r8 + (quad >> 1) * 8;  // + (ntile-pair)*16
    const int b_col = (quad & 1) * 4;

    const int srow = tid >> 3, skq = tid & 7;          // staging map

    for (int k0 = 0; k0 < K; k0 += 32) {
        // ---- stage hi/lo tiles ----
#pragma unroll
        for (int e = 0; e < 4; e++) {
            int row = srow + e * 32;                   // 0..127
            float4 a4 = *(const float4*)&A[(size_t)(bm + row) * K + k0 + skq * 4];
            float4 w4 = *(const float4*)&W[(size_t)(bn + row) * K + k0 + skq * 4];
            uint32_t off = (uint32_t)(row * TROW + skq * 4) * 4;
            float4 h, l;
            h.x = tf32r(a4.x); h.y = tf32r(a4.y); h.z = tf32r(a4.z); h.w = tf32r(a4.w);
            l.x = tf32r(a4.x - h.x); l.y = tf32r(a4.y - h.y);
            l.z = tf32r(a4.z - h.z); l.w = tf32r(a4.w - h.w);
            STS4(sb + TCS_A_HI * 4 + off, h);
            STS4(sb + TCS_A_LO * 4 + off, l);
            h.x = tf32r(w4.x); h.y = tf32r(w4.y); h.z = tf32r(w4.z); h.w = tf32r(w4.w);
            l.x = tf32r(w4.x - h.x); l.y = tf32r(w4.y - h.y);
            l.z = tf32r(w4.z - h.z); l.w = tf32r(w4.w - h.w);
            STS4(sb + TCS_B_HI * 4 + off, h);
            STS4(sb + TCS_B_LO * 4 + off, l);
        }
        __syncthreads();

#pragma unroll
        for (int ks = 0; ks < 4; ks++) {
            uint32_t ah[4][4], al[4][4], bh[4][2], bl[4][2];
#pragma unroll
            for (int mt = 0; mt < 4; mt++) {
                uint32_t ao = (uint32_t)((a_row + mt * 16) * TROW + ks * 8 + a_col) * 4;
                ldsm4(ah[mt], sb + TCS_A_HI * 4 + ao);
                ldsm4(al[mt], sb + TCS_A_LO * 4 + ao);
            }
            {
                uint32_t t[4];
                uint32_t bo = (uint32_t)(b_row * TROW + ks * 8 + b_col) * 4;
                ldsm4(t, sb + TCS_B_HI * 4 + bo);
                bh[0][0] = t[0]; bh[0][1] = t[1]; bh[1][0] = t[2]; bh[1][1] = t[3];
                ldsm4(t, sb + TCS_B_HI * 4 + bo + 16 * TROW * 4);
                bh[2][0] = t[0]; bh[2][1] = t[1]; bh[3][0] = t[2]; bh[3][1] = t[3];
                ldsm4(t, sb + TCS_B_LO * 4 + bo);
                bl[0][0] = t[0]; bl[0][1] = t[1]; bl[1][0] = t[2]; bl[1][1] = t[3];
                ldsm4(t, sb + TCS_B_LO * 4 + bo + 16 * TROW * 4);
                bl[2][0] = t[0]; bl[2][1] = t[1]; bl[3][0] = t[2]; bl[3][1] = t[3];
            }
#pragma unroll
            for (int mt = 0; mt < 4; mt++)
#pragma unroll
                for (int nt = 0; nt < 4; nt++) {
                    mma_tf32(c[mt][nt], ah[mt], bh[nt]);
                    mma_tf32(c[mt][nt], al[mt], bh[nt]);
                    mma_tf32(c[mt][nt], ah[mt], bl[nt]);
                }
        }
        __syncthreads();
    }

    // ---- epilogue ----
    const int g = lane >> 2, tq = lane & 3;
#pragma unroll
    for (int mt = 0; mt < 4; mt++) {
#pragma unroll
        for (int nt = 0; nt < 4; nt++) {
            int col = bn + wn * 32 + nt * 8 + tq * 2;
            float b0 = 0.f, b1 = 0.f;
            if (bias) { b0 = bias[col]; b1 = bias[col + 1]; }
#pragma unroll
            for (int half = 0; half < 2; half++) {
                int row = bm + wm * 64 + mt * 16 + g + half * 8;
                float v0 = c[mt][nt][half * 2 + 0] + b0;
                float v1 = c[mt][nt][half * 2 + 1] + b1;
                if (act == 1) {
                    v0 = v0 / (1.f + expf(1.f - v0));
                    v1 = v1 / (1.f + expf(1.f - v1));
                }
                if (res) {
                    const float2 r2 = *(const float2*)&res[(size_t)row * N + col];
                    v0 += r2.x; v1 += r2.y;
                }
                float2 o2; o2.x = v0; o2.y = v1;
                *(float2*)&C[(size_t)row * N + col] = o2;
            }
        }
    }
}

// ---------------- relative positional encoding ----------------
__global__ void pe_kernel() {
    int r = blockIdx.x;
    int d = threadIdx.x;
    float pos, sign;
    if (r < TT) { pos = (float)(TT - 1 - r); sign = 1.f; }
    else        { pos = (float)(r - TT + 1); sign = -1.f; }
    int j2 = (d >> 1) << 1;
    float div = expf(-(float)j2 * (logf(10000.f) / (float)DM));
    float ang = sign * pos * div;
    g_pe[r * DM + d] = (d & 1) ? cosf(ang) : sinf(ang);
}

// ---------------- fallback SGEMM (embed, p) ----------------
__global__ __launch_bounds__(256) void gemm_kernel(
    const float* __restrict__ A, const float* __restrict__ W,
    const float* __restrict__ bias, const float* __restrict__ res,
    float* __restrict__ C, int M, int N, int K, int act)
{
    __shared__ float As[16][128];
    __shared__ float Bs[16][128];
    const int bm = blockIdx.y * 128;
    const int bn = blockIdx.x * 128;
    const int tid = threadIdx.x;
    const int tm = tid >> 4, tn = tid & 15;

    float acc[8][8];
#pragma unroll
    for (int i = 0; i < 8; i++)
#pragma unroll
        for (int j = 0; j < 8; j++) acc[i][j] = 0.f;

    for (int k0 = 0; k0 < K; k0 += 16) {
#pragma unroll
        for (int e = 0; e < 8; e++) {
            int flat = tid + e * 256;
            int row = flat >> 4, kk = flat & 15;
            int ar = bm + row;
            As[kk][row] = (ar < M) ? A[(size_t)ar * K + k0 + kk] : 0.f;
            int wr = bn + row;
            Bs[kk][row] = (wr < N) ? W[(size_t)wr * K + k0 + kk] : 0.f;
        }
        __syncthreads();
#pragma unroll
        for (int kk = 0; kk < 16; kk++) {
            float4 a0 = *(const float4*)&As[kk][tm * 8];
            float4 a1 = *(const float4*)&As[kk][tm * 8 + 4];
            float4 b0 = *(const float4*)&Bs[kk][tn * 8];
            float4 b1 = *(const float4*)&Bs[kk][tn * 8 + 4];
            float a[8] = {a0.x,a0.y,a0.z,a0.w,a1.x,a1.y,a1.z,a1.w};
            float b[8] = {b0.x,b0.y,b0.z,b0.w,b1.x,b1.y,b1.z,b1.w};
#pragma unroll
            for (int i = 0; i < 8; i++)
#pragma unroll
                for (int j = 0; j < 8; j++) acc[i][j] += a[i] * b[j];
        }
        __syncthreads();
    }
#pragma unroll
    for (int i = 0; i < 8; i++) {
        int row = bm + tm * 8 + i;
        if (row >= M) continue;
#pragma unroll
        for (int j = 0; j < 8; j++) {
            int col = bn + tn * 8 + j;
            float c = acc[i][j];
            if (bias) c += bias[col];
            if (act == 1) c = c / (1.f + expf(1.f - c));
            if (res) c += res[(size_t)row * N + col];
            C[(size_t)row * N + col] = c;
        }
    }
}

// ---------------- BasicNorm ----------------
__global__ __launch_bounds__(DM) void norm_kernel(float* __restrict__ x) {
    int row = blockIdx.x, tid = threadIdx.x;
    float v = x[(size_t)row * DM + tid];
    float s = v * v;
#pragma unroll
    for (int o = 16; o; o >>= 1) s += __shfl_xor_sync(0xffffffffu, s, o);
    __shared__ float sm[8];
    int warp = tid >> 5, lane = tid & 31;
    if (lane == 0) sm[warp] = s;
    __syncthreads();
    if (warp == 0) {
        float t = (lane < 8) ? sm[lane] : 0.f;
#pragma unroll
        for (int o = 4; o; o >>= 1) t += __shfl_xor_sync(0xffffffffu, t, o);
        if (lane == 0) sm[0] = t;
    }
    __syncthreads();
    float scale = rsqrtf(sm[0] / (float)DM + 0.25f);
    x[(size_t)row * DM + tid] = v * scale;
}

// ================= fused flash attention =================
#define SQ_U   0
#define SQ_V   (SQ_U + 64*68)
#define SK_T   (SQ_V + 64*68)
#define SV_T   (SK_T + 64*68)
#define SP_T   (SV_T + 64*68)
#define SQP    (SP_T + 64*128)
#define SS     (SQP + 64*128)
#define SMR    (SS + 64*68)
#define SLR    (SMR + 64)
#define SFR    (SLR + 64)
#define FL_SMEM ((SFR + 64) * 4)

__global__ __launch_bounds__(256) void flash_kernel(
    const float* __restrict__ qkv, const float* __restrict__ p,
    const float* __restrict__ ub, const float* __restrict__ vb,
    const int* __restrict__ lens, float* __restrict__ att)
{
    extern __shared__ float sm[];
    const int i0 = blockIdx.x * 64;
    const int h  = blockIdx.y;
    const int b  = blockIdx.z;
    const int tid = threadIdx.x;
    const int len = lens[b];

#pragma unroll
    for (int e = 0; e < 4; e++) {
        int f4 = tid + e * 256;
        int row = f4 >> 4, c = (f4 & 15) * 4;
        float4 q4 = *(const float4*)&qkv[((size_t)(b * TT + i0 + row)) * 768 + h * DKK + c];
        float4 u4 = *(const float4*)&ub[h * DKK + c];
        float4 v4 = *(const float4*)&vb[h * DKK + c];
        float4 a; a.x = q4.x + u4.x; a.y = q4.y + u4.y; a.z = q4.z + u4.z; a.w = q4.w + u4.w;
        float4 bb2; bb2.x = q4.x + v4.x; bb2.y = q4.y + v4.y; bb2.z = q4.z + v4.z; bb2.w = q4.w + v4.w;
        *(float4*)&sm[SQ_U + row * 68 + c] = a;
        *(float4*)&sm[SQ_V + row * 68 + c] = bb2;
    }
    if (tid < 64) { sm[SMR + tid] = -3.4e38f; sm[SLR + tid] = 0.f; }

    float o[16];
#pragma unroll
    for (int q = 0; q < 16; q++) o[q] = 0.f;

    const int ti = tid >> 4, tj = tid & 15;
    const int rg = tid >> 2, dg = tid & 3;

    for (int j0 = 0; j0 <= i0; j0 += 64) {
        __syncthreads();
#pragma unroll
        for (int e = 0; e < 4; e++) {
            int f4 = tid + e * 256;
            int j = f4 >> 4, c = (f4 & 15) * 4;
            const float* base = &qkv[((size_t)(b * TT + j0 + j)) * 768 + h * DKK + c];
            float4 k4 = *(const float4*)(base + DM);
            float4 v4 = *(const float4*)(base + 2 * DM);
            sm[SK_T + (c + 0) * 68 + j] = k4.x;
            sm[SK_T + (c + 1) * 68 + j] = k4.y;
            sm[SK_T + (c + 2) * 68 + j] = k4.z;
            sm[SK_T + (c + 3) * 68 + j] = k4.w;
            *(float4*)&sm[SV_T + j * 68 + c] = v4;
        }
        const int pbase = TT - 1 - (i0 + 63) + j0;
#pragma unroll
        for (int e = 0; e < 8; e++) {
            int f4 = tid + e * 256;
            if (f4 < 127 * 16) {
                int r = f4 >> 4, c = (f4 & 15) * 4;
                float4 p4 = *(const float4*)&p[(size_t)(pbase + r) * DM + h * DKK + c];
                sm[SP_T + (c + 0) * 128 + r] = p4.x;
                sm[SP_T + (c + 1) * 128 + r] = p4.y;
                sm[SP_T + (c + 2) * 128 + r] = p4.z;
                sm[SP_T + (c + 3) * 128 + r] = p4.w;
            }
        }
        __syncthreads();

        {
            float acc[4][8];
#pragma unroll
            for (int iq = 0; iq < 4; iq++)
#pragma unroll
                for (int k = 0; k < 8; k++) acc[iq][k] = 0.f;
            for (int d4 = 0; d4 < 64; d4 += 4) {
                float qa[4][4];
#pragma unroll
                for (int iq = 0; iq < 4; iq++)
                    *(float4*)&qa[iq][0] = *(const float4*)&sm[SQ_V + (ti * 4 + iq) * 68 + d4];
#pragma unroll
                for (int dq = 0; dq < 4; dq++) {
                    float4 p0 = *(const float4*)&sm[SP_T + (d4 + dq) * 128 + tj * 8];
                    float4 p1 = *(const float4*)&sm[SP_T + (d4 + dq) * 128 + tj * 8 + 4];
#pragma unroll
                    for (int iq = 0; iq < 4; iq++) {
                        float a = qa[iq][dq];
                        acc[iq][0] += a * p0.x; acc[iq][1] += a * p0.y;
                        acc[iq][2] += a * p0.z; acc[iq][3] += a * p0.w;
                        acc[iq][4] += a * p1.x; acc[iq][5] += a * p1.y;
                        acc[iq][6] += a * p1.z; acc[iq][7] += a * p1.w;
                    }
                }
            }
#pragma unroll
            for (int iq = 0; iq < 4; iq++) {
                *(float4*)&sm[SQP + (ti * 4 + iq) * 128 + tj * 8]     = *(float4*)&acc[iq][0];
                *(float4*)&sm[SQP + (ti * 4 + iq) * 128 + tj * 8 + 4] = *(float4*)&acc[iq][4];
            }
        }
        __syncthreads();

        {
            float acc[4][4];
#pragma unroll
            for (int iq = 0; iq < 4; iq++)
#pragma unroll
                for (int jq = 0; jq < 4; jq++) acc[iq][jq] = 0.f;
            for (int d4 = 0; d4 < 64; d4 += 4) {
                float qa[4][4];
#pragma unroll
                for (int iq = 0; iq < 4; iq++)
                    *(float4*)&qa[iq][0] = *(const float4*)&sm[SQ_U + (ti * 4 + iq) * 68 + d4];
#pragma unroll
                for (int dq = 0; dq < 4; dq++) {
                    float4 kv = *(const float4*)&sm[SK_T + (d4 + dq) * 68 + tj * 4];
#pragma unroll
                    for (int iq = 0; iq < 4; iq++) {
                        float a = qa[iq][dq];
                        acc[iq][0] += a * kv.x; acc[iq][1] += a * kv.y;
                        acc[iq][2] += a * kv.z; acc[iq][3] += a * kv.w;
                    }
                }
            }
#pragma unroll
            for (int iq = 0; iq < 4; iq++) {
                int ii = ti * 4 + iq;
                float4 sv;
                sv.x = (acc[iq][0] + sm[SQP + ii * 128 + 63 - ii + tj * 4 + 0]) * 0.125f;
                sv.y = (acc[iq][1] + sm[SQP + ii * 128 + 63 - ii + tj * 4 + 1]) * 0.125f;
                sv.z = (acc[iq][2] + sm[SQP + ii * 128 + 63 - ii + tj * 4 + 2]) * 0.125f;
                sv.w = (acc[iq][3] + sm[SQP + ii * 128 + 63 - ii + tj * 4 + 3]) * 0.125f;
                *(float4*)&sm[SS + ii * 68 + tj * 4] = sv;
            }
        }
        __syncthreads();

        {
            const int i = i0 + rg;
            float mloc = -3.4e38f;
#pragma unroll
            for (int k = 0; k < 16; k++) {
                int jj = dg + k * 4;
                int j = j0 + jj;
                bool ok = (j <= i) && (j < len);
                float v = ok ? sm[SS + rg * 68 + jj] : -3.4e38f;
                mloc = fmaxf(mloc, v);
            }
            mloc = fmaxf(mloc, __shfl_xor_sync(0xffffffffu, mloc, 1));
            mloc = fmaxf(mloc, __shfl_xor_sync(0xffffffffu, mloc, 2));
            float mold = sm[SMR + rg];
            float mnew = fmaxf(mold, mloc);
            float fac = expf(mold - mnew);
            float ssum = 0.f;
#pragma unroll
            for (int k = 0; k < 16; k++) {
                int jj = dg + k * 4;
                int j = j0 + jj;
                bool ok = (j <= i) && (j < len);
                float e = ok ? expf(sm[SS + rg * 68 + jj] - mnew) : 0.f;
                sm[SS + rg * 68 + jj] = e;
                ssum += e;
            }
            ssum += __shfl_xor_sync(0xffffffffu, ssum, 1);
            ssum += __shfl_xor_sync(0xffffffffu, ssum, 2);
            if (dg == 0) {
                sm[SMR + rg] = mnew;
                sm[SLR + rg] = sm[SLR + rg] * fac + ssum;
                sm[SFR + rg] = fac;
            }
        }
        __syncthreads();

        {
            float fac = sm[SFR + rg];
#pragma unroll
            for (int q = 0; q < 16; q++) o[q] *= fac;
            for (int j = 0; j < 64; j++) {
                float w = sm[SS + rg * 68 + j];
                float4 v0 = *(const float4*)&sm[SV_T + j * 68 + dg * 16 + 0];
                float4 v1 = *(const float4*)&sm[SV_T + j * 68 + dg * 16 + 4];
                float4 v2 = *(const float4*)&sm[SV_T + j * 68 + dg * 16 + 8];
                float4 v3 = *(const float4*)&sm[SV_T + j * 68 + dg * 16 + 12];
                o[0]  += w * v0.x; o[1]  += w * v0.y; o[2]  += w * v0.z; o[3]  += w * v0.w;
                o[4]  += w * v1.x; o[5]  += w * v1.y; o[6]  += w * v1.z; o[7]  += w * v1.w;
                o[8]  += w * v2.x; o[9]  += w * v2.y; o[10] += w * v2.z; o[11] += w * v2.w;
                o[12] += w * v3.x; o[13] += w * v3.y; o[14] += w * v3.z; o[15] += w * v3.w;
            }
        }
    }

    float inv = 1.f / sm[SLR + rg];
    float* dst = &att[((size_t)(b * TT + i0 + rg)) * DM + h * DKK + dg * 16];
#pragma unroll
    for (int q4 = 0; q4 < 4; q4++) {
        float4 w;
        w.x = o[q4 * 4 + 0] * inv; w.y = o[q4 * 4 + 1] * inv;
        w.z = o[q4 * 4 + 2] * inv; w.w = o[q4 * 4 + 3] * inv;
        *(float4*)(dst + q4 * 4) = w;
    }
}

// ---------------- final copy ----------------
__global__ void out_kernel(const float* __restrict__ x, const int* __restrict__ lens,
                           float* __restrict__ out, int out_size) {
    int idx = blockIdx.x * 256 + threadIdx.x;
    const int n = BB * TT * DM;
    if (idx < n) out[idx] = x[idx];
    if (idx < BB && out_size >= n + BB) out[n + idx] = (float)lens[idx];
}

extern "C" void kernel_launch(void* const* d_in, const int* in_sizes, int n_in,
                              void* d_out, int out_size) {
    const float* x        = (const float*)d_in[0];
    const int*   lens     = (const int*)  d_in[1];
    const float* embed_W  = (const float*)d_in[2];
    const float* embed_b  = (const float*)d_in[3];
    const float* in_projW = (const float*)d_in[4];
    const float* in_projb = (const float*)d_in[5];
    const float* pos_W    = (const float*)d_in[6];
    const float* pbu      = (const float*)d_in[7];
    const float* pbv      = (const float*)d_in[8];
    const float* out_W    = (const float*)d_in[9];
    const float* out_b    = (const float*)d_in[10];
    const float* ff1_W    = (const float*)d_in[11];
    const float* ff1_b    = (const float*)d_in[12];
    const float* ff2_W    = (const float*)d_in[13];
    const float* ff2_b    = (const float*)d_in[14];

    float *xbuf, *qkvb, *peb, *pbuf, *attb, *hbuf;
    cudaGetSymbolAddress((void**)&xbuf, g_x);
    cudaGetSymbolAddress((void**)&qkvb, g_qkv);
    cudaGetSymbolAddress((void**)&peb,  g_pe);
    cudaGetSymbolAddress((void**)&pbuf, g_p);
    cudaGetSymbolAddress((void**)&attb, g_att);
    cudaGetSymbolAddress((void**)&hbuf, g_h);

    cudaFuncSetAttribute(flash_kernel, cudaFuncAttributeMaxDynamicSharedMemorySize, FL_SMEM);
    cudaFuncSetAttribute(mma_gemm, cudaFuncAttributeMaxDynamicSharedMemorySize, MMA_SMEM);

    const int M = BB * TT;

    pe_kernel<<<PP, DM>>>();
    gemm_kernel<<<dim3(DM/128, M/128), 256>>>(x, embed_W, embed_b, nullptr, xbuf, M, DM, IND, 0);
    norm_kernel<<<M, DM>>>(xbuf);

    for (int l = 0; l < NL; l++) {
        mma_gemm<<<dim3(768/128, M/128), 256, MMA_SMEM>>>(
            xbuf, in_projW + (size_t)l*3*DM*DM, in_projb + (size_t)l*3*DM,
            nullptr, qkvb, M, 3*DM, DM, 0);
        gemm_kernel<<<dim3(DM/128, (PP+127)/128), 256>>>(
            peb, pos_W + (size_t)l*DM*DM, nullptr, nullptr, pbuf, PP, DM, DM, 0);
        flash_kernel<<<dim3(TT/64, NH, BB), 256, FL_SMEM>>>(
            qkvb, pbuf, pbu + (size_t)l*NH*DKK, pbv + (size_t)l*NH*DKK, lens, attb);
        mma_gemm<<<dim3(DM/128, M/128), 256, MMA_SMEM>>>(
            attb, out_W + (size_t)l*DM*DM, out_b + (size_t)l*DM, xbuf, xbuf, M, DM, DM, 0);
        mma_gemm<<<dim3(FFD/128, M/128), 256, MMA_SMEM>>>(
            xbuf, ff1_W + (size_t)l*FFD*DM, ff1_b + (size_t)l*FFD, nullptr, hbuf, M, FFD, DM, 1);
        mma_gemm<<<dim3(DM/128, M/128), 256, MMA_SMEM>>>(
            hbuf, ff2_W + (size_t)l*DM*FFD, ff2_b + (size_t)l*DM, xbuf, xbuf, M, DM, FFD, 0);
        norm_kernel<<<M, DM>>>(xbuf);
    }

    int n = BB * TT * DM;
    out_kernel<<<(n + 255)/256, 256>>>(xbuf, lens, (float*)d_out, out_size);
}

// round 10
// speedup vs baseline: 2.8105x; 1.1887x over previous
#include <cuda_runtime.h>
#include <math.h>
#include <stdint.h>

#define BB 8
#define TT 1024
#define IND 80
#define DM 256
#define NH 4
#define DKK 64
#define FFD 2048
#define NL 6
#define PP (2*TT-1)

// ---------------- device scratch (allocation-free) ----------------
__device__ float g_x[BB*TT*DM];
__device__ float g_qkv[BB*TT*3*DM];
__device__ float g_pe[PP*DM];
__device__ float g_p[PP*DM];
__device__ float g_att[BB*TT*DM];
__device__ float g_h[BB*TT*FFD];

// ================= helpers =================
__device__ __forceinline__ uint32_t smem_u32(const void* p) {
    uint32_t a;
    asm("{ .reg .u64 t; cvta.to.shared.u64 t, %1; cvt.u32.u64 %0, t; }" : "=r"(a) : "l"(p));
    return a;
}
__device__ __forceinline__ float tf32r(float x) {
    uint32_t u;
    asm("cvt.rna.tf32.f32 %0, %1;" : "=r"(u) : "f"(x));
    return __uint_as_float(u);
}
__device__ __forceinline__ void ldsm4(uint32_t* r, uint32_t addr) {
    asm volatile("ldmatrix.sync.aligned.m8n8.x4.shared.b16 {%0,%1,%2,%3}, [%4];"
        : "=r"(r[0]), "=r"(r[1]), "=r"(r[2]), "=r"(r[3]) : "r"(addr));
}
__device__ __forceinline__ void mma_tf32(float* c, const uint32_t* a, const uint32_t* b) {
    asm volatile(
        "mma.sync.aligned.m16n8k8.row.col.f32.tf32.tf32.f32 "
        "{%0,%1,%2,%3}, {%4,%5,%6,%7}, {%8,%9}, {%0,%1,%2,%3};"
        : "+f"(c[0]), "+f"(c[1]), "+f"(c[2]), "+f"(c[3])
        : "r"(a[0]), "r"(a[1]), "r"(a[2]), "r"(a[3]), "r"(b[0]), "r"(b[1]));
}
#define STS4(addr, v) asm volatile("st.shared.v4.b32 [%0], {%1,%2,%3,%4};" :: "r"(addr), \
    "r"(__float_as_uint((v).x)), "r"(__float_as_uint((v).y)), \
    "r"(__float_as_uint((v).z)), "r"(__float_as_uint((v).w)) : "memory")

// ================= mma.sync tf32x3 GEMM: C = A(MxK) @ W(NxK)^T =================
// N multiple of 128, K multiple of 32, M arbitrary (loads clamped, stores guarded).
#define TROW 36
#define TCS_A_HI 0
#define TCS_A_LO (128*TROW)
#define TCS_B_HI (2*128*TROW)
#define TCS_B_LO (3*128*TROW)
#define MMA_SMEM (4*128*TROW*4)

__global__ __launch_bounds__(256) void mma_gemm(
    const float* __restrict__ A, const float* __restrict__ W,
    const float* __restrict__ bias, const float* __restrict__ res,
    float* __restrict__ C, int M, int N, int K, int act)
{
    extern __shared__ float dsm[];
    const uint32_t sb = smem_u32(dsm);
    const int tid = threadIdx.x;
    const int wid = tid >> 5, lane = tid & 31;
    const int wm = wid >> 2, wn = wid & 3;          // warp grid 2x4
    const int bm = blockIdx.y * 128, bn = blockIdx.x * 128;

    float c[4][4][4];
#pragma unroll
    for (int mt = 0; mt < 4; mt++)
#pragma unroll
        for (int nt = 0; nt < 4; nt++)
#pragma unroll
            for (int q = 0; q < 4; q++) c[mt][nt][q] = 0.f;

    const int quad = lane >> 3, r8 = lane & 7;
    const int a_row = wm * 64 + r8 + (quad & 1) * 8;
    const int a_col = (quad >> 1) * 4;
    const int b_row = wn * 32 + r8 + (quad >> 1) * 8;
    const int b_col = (quad & 1) * 4;

    const int srow = tid >> 3, skq = tid & 7;

    for (int k0 = 0; k0 < K; k0 += 32) {
#pragma unroll
        for (int e = 0; e < 4; e++) {
            int row = srow + e * 32;
            int ar = bm + row; if (ar >= M) ar = M - 1;
            float4 a4 = *(const float4*)&A[(size_t)ar * K + k0 + skq * 4];
            float4 w4 = *(const float4*)&W[(size_t)(bn + row) * K + k0 + skq * 4];
            uint32_t off = (uint32_t)(row * TROW + skq * 4) * 4;
            float4 h, l;
            h.x = tf32r(a4.x); h.y = tf32r(a4.y); h.z = tf32r(a4.z); h.w = tf32r(a4.w);
            l.x = tf32r(a4.x - h.x); l.y = tf32r(a4.y - h.y);
            l.z = tf32r(a4.z - h.z); l.w = tf32r(a4.w - h.w);
            STS4(sb + TCS_A_HI * 4 + off, h);
            STS4(sb + TCS_A_LO * 4 + off, l);
            h.x = tf32r(w4.x); h.y = tf32r(w4.y); h.z = tf32r(w4.z); h.w = tf32r(w4.w);
            l.x = tf32r(w4.x - h.x); l.y = tf32r(w4.y - h.y);
            l.z = tf32r(w4.z - h.z); l.w = tf32r(w4.w - h.w);
            STS4(sb + TCS_B_HI * 4 + off, h);
            STS4(sb + TCS_B_LO * 4 + off, l);
        }
        __syncthreads();

#pragma unroll
        for (int ks = 0; ks < 4; ks++) {
            uint32_t ah[4][4], al[4][4], bh[4][2], bl[4][2];
#pragma unroll
            for (int mt = 0; mt < 4; mt++) {
                uint32_t ao = (uint32_t)((a_row + mt * 16) * TROW + ks * 8 + a_col) * 4;
                ldsm4(ah[mt], sb + TCS_A_HI * 4 + ao);
                ldsm4(al[mt], sb + TCS_A_LO * 4 + ao);
            }
            {
                uint32_t t[4];
                uint32_t bo = (uint32_t)(b_row * TROW + ks * 8 + b_col) * 4;
                ldsm4(t, sb + TCS_B_HI * 4 + bo);
                bh[0][0] = t[0]; bh[0][1] = t[1]; bh[1][0] = t[2]; bh[1][1] = t[3];
                ldsm4(t, sb + TCS_B_HI * 4 + bo + 16 * TROW * 4);
                bh[2][0] = t[0]; bh[2][1] = t[1]; bh[3][0] = t[2]; bh[3][1] = t[3];
                ldsm4(t, sb + TCS_B_LO * 4 + bo);
                bl[0][0] = t[0]; bl[0][1] = t[1]; bl[1][0] = t[2]; bl[1][1] = t[3];
                ldsm4(t, sb + TCS_B_LO * 4 + bo + 16 * TROW * 4);
                bl[2][0] = t[0]; bl[2][1] = t[1]; bl[3][0] = t[2]; bl[3][1] = t[3];
            }
#pragma unroll
            for (int mt = 0; mt < 4; mt++)
#pragma unroll
                for (int nt = 0; nt < 4; nt++) {
                    mma_tf32(c[mt][nt], ah[mt], bh[nt]);
                    mma_tf32(c[mt][nt], al[mt], bh[nt]);
                    mma_tf32(c[mt][nt], ah[mt], bl[nt]);
                }
        }
        __syncthreads();
    }

    const int g = lane >> 2, tq = lane & 3;
#pragma unroll
    for (int mt = 0; mt < 4; mt++) {
#pragma unroll
        for (int nt = 0; nt < 4; nt++) {
            int col = bn + wn * 32 + nt * 8 + tq * 2;
            float b0 = 0.f, b1 = 0.f;
            if (bias) { b0 = bias[col]; b1 = bias[col + 1]; }
#pragma unroll
            for (int half = 0; half < 2; half++) {
                int row = bm + wm * 64 + mt * 16 + g + half * 8;
                if (row >= M) continue;
                float v0 = c[mt][nt][half * 2 + 0] + b0;
                float v1 = c[mt][nt][half * 2 + 1] + b1;
                if (act == 1) {
                    v0 = v0 / (1.f + expf(1.f - v0));
                    v1 = v1 / (1.f + expf(1.f - v1));
                }
                if (res) {
                    const float2 r2 = *(const float2*)&res[(size_t)row * N + col];
                    v0 += r2.x; v1 += r2.y;
                }
                float2 o2; o2.x = v0; o2.y = v1;
                *(float2*)&C[(size_t)row * N + col] = o2;
            }
        }
    }
}

// ---------------- relative positional encoding ----------------
__global__ void pe_kernel() {
    int r = blockIdx.x;
    int d = threadIdx.x;
    float pos, sign;
    if (r < TT) { pos = (float)(TT - 1 - r); sign = 1.f; }
    else        { pos = (float)(r - TT + 1); sign = -1.f; }
    int j2 = (d >> 1) << 1;
    float div = expf(-(float)j2 * (logf(10000.f) / (float)DM));
    float ang = sign * pos * div;
    g_pe[r * DM + d] = (d & 1) ? cosf(ang) : sinf(ang);
}

// ---------------- fallback SGEMM (embed only) ----------------
__global__ __launch_bounds__(256) void gemm_kernel(
    const float* __restrict__ A, const float* __restrict__ W,
    const float* __restrict__ bias, const float* __restrict__ res,
    float* __restrict__ C, int M, int N, int K, int act)
{
    __shared__ float As[16][128];
    __shared__ float Bs[16][128];
    const int bm = blockIdx.y * 128;
    const int bn = blockIdx.x * 128;
    const int tid = threadIdx.x;
    const int tm = tid >> 4, tn = tid & 15;

    float acc[8][8];
#pragma unroll
    for (int i = 0; i < 8; i++)
#pragma unroll
        for (int j = 0; j < 8; j++) acc[i][j] = 0.f;

    for (int k0 = 0; k0 < K; k0 += 16) {
#pragma unroll
        for (int e = 0; e < 8; e++) {
            int flat = tid + e * 256;
            int row = flat >> 4, kk = flat & 15;
            int ar = bm + row;
            As[kk][row] = (ar < M) ? A[(size_t)ar * K + k0 + kk] : 0.f;
            int wr = bn + row;
            Bs[kk][row] = (wr < N) ? W[(size_t)wr * K + k0 + kk] : 0.f;
        }
        __syncthreads();
#pragma unroll
        for (int kk = 0; kk < 16; kk++) {
            float4 a0 = *(const float4*)&As[kk][tm * 8];
            float4 a1 = *(const float4*)&As[kk][tm * 8 + 4];
            float4 b0 = *(const float4*)&Bs[kk][tn * 8];
            float4 b1 = *(const float4*)&Bs[kk][tn * 8 + 4];
            float a[8] = {a0.x,a0.y,a0.z,a0.w,a1.x,a1.y,a1.z,a1.w};
            float b[8] = {b0.x,b0.y,b0.z,b0.w,b1.x,b1.y,b1.z,b1.w};
#pragma unroll
            for (int i = 0; i < 8; i++)
#pragma unroll
                for (int j = 0; j < 8; j++) acc[i][j] += a[i] * b[j];
        }
        __syncthreads();
    }
#pragma unroll
    for (int i = 0; i < 8; i++) {
        int row = bm + tm * 8 + i;
        if (row >= M) continue;
#pragma unroll
        for (int j = 0; j < 8; j++) {
            int col = bn + tn * 8 + j;
            float c = acc[i][j];
            if (bias) c += bias[col];
            if (act == 1) c = c / (1.f + expf(1.f - c));
            if (res) c += res[(size_t)row * N + col];
            C[(size_t)row * N + col] = c;
        }
    }
}

// ---------------- BasicNorm ----------------
__global__ __launch_bounds__(DM) void norm_kernel(float* __restrict__ x) {
    int row = blockIdx.x, tid = threadIdx.x;
    float v = x[(size_t)row * DM + tid];
    float s = v * v;
#pragma unroll
    for (int o = 16; o; o >>= 1) s += __shfl_xor_sync(0xffffffffu, s, o);
    __shared__ float sm[8];
    int warp = tid >> 5, lane = tid & 31;
    if (lane == 0) sm[warp] = s;
    __syncthreads();
    if (warp == 0) {
        float t = (lane < 8) ? sm[lane] : 0.f;
#pragma unroll
        for (int o = 4; o; o >>= 1) t += __shfl_xor_sync(0xffffffffu, t, o);
        if (lane == 0) sm[0] = t;
    }
    __syncthreads();
    float scale = rsqrtf(sm[0] / (float)DM + 0.25f);
    x[(size_t)row * DM + tid] = v * scale;
}

// ================= flash attention with tf32x3 mma score GEMMs =================
// smem (floats), row stride 68 unless noted:
#define FQU_H 0
#define FQU_L (FQU_H + 64*68)
#define FQV_H (FQU_L + 64*68)
#define FQV_L (FQV_H + 64*68)
#define FK    (FQV_L + 64*68)     // [64][68]  Kh then Kl
#define FP    (FK + 64*68)        // [128][68] Ph then Pl
#define FV    (FP + 128*68)       // [64][68]  fp32
#define FQP   (FV + 64*68)        // [64][128]
#define FS    (FQP + 64*128)      // [64][68]
#define FMR   (FS + 64*68)
#define FLR   (FMR + 64)
#define FFR   (FLR + 64)
#define FL_SMEM ((FFR + 64) * 4)

__global__ __launch_bounds__(256) void flash_kernel(
    const float* __restrict__ qkv, const float* __restrict__ p,
    const float* __restrict__ ub, const float* __restrict__ vb,
    const int* __restrict__ lens, float* __restrict__ att)
{
    extern __shared__ float sm[];
    const uint32_t sb = smem_u32(sm);
    const int i0 = blockIdx.x * 64;
    const int h  = blockIdx.y;
    const int b  = blockIdx.z;
    const int tid = threadIdx.x;
    const int wid = tid >> 5, lane = tid & 31;
    const int len = lens[b];

    // ---- prologue: qu/qv hi/lo tiles ----
#pragma unroll
    for (int e = 0; e < 4; e++) {
        int f4 = tid + e * 256;
        int row = f4 >> 4, c = (f4 & 15) * 4;
        float4 q4 = *(const float4*)&qkv[((size_t)(b * TT + i0 + row)) * 768 + h * DKK + c];
        float4 u4 = *(const float4*)&ub[h * DKK + c];
        float4 v4 = *(const float4*)&vb[h * DKK + c];
        float4 qu, qv;
        qu.x = q4.x + u4.x; qu.y = q4.y + u4.y; qu.z = q4.z + u4.z; qu.w = q4.w + u4.w;
        qv.x = q4.x + v4.x; qv.y = q4.y + v4.y; qv.z = q4.z + v4.z; qv.w = q4.w + v4.w;
        float4 hh, ll;
        uint32_t off = (uint32_t)(row * 68 + c) * 4;
        hh.x = tf32r(qu.x); hh.y = tf32r(qu.y); hh.z = tf32r(qu.z); hh.w = tf32r(qu.w);
        ll.x = qu.x - hh.x; ll.y = qu.y - hh.y; ll.z = qu.z - hh.z; ll.w = qu.w - hh.w;
        STS4(sb + FQU_H * 4 + off, hh); STS4(sb + FQU_L * 4 + off, ll);
        hh.x = tf32r(qv.x); hh.y = tf32r(qv.y); hh.z = tf32r(qv.z); hh.w = tf32r(qv.w);
        ll.x = qv.x - hh.x; ll.y = qv.y - hh.y; ll.z = qv.z - hh.z; ll.w = qv.w - hh.w;
        STS4(sb + FQV_H * 4 + off, hh); STS4(sb + FQV_L * 4 + off, ll);
    }
    if (tid < 64) { sm[FMR + tid] = -3.4e38f; sm[FLR + tid] = 0.f; }

    float o[16];
#pragma unroll
    for (int q = 0; q < 16; q++) o[q] = 0.f;

    // fragment maps (same as mma_gemm)
    const int wmS = wid & 3, wnS = wid >> 2;          // 4x2 warp grid
    const int quad = lane >> 3, r8 = lane & 7;
    const int a_row = wmS * 16 + r8 + (quad & 1) * 8;
    const int a_col = (quad >> 1) * 4;
    const int bS_row = wnS * 32 + r8 + (quad >> 1) * 8;
    const int bQ_row = wnS * 64 + r8 + (quad >> 1) * 8;
    const int b_col = (quad & 1) * 4;
    const int g = lane >> 2, tq = lane & 3;
    const int rg = tid >> 2, dg = tid & 3;

    for (int j0 = 0; j0 <= i0; j0 += 64) {
        __syncthreads();   // prior AV / prologue done
        // ---- stage Kh, V, Ph ----
#pragma unroll
        for (int e = 0; e < 4; e++) {
            int f4 = tid + e * 256;
            int j = f4 >> 4, c = (f4 & 15) * 4;
            const float* base = &qkv[((size_t)(b * TT + j0 + j)) * 768 + h * DKK + c];
            float4 k4 = *(const float4*)(base + DM);
            float4 v4 = *(const float4*)(base + 2 * DM);
            uint32_t off = (uint32_t)(j * 68 + c) * 4;
            float4 hh;
            hh.x = tf32r(k4.x); hh.y = tf32r(k4.y); hh.z = tf32r(k4.z); hh.w = tf32r(k4.w);
            STS4(sb + FK * 4 + off, hh);
            STS4(sb + FV * 4 + off, v4);
        }
        const int pbase = TT - 1 - (i0 + 63) + j0;
#pragma unroll
        for (int e = 0; e < 8; e++) {
            int f4 = tid + e * 256;
            if (f4 < 127 * 16) {
                int r = f4 >> 4, c = (f4 & 15) * 4;
                float4 p4 = *(const float4*)&p[(size_t)(pbase + r) * DM + h * DKK + c];
                float4 hh;
                hh.x = tf32r(p4.x); hh.y = tf32r(p4.y); hh.z = tf32r(p4.z); hh.w = tf32r(p4.w);
                STS4(sb + FP * 4 + (uint32_t)(r * 68 + c) * 4, hh);
            }
        }
        __syncthreads();

        // ---- phase A: S += uh*Kh + ul*Kh ; QP += vh*Ph + vl*Ph ----
        float cS[4][4], cQ[8][4];
#pragma unroll
        for (int nt = 0; nt < 4; nt++)
#pragma unroll
            for (int q = 0; q < 4; q++) cS[nt][q] = 0.f;
#pragma unroll
        for (int nt = 0; nt < 8; nt++)
#pragma unroll
            for (int q = 0; q < 4; q++) cQ[nt][q] = 0.f;

#pragma unroll
        for (int ks = 0; ks < 8; ks++) {
            uint32_t ao = (uint32_t)(a_row * 68 + ks * 8 + a_col) * 4;
            uint32_t ah[4], al[4], t[4], bb[8][2];
            // S part
            ldsm4(ah, sb + FQU_H * 4 + ao);
            ldsm4(al, sb + FQU_L * 4 + ao);
            uint32_t bo = (uint32_t)(bS_row * 68 + ks * 8 + b_col) * 4;
            ldsm4(t, sb + FK * 4 + bo);
            bb[0][0] = t[0]; bb[0][1] = t[1]; bb[1][0] = t[2]; bb[1][1] = t[3];
            ldsm4(t, sb + FK * 4 + bo + 16 * 68 * 4);
            bb[2][0] = t[0]; bb[2][1] = t[1]; bb[3][0] = t[2]; bb[3][1] = t[3];
#pragma unroll
            for (int nt = 0; nt < 4; nt++) {
                mma_tf32(cS[nt], ah, bb[nt]);
                mma_tf32(cS[nt], al, bb[nt]);
            }
            // QP part
            ldsm4(ah, sb + FQV_H * 4 + ao);
            ldsm4(al, sb + FQV_L * 4 + ao);
            uint32_t boq = (uint32_t)(bQ_row * 68 + ks * 8 + b_col) * 4;
#pragma unroll
            for (int pr = 0; pr < 4; pr++) {
                ldsm4(t, sb + FP * 4 + boq + (uint32_t)(pr * 16 * 68) * 4);
                bb[2*pr][0] = t[0]; bb[2*pr][1] = t[1];
                bb[2*pr+1][0] = t[2]; bb[2*pr+1][1] = t[3];
            }
#pragma unroll
            for (int nt = 0; nt < 8; nt++) {
                mma_tf32(cQ[nt], ah, bb[nt]);
                mma_tf32(cQ[nt], al, bb[nt]);
            }
        }
        __syncthreads();

        // ---- restage Kl, Pl into same buffers ----
#pragma unroll
        for (int e = 0; e < 4; e++) {
            int f4 = tid + e * 256;
            int j = f4 >> 4, c = (f4 & 15) * 4;
            const float* base = &qkv[((size_t)(b * TT + j0 + j)) * 768 + h * DKK + c];
            float4 k4 = *(const float4*)(base + DM);
            float4 ll;
            ll.x = k4.x - tf32r(k4.x); ll.y = k4.y - tf32r(k4.y);
            ll.z = k4.z - tf32r(k4.z); ll.w = k4.w - tf32r(k4.w);
            STS4(sb + FK * 4 + (uint32_t)(j * 68 + c) * 4, ll);
        }
#pragma unroll
        for (int e = 0; e < 8; e++) {
            int f4 = tid + e * 256;
            if (f4 < 127 * 16) {
                int r = f4 >> 4, c = (f4 & 15) * 4;
                float4 p4 = *(const float4*)&p[(size_t)(pbase + r) * DM + h * DKK + c];
                float4 ll;
                ll.x = p4.x - tf32r(p4.x); ll.y = p4.y - tf32r(p4.y);
                ll.z = p4.z - tf32r(p4.z); ll.w = p4.w - tf32r(p4.w);
                STS4(sb + FP * 4 + (uint32_t)(r * 68 + c) * 4, ll);
            }
        }
        __syncthreads();

        // ---- phase B: S += uh*Kl ; QP += vh*Pl ; write QP ----
#pragma unroll
        for (int ks = 0; ks < 8; ks++) {
            uint32_t ao = (uint32_t)(a_row * 68 + ks * 8 + a_col) * 4;
            uint32_t ah[4], t[4], bb[8][2];
            ldsm4(ah, sb + FQU_H * 4 + ao);
            uint32_t bo = (uint32_t)(bS_row * 68 + ks * 8 + b_col) * 4;
            ldsm4(t, sb + FK * 4 + bo);
            bb[0][0] = t[0]; bb[0][1] = t[1]; bb[1][0] = t[2]; bb[1][1] = t[3];
            ldsm4(t, sb + FK * 4 + bo + 16 * 68 * 4);
            bb[2][0] = t[0]; bb[2][1] = t[1]; bb[3][0] = t[2]; bb[3][1] = t[3];
#pragma unroll
            for (int nt = 0; nt < 4; nt++) mma_tf32(cS[nt], ah, bb[nt]);
            ldsm4(ah, sb + FQV_H * 4 + ao);
            uint32_t boq = (uint32_t)(bQ_row * 68 + ks * 8 + b_col) * 4;
#pragma unroll
            for (int pr = 0; pr < 4; pr++) {
                ldsm4(t, sb + FP * 4 + boq + (uint32_t)(pr * 16 * 68) * 4);
                bb[2*pr][0] = t[0]; bb[2*pr][1] = t[1];
                bb[2*pr+1][0] = t[2]; bb[2*pr+1][1] = t[3];
            }
#pragma unroll
            for (int nt = 0; nt < 8; nt++) mma_tf32(cQ[nt], ah, bb[nt]);
        }
        // write QP
#pragma unroll
        for (int nt = 0; nt < 8; nt++) {
            int col = wnS * 64 + nt * 8 + tq * 2;
#pragma unroll
            for (int half = 0; half < 2; half++) {
                int row = wmS * 16 + g + half * 8;
                sm[FQP + row * 128 + col]     = cQ[nt][half * 2 + 0];
                sm[FQP + row * 128 + col + 1] = cQ[nt][half * 2 + 1];
            }
        }
        __syncthreads();

        // ---- S epilogue: (cS + QP-shift) * scale -> FS ----
#pragma unroll
        for (int nt = 0; nt < 4; nt++) {
            int col = wnS * 32 + nt * 8 + tq * 2;
#pragma unroll
            for (int half = 0; half < 2; half++) {
                int row = wmS * 16 + g + half * 8;
                int rsh = 63 - row + col;
                sm[FS + row * 68 + col]     = (cS[nt][half*2+0] + sm[FQP + row * 128 + rsh])     * 0.125f;
                sm[FS + row * 68 + col + 1] = (cS[nt][half*2+1] + sm[FQP + row * 128 + rsh + 1]) * 0.125f;
            }
        }
        __syncthreads();

        // ---- online softmax ----
        {
            const int i = i0 + rg;
            float mloc = -3.4e38f;
#pragma unroll
            for (int k = 0; k < 16; k++) {
                int jj = dg + k * 4;
                int j = j0 + jj;
                bool ok = (j <= i) && (j < len);
                float v = ok ? sm[FS + rg * 68 + jj] : -3.4e38f;
                mloc = fmaxf(mloc, v);
            }
            mloc = fmaxf(mloc, __shfl_xor_sync(0xffffffffu, mloc, 1));
            mloc = fmaxf(mloc, __shfl_xor_sync(0xffffffffu, mloc, 2));
            float mold = sm[FMR + rg];
            float mnew = fmaxf(mold, mloc);
            float fac = expf(mold - mnew);
            float ssum = 0.f;
#pragma unroll
            for (int k = 0; k < 16; k++) {
                int jj = dg + k * 4;
                int j = j0 + jj;
                bool ok = (j <= i) && (j < len);
                float e = ok ? expf(sm[FS + rg * 68 + jj] - mnew) : 0.f;
                sm[FS + rg * 68 + jj] = e;
                ssum += e;
            }
            ssum += __shfl_xor_sync(0xffffffffu, ssum, 1);
            ssum += __shfl_xor_sync(0xffffffffu, ssum, 2);
            if (dg == 0) {
                sm[FMR + rg] = mnew;
                sm[FLR + rg] = sm[FLR + rg] * fac + ssum;
                sm[FFR + rg] = fac;
            }
        }
        __syncthreads();

        // ---- AV accumulate (scalar) ----
        {
            float fac = sm[FFR + rg];
#pragma unroll
            for (int q = 0; q < 16; q++) o[q] *= fac;
            for (int j = 0; j < 64; j++) {
                float w = sm[FS + rg * 68 + j];
                float4 v0 = *(const float4*)&sm[FV + j * 68 + dg * 16 + 0];
                float4 v1 = *(const float4*)&sm[FV + j * 68 + dg * 16 + 4];
                float4 v2 = *(const float4*)&sm[FV + j * 68 + dg * 16 + 8];
                float4 v3 = *(const float4*)&sm[FV + j * 68 + dg * 16 + 12];
                o[0]  += w * v0.x; o[1]  += w * v0.y; o[2]  += w * v0.z; o[3]  += w * v0.w;
                o[4]  += w * v1.x; o[5]  += w * v1.y; o[6]  += w * v1.z; o[7]  += w * v1.w;
                o[8]  += w * v2.x; o[9]  += w * v2.y; o[10] += w * v2.z; o[11] += w * v2.w;
                o[12] += w * v3.x; o[13] += w * v3.y; o[14] += w * v3.z; o[15] += w * v3.w;
            }
        }
    }

    float inv = 1.f / sm[FLR + rg];
    float* dst = &att[((size_t)(b * TT + i0 + rg)) * DM + h * DKK + dg * 16];
#pragma unroll
    for (int q4 = 0; q4 < 4; q4++) {
        float4 w;
        w.x = o[q4 * 4 + 0] * inv; w.y = o[q4 * 4 + 1] * inv;
        w.z = o[q4 * 4 + 2] * inv; w.w = o[q4 * 4 + 3] * inv;
        *(float4*)(dst + q4 * 4) = w;
    }
}

// ---------------- final copy ----------------
__global__ void out_kernel(const float* __restrict__ x, const int* __restrict__ lens,
                           float* __restrict__ out, int out_size) {
    int idx = blockIdx.x * 256 + threadIdx.x;
    const int n = BB * TT * DM;
    if (idx < n) out[idx] = x[idx];
    if (idx < BB && out_size >= n + BB) out[n + idx] = (float)lens[idx];
}

extern "C" void kernel_launch(void* const* d_in, const int* in_sizes, int n_in,
                              void* d_out, int out_size) {
    const float* x        = (const float*)d_in[0];
    const int*   lens     = (const int*)  d_in[1];
    const float* embed_W  = (const float*)d_in[2];
    const float* embed_b  = (const float*)d_in[3];
    const float* in_projW = (const float*)d_in[4];
    const float* in_projb = (const float*)d_in[5];
    const float* pos_W    = (const float*)d_in[6];
    const float* pbu      = (const float*)d_in[7];
    const float* pbv      = (const float*)d_in[8];
    const float* out_W    = (const float*)d_in[9];
    const float* out_b    = (const float*)d_in[10];
    const float* ff1_W    = (const float*)d_in[11];
    const float* ff1_b    = (const float*)d_in[12];
    const float* ff2_W    = (const float*)d_in[13];
    const float* ff2_b    = (const float*)d_in[14];

    float *xbuf, *qkvb, *peb, *pbuf, *attb, *hbuf;
    cudaGetSymbolAddress((void**)&xbuf, g_x);
    cudaGetSymbolAddress((void**)&qkvb, g_qkv);
    cudaGetSymbolAddress((void**)&peb,  g_pe);
    cudaGetSymbolAddress((void**)&pbuf, g_p);
    cudaGetSymbolAddress((void**)&attb, g_att);
    cudaGetSymbolAddress((void**)&hbuf, g_h);

    cudaFuncSetAttribute(flash_kernel, cudaFuncAttributeMaxDynamicSharedMemorySize, FL_SMEM);
    cudaFuncSetAttribute(mma_gemm, cudaFuncAttributeMaxDynamicSharedMemorySize, MMA_SMEM);

    const int M = BB * TT;

    pe_kernel<<<PP, DM>>>();
    gemm_kernel<<<dim3(DM/128, M/128), 256>>>(x, embed_W, embed_b, nullptr, xbuf, M, DM, IND, 0);
    norm_kernel<<<M, DM>>>(xbuf);

    for (int l = 0; l < NL; l++) {
        mma_gemm<<<dim3(768/128, M/128), 256, MMA_SMEM>>>(
            xbuf, in_projW + (size_t)l*3*DM*DM, in_projb + (size_t)l*3*DM,
            nullptr, qkvb, M, 3*DM, DM, 0);
        mma_gemm<<<dim3(DM/128, 16), 256, MMA_SMEM>>>(
            peb, pos_W + (size_t)l*DM*DM, nullptr, nullptr, pbuf, PP, DM, DM, 0);
        flash_kernel<<<dim3(TT/64, NH, BB), 256, FL_SMEM>>>(
            qkvb, pbuf, pbu + (size_t)l*NH*DKK, pbv + (size_t)l*NH*DKK, lens, attb);
        mma_gemm<<<dim3(DM/128, M/128), 256, MMA_SMEM>>>(
            attb, out_W + (size_t)l*DM*DM, out_b + (size_t)l*DM, xbuf, xbuf, M, DM, DM, 0);
        mma_gemm<<<dim3(FFD/128, M/128), 256, MMA_SMEM>>>(
            xbuf, ff1_W + (size_t)l*FFD*DM, ff1_b + (size_t)l*FFD, nullptr, hbuf, M, FFD, DM, 1);
        mma_gemm<<<dim3(DM/128, M/128), 256, MMA_SMEM>>>(
            hbuf, ff2_W + (size_t)l*DM*FFD, ff2_b + (size_t)l*DM, xbuf, xbuf, M, DM, FFD, 0);
        norm_kernel<<<M, DM>>>(xbuf);
    }

    int n = BB * TT * DM;
    out_kernel<<<(n + 255)/256, 256>>>(xbuf, lens, (float*)d_out, out_size);
}

// round 11
// speedup vs baseline: 2.9377x; 1.0452x over previous
#include <cuda_runtime.h>
#include <math.h>
#include <stdint.h>

#define BB 8
#define TT 1024
#define IND 80
#define DM 256
#define NH 4
#define DKK 64
#define FFD 2048
#define NL 6
#define PP (2*TT-1)

// ---------------- device scratch (allocation-free) ----------------
__device__ float g_x[BB*TT*DM];
__device__ float g_qkv[BB*TT*3*DM];
__device__ float g_pe[PP*DM];
__device__ float g_p[PP*DM];
__device__ float g_att[BB*TT*DM];
__device__ float g_h[BB*TT*FFD];

// ================= helpers =================
__device__ __forceinline__ uint32_t smem_u32(const void* p) {
    uint32_t a;
    asm("{ .reg .u64 t; cvta.to.shared.u64 t, %1; cvt.u32.u64 %0, t; }" : "=r"(a) : "l"(p));
    return a;
}
__device__ __forceinline__ float tf32r(float x) {
    uint32_t u;
    asm("cvt.rna.tf32.f32 %0, %1;" : "=r"(u) : "f"(x));
    return __uint_as_float(u);
}
__device__ __forceinline__ void split2(uint32_t raw, uint32_t& h, uint32_t& l) {
    float f = __uint_as_float(raw);
    float fh = tf32r(f);
    h = __float_as_uint(fh);
    l = __float_as_uint(tf32r(f - fh));
}
__device__ __forceinline__ void ldsm4(uint32_t* r, uint32_t addr) {
    asm volatile("ldmatrix.sync.aligned.m8n8.x4.shared.b16 {%0,%1,%2,%3}, [%4];"
        : "=r"(r[0]), "=r"(r[1]), "=r"(r[2]), "=r"(r[3]) : "r"(addr));
}
__device__ __forceinline__ void mma_tf32(float* c, const uint32_t* a, const uint32_t* b) {
    asm volatile(
        "mma.sync.aligned.m16n8k8.row.col.f32.tf32.tf32.f32 "
        "{%0,%1,%2,%3}, {%4,%5,%6,%7}, {%8,%9}, {%0,%1,%2,%3};"
        : "+f"(c[0]), "+f"(c[1]), "+f"(c[2]), "+f"(c[3])
        : "r"(a[0]), "r"(a[1]), "r"(a[2]), "r"(a[3]), "r"(b[0]), "r"(b[1]));
}
__device__ __forceinline__ void cpasync16(uint32_t saddr, const void* g) {
    asm volatile("cp.async.cg.shared.global [%0], [%1], 16;" :: "r"(saddr), "l"(g) : "memory");
}
#define CP_COMMIT() asm volatile("cp.async.commit_group;" ::: "memory")
#define CP_WAIT1()  asm volatile("cp.async.wait_group 1;" ::: "memory")
#define CP_WAIT0()  asm volatile("cp.async.wait_group 0;" ::: "memory")
#define STS4(addr, v) asm volatile("st.shared.v4.b32 [%0], {%1,%2,%3,%4};" :: "r"(addr), \
    "r"(__float_as_uint((v).x)), "r"(__float_as_uint((v).y)), \
    "r"(__float_as_uint((v).z)), "r"(__float_as_uint((v).w)) : "memory")

// ================= mma.sync tf32x3 GEMM (cp.async double-buffered) =================
// C = A(MxK) @ W(NxK)^T. N mult of 128, K mult of 32, M arbitrary.
#define TROW 36
#define PSTAGE (128*TROW)                  // floats per tile
#define MMA_SMEM (2*2*PSTAGE*4)            // 2 stages x (A,B)

__global__ __launch_bounds__(256) void mma_gemm(
    const float* __restrict__ A, const float* __restrict__ W,
    const float* __restrict__ bias, const float* __restrict__ res,
    float* __restrict__ C, int M, int N, int K, int act)
{
    extern __shared__ float dsm[];
    const uint32_t sb = smem_u32(dsm);
    const int tid = threadIdx.x;
    const int wid = tid >> 5, lane = tid & 31;
    const int wm = wid >> 2, wn = wid & 3;          // warp grid 2x4
    const int bm = blockIdx.y * 128, bn = blockIdx.x * 128;

    float c[4][4][4];
#pragma unroll
    for (int mt = 0; mt < 4; mt++)
#pragma unroll
        for (int nt = 0; nt < 4; nt++)
#pragma unroll
            for (int q = 0; q < 4; q++) c[mt][nt][q] = 0.f;

    const int quad = lane >> 3, r8 = lane & 7;
    const int a_row = wm * 64 + r8 + (quad & 1) * 8;
    const int a_col = (quad >> 1) * 4;
    const int b_row = wn * 32 + r8 + (quad >> 1) * 8;
    const int b_col = (quad & 1) * 4;

    const int srow = tid >> 3, skq = tid & 7;
    const int nchunk = K / 32;

    // issue one chunk's async copies
    auto issue = [&](int cc) {
        const int s = cc & 1;
        const int k0 = cc * 32;
        const uint32_t sA = sb + (uint32_t)(s * 2 * PSTAGE) * 4;
        const uint32_t sB = sA + (uint32_t)PSTAGE * 4;
#pragma unroll
        for (int e = 0; e < 4; e++) {
            int row = srow + e * 32;
            int ar = bm + row; if (ar >= M) ar = M - 1;
            uint32_t off = (uint32_t)(row * TROW + skq * 4) * 4;
            cpasync16(sA + off, &A[(size_t)ar * K + k0 + skq * 4]);
            cpasync16(sB + off, &W[(size_t)(bn + row) * K + k0 + skq * 4]);
        }
        CP_COMMIT();
    };

    issue(0);
    for (int cc = 0; cc < nchunk; cc++) {
        if (cc + 1 < nchunk) { issue(cc + 1); CP_WAIT1(); }
        else                 { CP_WAIT0(); }
        __syncthreads();
        const int s = cc & 1;
        const uint32_t sA = sb + (uint32_t)(s * 2 * PSTAGE) * 4;
        const uint32_t sB = sA + (uint32_t)PSTAGE * 4;
#pragma unroll
        for (int ks = 0; ks < 4; ks++) {
            uint32_t ah[4][4], al[4][4], bh[4][2], bl[4][2];
#pragma unroll
            for (int mt = 0; mt < 4; mt++) {
                uint32_t raw[4];
                ldsm4(raw, sA + (uint32_t)((a_row + mt * 16) * TROW + ks * 8 + a_col) * 4);
#pragma unroll
                for (int q = 0; q < 4; q++) split2(raw[q], ah[mt][q], al[mt][q]);
            }
            {
                uint32_t t[4], th[4], tl[4];
                uint32_t bo = (uint32_t)(b_row * TROW + ks * 8 + b_col) * 4;
                ldsm4(t, sB + bo);
#pragma unroll
                for (int q = 0; q < 4; q++) split2(t[q], th[q], tl[q]);
                bh[0][0] = th[0]; bh[0][1] = th[1]; bh[1][0] = th[2]; bh[1][1] = th[3];
                bl[0][0] = tl[0]; bl[0][1] = tl[1]; bl[1][0] = tl[2]; bl[1][1] = tl[3];
                ldsm4(t, sB + bo + (uint32_t)(16 * TROW) * 4);
#pragma unroll
                for (int q = 0; q < 4; q++) split2(t[q], th[q], tl[q]);
                bh[2][0] = th[0]; bh[2][1] = th[1]; bh[3][0] = th[2]; bh[3][1] = th[3];
                bl[2][0] = tl[0]; bl[2][1] = tl[1]; bl[3][0] = tl[2]; bl[3][1] = tl[3];
            }
#pragma unroll
            for (int mt = 0; mt < 4; mt++)
#pragma unroll
                for (int nt = 0; nt < 4; nt++) {
                    mma_tf32(c[mt][nt], ah[mt], bh[nt]);
                    mma_tf32(c[mt][nt], al[mt], bh[nt]);
                    mma_tf32(c[mt][nt], ah[mt], bl[nt]);
                }
        }
        __syncthreads();
    }

    const int g = lane >> 2, tq = lane & 3;
#pragma unroll
    for (int mt = 0; mt < 4; mt++) {
#pragma unroll
        for (int nt = 0; nt < 4; nt++) {
            int col = bn + wn * 32 + nt * 8 + tq * 2;
            float b0 = 0.f, b1 = 0.f;
            if (bias) { b0 = bias[col]; b1 = bias[col + 1]; }
#pragma unroll
            for (int half = 0; half < 2; half++) {
                int row = bm + wm * 64 + mt * 16 + g + half * 8;
                if (row >= M) continue;
                float v0 = c[mt][nt][half * 2 + 0] + b0;
                float v1 = c[mt][nt][half * 2 + 1] + b1;
                if (act == 1) {
                    v0 = v0 / (1.f + expf(1.f - v0));
                    v1 = v1 / (1.f + expf(1.f - v1));
                }
                if (res) {
                    const float2 r2 = *(const float2*)&res[(size_t)row * N + col];
                    v0 += r2.x; v1 += r2.y;
                }
                float2 o2; o2.x = v0; o2.y = v1;
                *(float2*)&C[(size_t)row * N + col] = o2;
            }
        }
    }
}

// ---------------- relative positional encoding ----------------
__global__ void pe_kernel() {
    int r = blockIdx.x;
    int d = threadIdx.x;
    float pos, sign;
    if (r < TT) { pos = (float)(TT - 1 - r); sign = 1.f; }
    else        { pos = (float)(r - TT + 1); sign = -1.f; }
    int j2 = (d >> 1) << 1;
    float div = expf(-(float)j2 * (logf(10000.f) / (float)DM));
    float ang = sign * pos * div;
    g_pe[r * DM + d] = (d & 1) ? cosf(ang) : sinf(ang);
}

// ---------------- fallback SGEMM (embed only) ----------------
__global__ __launch_bounds__(256) void gemm_kernel(
    const float* __restrict__ A, const float* __restrict__ W,
    const float* __restrict__ bias, const float* __restrict__ res,
    float* __restrict__ C, int M, int N, int K, int act)
{
    __shared__ float As[16][128];
    __shared__ float Bs[16][128];
    const int bm = blockIdx.y * 128;
    const int bn = blockIdx.x * 128;
    const int tid = threadIdx.x;
    const int tm = tid >> 4, tn = tid & 15;

    float acc[8][8];
#pragma unroll
    for (int i = 0; i < 8; i++)
#pragma unroll
        for (int j = 0; j < 8; j++) acc[i][j] = 0.f;

    for (int k0 = 0; k0 < K; k0 += 16) {
#pragma unroll
        for (int e = 0; e < 8; e++) {
            int flat = tid + e * 256;
            int row = flat >> 4, kk = flat & 15;
            int ar = bm + row;
            As[kk][row] = (ar < M) ? A[(size_t)ar * K + k0 + kk] : 0.f;
            int wr = bn + row;
            Bs[kk][row] = (wr < N) ? W[(size_t)wr * K + k0 + kk] : 0.f;
        }
        __syncthreads();
#pragma unroll
        for (int kk = 0; kk < 16; kk++) {
            float4 a0 = *(const float4*)&As[kk][tm * 8];
            float4 a1 = *(const float4*)&As[kk][tm * 8 + 4];
            float4 b0 = *(const float4*)&Bs[kk][tn * 8];
            float4 b1 = *(const float4*)&Bs[kk][tn * 8 + 4];
            float a[8] = {a0.x,a0.y,a0.z,a0.w,a1.x,a1.y,a1.z,a1.w};
            float b[8] = {b0.x,b0.y,b0.z,b0.w,b1.x,b1.y,b1.z,b1.w};
#pragma unroll
            for (int i = 0; i < 8; i++)
#pragma unroll
                for (int j = 0; j < 8; j++) acc[i][j] += a[i] * b[j];
        }
        __syncthreads();
    }
#pragma unroll
    for (int i = 0; i < 8; i++) {
        int row = bm + tm * 8 + i;
        if (row >= M) continue;
#pragma unroll
        for (int j = 0; j < 8; j++) {
            int col = bn + tn * 8 + j;
            float c = acc[i][j];
            if (bias) c += bias[col];
            if (act == 1) c = c / (1.f + expf(1.f - c));
            if (res) c += res[(size_t)row * N + col];
            C[(size_t)row * N + col] = c;
        }
    }
}

// ---------------- BasicNorm ----------------
__global__ __launch_bounds__(DM) void norm_kernel(float* __restrict__ x) {
    int row = blockIdx.x, tid = threadIdx.x;
    float v = x[(size_t)row * DM + tid];
    float s = v * v;
#pragma unroll
    for (int o = 16; o; o >>= 1) s += __shfl_xor_sync(0xffffffffu, s, o);
    __shared__ float sm[8];
    int warp = tid >> 5, lane = tid & 31;
    if (lane == 0) sm[warp] = s;
    __syncthreads();
    if (warp == 0) {
        float t = (lane < 8) ? sm[lane] : 0.f;
#pragma unroll
        for (int o = 4; o; o >>= 1) t += __shfl_xor_sync(0xffffffffu, t, o);
        if (lane == 0) sm[0] = t;
    }
    __syncthreads();
    float scale = rsqrtf(sm[0] / (float)DM + 0.25f);
    x[(size_t)row * DM + tid] = v * scale;
}

// ================= flash attention, tf32x3 mma scores, raw staging =================
#define FQU 0
#define FQV (FQU + 64*68)
#define FK  (FQV + 64*68)
#define FV  (FK + 64*68)
#define FP  (FV + 64*68)        // [128][68]
#define FQP (FP + 128*68)       // [64][128]
#define FS  (FQP + 64*128)      // [64][68]
#define FMR (FS + 64*68)
#define FLR (FMR + 64)
#define FFR (FLR + 64)
#define FL_SMEM ((FFR + 64) * 4)

__global__ __launch_bounds__(256) void flash_kernel(
    const float* __restrict__ qkv, const float* __restrict__ p,
    const float* __restrict__ ub, const float* __restrict__ vb,
    const int* __restrict__ lens, float* __restrict__ att)
{
    extern __shared__ float sm[];
    const uint32_t sb = smem_u32(sm);
    const int i0 = blockIdx.x * 64;
    const int h  = blockIdx.y;
    const int b  = blockIdx.z;
    const int tid = threadIdx.x;
    const int wid = tid >> 5, lane = tid & 31;
    const int len = lens[b];

    // ---- prologue: raw qu/qv ----
#pragma unroll
    for (int e = 0; e < 4; e++) {
        int f4 = tid + e * 256;
        int row = f4 >> 4, c = (f4 & 15) * 4;
        float4 q4 = *(const float4*)&qkv[((size_t)(b * TT + i0 + row)) * 768 + h * DKK + c];
        float4 u4 = *(const float4*)&ub[h * DKK + c];
        float4 v4 = *(const float4*)&vb[h * DKK + c];
        float4 qu, qv;
        qu.x = q4.x + u4.x; qu.y = q4.y + u4.y; qu.z = q4.z + u4.z; qu.w = q4.w + u4.w;
        qv.x = q4.x + v4.x; qv.y = q4.y + v4.y; qv.z = q4.z + v4.z; qv.w = q4.w + v4.w;
        uint32_t off = (uint32_t)(row * 68 + c) * 4;
        STS4(sb + FQU * 4 + off, qu);
        STS4(sb + FQV * 4 + off, qv);
    }
    if (tid < 64) { sm[FMR + tid] = -3.4e38f; sm[FLR + tid] = 0.f; }

    float o[16];
#pragma unroll
    for (int q = 0; q < 16; q++) o[q] = 0.f;

    const int wmS = wid & 3, wnS = wid >> 2;          // 4x2 warp grid
    const int quad = lane >> 3, r8 = lane & 7;
    const int a_row = wmS * 16 + r8 + (quad & 1) * 8;
    const int a_col = (quad >> 1) * 4;
    const int bS_row = wnS * 32 + r8 + (quad >> 1) * 8;
    const int bQ_row = wnS * 64 + r8 + (quad >> 1) * 8;
    const int b_col = (quad & 1) * 4;
    const int g = lane >> 2, tq = lane & 3;
    const int rg = tid >> 2, dg = tid & 3;

    for (int j0 = 0; j0 <= i0; j0 += 64) {
        __syncthreads();
        // ---- stage raw K, V, P ----
#pragma unroll
        for (int e = 0; e < 4; e++) {
            int f4 = tid + e * 256;
            int j = f4 >> 4, c = (f4 & 15) * 4;
            const float* base = &qkv[((size_t)(b * TT + j0 + j)) * 768 + h * DKK + c];
            float4 k4 = *(const float4*)(base + DM);
            float4 v4 = *(const float4*)(base + 2 * DM);
            uint32_t off = (uint32_t)(j * 68 + c) * 4;
            STS4(sb + FK * 4 + off, k4);
            STS4(sb + FV * 4 + off, v4);
        }
        const int pbase = TT - 1 - (i0 + 63) + j0;
#pragma unroll
        for (int e = 0; e < 8; e++) {
            int f4 = tid + e * 256;
            if (f4 < 127 * 16) {
                int r = f4 >> 4, c = (f4 & 15) * 4;
                float4 p4 = *(const float4*)&p[(size_t)(pbase + r) * DM + h * DKK + c];
                STS4(sb + FP * 4 + (uint32_t)(r * 68 + c) * 4, p4);
            }
        }
        __syncthreads();

        // ---- single-pass tf32x3 score GEMMs ----
        float cS[4][4], cQ[8][4];
#pragma unroll
        for (int nt = 0; nt < 4; nt++)
#pragma unroll
            for (int q = 0; q < 4; q++) cS[nt][q] = 0.f;
#pragma unroll
        for (int nt = 0; nt < 8; nt++)
#pragma unroll
            for (int q = 0; q < 4; q++) cQ[nt][q] = 0.f;

#pragma unroll
        for (int ks = 0; ks < 8; ks++) {
            uint32_t ao = (uint32_t)(a_row * 68 + ks * 8 + a_col) * 4;
            uint32_t raw[4], ah[4], al[4], t[4], th[4], tl[4];
            // S = qu . K^T
            ldsm4(raw, sb + FQU * 4 + ao);
#pragma unroll
            for (int q = 0; q < 4; q++) split2(raw[q], ah[q], al[q]);
            uint32_t bo = (uint32_t)(bS_row * 68 + ks * 8 + b_col) * 4;
#pragma unroll
            for (int half = 0; half < 2; half++) {
                ldsm4(t, sb + FK * 4 + bo + (uint32_t)(half * 16 * 68) * 4);
#pragma unroll
                for (int q = 0; q < 4; q++) split2(t[q], th[q], tl[q]);
                uint32_t bhp[2][2] = {{th[0], th[1]}, {th[2], th[3]}};
                uint32_t blp[2][2] = {{tl[0], tl[1]}, {tl[2], tl[3]}};
#pragma unroll
                for (int k2 = 0; k2 < 2; k2++) {
                    int nt = half * 2 + k2;
                    mma_tf32(cS[nt], ah, bhp[k2]);
                    mma_tf32(cS[nt], al, bhp[k2]);
                    mma_tf32(cS[nt], ah, blp[k2]);
                }
            }
            // QP = qv . P^T
            ldsm4(raw, sb + FQV * 4 + ao);
#pragma unroll
            for (int q = 0; q < 4; q++) split2(raw[q], ah[q], al[q]);
            uint32_t boq = (uint32_t)(bQ_row * 68 + ks * 8 + b_col) * 4;
#pragma unroll
            for (int pr = 0; pr < 4; pr++) {
                ldsm4(t, sb + FP * 4 + boq + (uint32_t)(pr * 16 * 68) * 4);
#pragma unroll
                for (int q = 0; q < 4; q++) split2(t[q], th[q], tl[q]);
                uint32_t bhp[2][2] = {{th[0], th[1]}, {th[2], th[3]}};
                uint32_t blp[2][2] = {{tl[0], tl[1]}, {tl[2], tl[3]}};
#pragma unroll
                for (int k2 = 0; k2 < 2; k2++) {
                    int nt = pr * 2 + k2;
                    mma_tf32(cQ[nt], ah, bhp[k2]);
                    mma_tf32(cQ[nt], al, bhp[k2]);
                    mma_tf32(cQ[nt], ah, blp[k2]);
                }
            }
        }
        // write QP
#pragma unroll
        for (int nt = 0; nt < 8; nt++) {
            int col = wnS * 64 + nt * 8 + tq * 2;
#pragma unroll
            for (int half = 0; half < 2; half++) {
                int row = wmS * 16 + g + half * 8;
                sm[FQP + row * 128 + col]     = cQ[nt][half * 2 + 0];
                sm[FQP + row * 128 + col + 1] = cQ[nt][half * 2 + 1];
            }
        }
        __syncthreads();

        // ---- S epilogue: (cS + QP-shift) * scale -> FS ----
#pragma unroll
        for (int nt = 0; nt < 4; nt++) {
            int col = wnS * 32 + nt * 8 + tq * 2;
#pragma unroll
            for (int half = 0; half < 2; half++) {
                int row = wmS * 16 + g + half * 8;
                int rsh = 63 - row + col;
                sm[FS + row * 68 + col]     = (cS[nt][half*2+0] + sm[FQP + row * 128 + rsh])     * 0.125f;
                sm[FS + row * 68 + col + 1] = (cS[nt][half*2+1] + sm[FQP + row * 128 + rsh + 1]) * 0.125f;
            }
        }
        __syncthreads();

        // ---- online softmax ----
        {
            const int i = i0 + rg;
            float mloc = -3.4e38f;
#pragma unroll
            for (int k = 0; k < 16; k++) {
                int jj = dg + k * 4;
                int j = j0 + jj;
                bool ok = (j <= i) && (j < len);
                float v = ok ? sm[FS + rg * 68 + jj] : -3.4e38f;
                mloc = fmaxf(mloc, v);
            }
            mloc = fmaxf(mloc, __shfl_xor_sync(0xffffffffu, mloc, 1));
            mloc = fmaxf(mloc, __shfl_xor_sync(0xffffffffu, mloc, 2));
            float mold = sm[FMR + rg];
            float mnew = fmaxf(mold, mloc);
            float fac = expf(mold - mnew);
            float ssum = 0.f;
#pragma unroll
            for (int k = 0; k < 16; k++) {
                int jj = dg + k * 4;
                int j = j0 + jj;
                bool ok = (j <= i) && (j < len);
                float e = ok ? expf(sm[FS + rg * 68 + jj] - mnew) : 0.f;
                sm[FS + rg * 68 + jj] = e;
                ssum += e;
            }
            ssum += __shfl_xor_sync(0xffffffffu, ssum, 1);
            ssum += __shfl_xor_sync(0xffffffffu, ssum, 2);
            if (dg == 0) {
                sm[FMR + rg] = mnew;
                sm[FLR + rg] = sm[FLR + rg] * fac + ssum;
                sm[FFR + rg] = fac;
            }
        }
        __syncthreads();

        // ---- AV accumulate (scalar) ----
        {
            float fac = sm[FFR + rg];
#pragma unroll
            for (int q = 0; q < 16; q++) o[q] *= fac;
            for (int j = 0; j < 64; j++) {
                float w = sm[FS + rg * 68 + j];
                float4 v0 = *(const float4*)&sm[FV + j * 68 + dg * 16 + 0];
                float4 v1 = *(const float4*)&sm[FV + j * 68 + dg * 16 + 4];
                float4 v2 = *(const float4*)&sm[FV + j * 68 + dg * 16 + 8];
                float4 v3 = *(const float4*)&sm[FV + j * 68 + dg * 16 + 12];
                o[0]  += w * v0.x; o[1]  += w * v0.y; o[2]  += w * v0.z; o[3]  += w * v0.w;
                o[4]  += w * v1.x; o[5]  += w * v1.y; o[6]  += w * v1.z; o[7]  += w * v1.w;
                o[8]  += w * v2.x; o[9]  += w * v2.y; o[10] += w * v2.z; o[11] += w * v2.w;
                o[12] += w * v3.x; o[13] += w * v3.y; o[14] += w * v3.z; o[15] += w * v3.w;
            }
        }
    }

    float inv = 1.f / sm[FLR + rg];
    float* dst = &att[((size_t)(b * TT + i0 + rg)) * DM + h * DKK + dg * 16];
#pragma unroll
    for (int q4 = 0; q4 < 4; q4++) {
        float4 w;
        w.x = o[q4 * 4 + 0] * inv; w.y = o[q4 * 4 + 1] * inv;
        w.z = o[q4 * 4 + 2] * inv; w.w = o[q4 * 4 + 3] * inv;
        *(float4*)(dst + q4 * 4) = w;
    }
}

// ---------------- final copy ----------------
__global__ void out_kernel(const float* __restrict__ x, const int* __restrict__ lens,
                           float* __restrict__ out, int out_size) {
    int idx = blockIdx.x * 256 + threadIdx.x;
    const int n = BB * TT * DM;
    if (idx < n) out[idx] = x[idx];
    if (idx < BB && out_size >= n + BB) out[n + idx] = (float)lens[idx];
}

extern "C" void kernel_launch(void* const* d_in, const int* in_sizes, int n_in,
                              void* d_out, int out_size) {
    const float* x        = (const float*)d_in[0];
    const int*   lens     = (const int*)  d_in[1];
    const float* embed_W  = (const float*)d_in[2];
    const float* embed_b  = (const float*)d_in[3];
    const float* in_projW = (const float*)d_in[4];
    const float* in_projb = (const float*)d_in[5];
    const float* pos_W    = (const float*)d_in[6];
    const float* pbu      = (const float*)d_in[7];
    const float* pbv      = (const float*)d_in[8];
    const float* out_W    = (const float*)d_in[9];
    const float* out_b    = (const float*)d_in[10];
    const float* ff1_W    = (const float*)d_in[11];
    const float* ff1_b    = (const float*)d_in[12];
    const float* ff2_W    = (const float*)d_in[13];
    const float* ff2_b    = (const float*)d_in[14];

    float *xbuf, *qkvb, *peb, *pbuf, *attb, *hbuf;
    cudaGetSymbolAddress((void**)&xbuf, g_x);
    cudaGetSymbolAddress((void**)&qkvb, g_qkv);
    cudaGetSymbolAddress((void**)&peb,  g_pe);
    cudaGetSymbolAddress((void**)&pbuf, g_p);
    cudaGetSymbolAddress((void**)&attb, g_att);
    cudaGetSymbolAddress((void**)&hbuf, g_h);

    cudaFuncSetAttribute(flash_kernel, cudaFuncAttributeMaxDynamicSharedMemorySize, FL_SMEM);
    cudaFuncSetAttribute(mma_gemm, cudaFuncAttributeMaxDynamicSharedMemorySize, MMA_SMEM);

    const int M = BB * TT;

    pe_kernel<<<PP, DM>>>();
    gemm_kernel<<<dim3(DM/128, M/128), 256>>>(x, embed_W, embed_b, nullptr, xbuf, M, DM, IND, 0);
    norm_kernel<<<M, DM>>>(xbuf);

    for (int l = 0; l < NL; l++) {
        mma_gemm<<<dim3(768/128, M/128), 256, MMA_SMEM>>>(
            xbuf, in_projW + (size_t)l*3*DM*DM, in_projb + (size_t)l*3*DM,
            nullptr, qkvb, M, 3*DM, DM, 0);
        mma_gemm<<<dim3(DM/128, 16), 256, MMA_SMEM>>>(
            peb, pos_W + (size_t)l*DM*DM, nullptr, nullptr, pbuf, PP, DM, DM, 0);
        flash_kernel<<<dim3(TT/64, NH, BB), 256, FL_SMEM>>>(
            qkvb, pbuf, pbu + (size_t)l*NH*DKK, pbv + (size_t)l*NH*DKK, lens, attb);
        mma_gemm<<<dim3(DM/128, M/128), 256, MMA_SMEM>>>(
            attb, out_W + (size_t)l*DM*DM, out_b + (size_t)l*DM, xbuf, xbuf, M, DM, DM, 0);
        mma_gemm<<<dim3(FFD/128, M/128), 256, MMA_SMEM>>>(
            xbuf, ff1_W + (size_t)l*FFD*DM, ff1_b + (size_t)l*FFD, nullptr, hbuf, M, FFD, DM, 1);
        mma_gemm<<<dim3(DM/128, M/128), 256, MMA_SMEM>>>(
            hbuf, ff2_W + (size_t)l*DM*FFD, ff2_b + (size_t)l*DM, xbuf, xbuf, M, DM, FFD, 0);
        norm_kernel<<<M, DM>>>(xbuf);
    }

    int n = BB * TT * DM;
    out_kernel<<<(n + 255)/256, 256>>>(xbuf, lens, (float*)d_out, out_size);
}

// round 12
// speedup vs baseline: 3.0481x; 1.0376x over previous
#include <cuda_runtime.h>
#include <math.h>
#include <stdint.h>

#define BB 8
#define TT 1024
#define IND 80
#define DM 256
#define NH 4
#define DKK 64
#define FFD 2048
#define NL 6
#define PP (2*TT-1)

// ---------------- device scratch (allocation-free) ----------------
__device__ float g_x[BB*TT*DM];
__device__ float g_qkv[BB*TT*3*DM];
__device__ float g_pe[PP*DM];
__device__ float g_p[PP*DM];
__device__ float g_att[BB*TT*DM];
__device__ float g_h[BB*TT*FFD];

// ================= helpers =================
__device__ __forceinline__ uint32_t smem_u32(const void* p) {
    uint32_t a;
    asm("{ .reg .u64 t; cvta.to.shared.u64 t, %1; cvt.u32.u64 %0, t; }" : "=r"(a) : "l"(p));
    return a;
}
// tf32 mma HW reads top 19 bits of the f32 register and ignores the low 13.
// hi = masked-truncate (LOP3, alu pipe); lo = exact residual (FADD, fma pipe).
__device__ __forceinline__ void split2(uint32_t raw, uint32_t& h, uint32_t& l) {
    h = raw & 0xFFFFE000u;
    l = __float_as_uint(__uint_as_float(raw) - __uint_as_float(h));
}
__device__ __forceinline__ void ldsm4(uint32_t* r, uint32_t addr) {
    asm volatile("ldmatrix.sync.aligned.m8n8.x4.shared.b16 {%0,%1,%2,%3}, [%4];"
        : "=r"(r[0]), "=r"(r[1]), "=r"(r[2]), "=r"(r[3]) : "r"(addr));
}
__device__ __forceinline__ void mma_tf32(float* c, const uint32_t* a, const uint32_t* b) {
    asm volatile(
        "mma.sync.aligned.m16n8k8.row.col.f32.tf32.tf32.f32 "
        "{%0,%1,%2,%3}, {%4,%5,%6,%7}, {%8,%9}, {%0,%1,%2,%3};"
        : "+f"(c[0]), "+f"(c[1]), "+f"(c[2]), "+f"(c[3])
        : "r"(a[0]), "r"(a[1]), "r"(a[2]), "r"(a[3]), "r"(b[0]), "r"(b[1]));
}
__device__ __forceinline__ void cpasync16(uint32_t saddr, const void* g) {
    asm volatile("cp.async.cg.shared.global [%0], [%1], 16;" :: "r"(saddr), "l"(g) : "memory");
}
#define CP_COMMIT() asm volatile("cp.async.commit_group;" ::: "memory")
#define CP_WAIT2()  asm volatile("cp.async.wait_group 2;" ::: "memory")
#define CP_WAIT1()  asm volatile("cp.async.wait_group 1;" ::: "memory")
#define CP_WAIT0()  asm volatile("cp.async.wait_group 0;" ::: "memory")
#define STS4(addr, v) asm volatile("st.shared.v4.b32 [%0], {%1,%2,%3,%4};" :: "r"(addr), \
    "r"(__float_as_uint((v).x)), "r"(__float_as_uint((v).y)), \
    "r"(__float_as_uint((v).z)), "r"(__float_as_uint((v).w)) : "memory")

// ================= mma.sync tf32x3 GEMM (3-stage cp.async pipeline) =================
// C = A(MxK) @ W(NxK)^T. N mult of 128, K mult of 32, M arbitrary.
#define TROW 36
#define PSTAGE (128*TROW)                  // floats per tile
#define NSTG 3
#define MMA_SMEM (NSTG*2*PSTAGE*4)

__global__ __launch_bounds__(256) void mma_gemm(
    const float* __restrict__ A, const float* __restrict__ W,
    const float* __restrict__ bias, const float* __restrict__ res,
    float* __restrict__ C, int M, int N, int K, int act)
{
    extern __shared__ float dsm[];
    const uint32_t sb = smem_u32(dsm);
    const int tid = threadIdx.x;
    const int wid = tid >> 5, lane = tid & 31;
    const int wm = wid >> 2, wn = wid & 3;          // warp grid 2x4
    const int bm = blockIdx.y * 128, bn = blockIdx.x * 128;

    float c[4][4][4];
#pragma unroll
    for (int mt = 0; mt < 4; mt++)
#pragma unroll
        for (int nt = 0; nt < 4; nt++)
#pragma unroll
            for (int q = 0; q < 4; q++) c[mt][nt][q] = 0.f;

    const int quad = lane >> 3, r8 = lane & 7;
    const int a_row = wm * 64 + r8 + (quad & 1) * 8;
    const int a_col = (quad >> 1) * 4;
    const int b_row = wn * 32 + r8 + (quad >> 1) * 8;
    const int b_col = (quad & 1) * 4;

    const int srow = tid >> 3, skq = tid & 7;
    const int nchunk = K / 32;

    auto issue = [&](int cc) {
        const int s = cc % NSTG;
        const int k0 = cc * 32;
        const uint32_t sA = sb + (uint32_t)(s * 2 * PSTAGE) * 4;
        const uint32_t sB = sA + (uint32_t)PSTAGE * 4;
#pragma unroll
        for (int e = 0; e < 4; e++) {
            int row = srow + e * 32;
            int ar = bm + row; if (ar >= M) ar = M - 1;
            uint32_t off = (uint32_t)(row * TROW + skq * 4) * 4;
            cpasync16(sA + off, &A[(size_t)ar * K + k0 + skq * 4]);
            cpasync16(sB + off, &W[(size_t)(bn + row) * K + k0 + skq * 4]);
        }
        CP_COMMIT();
    };

    issue(0);
    if (nchunk > 1) issue(1);
    for (int cc = 0; cc < nchunk; cc++) {
        if (cc + 2 < nchunk) issue(cc + 2);
        int rem = ((cc + 3 < nchunk ? cc + 3 : nchunk)) - cc - 1;   // pending newer groups
        if (rem >= 2) CP_WAIT2(); else if (rem == 1) CP_WAIT1(); else CP_WAIT0();
        __syncthreads();
        const int s = cc % NSTG;
        const uint32_t sA = sb + (uint32_t)(s * 2 * PSTAGE) * 4;
        const uint32_t sB = sA + (uint32_t)PSTAGE * 4;
#pragma unroll
        for (int ks = 0; ks < 4; ks++) {
            uint32_t ah[4][4], al[4][4], bh[4][2], bl[4][2];
#pragma unroll
            for (int mt = 0; mt < 4; mt++) {
                uint32_t raw[4];
                ldsm4(raw, sA + (uint32_t)((a_row + mt * 16) * TROW + ks * 8 + a_col) * 4);
#pragma unroll
                for (int q = 0; q < 4; q++) split2(raw[q], ah[mt][q], al[mt][q]);
            }
            {
                uint32_t t[4], th[4], tl[4];
                uint32_t bo = (uint32_t)(b_row * TROW + ks * 8 + b_col) * 4;
                ldsm4(t, sB + bo);
#pragma unroll
                for (int q = 0; q < 4; q++) split2(t[q], th[q], tl[q]);
                bh[0][0] = th[0]; bh[0][1] = th[1]; bh[1][0] = th[2]; bh[1][1] = th[3];
                bl[0][0] = tl[0]; bl[0][1] = tl[1]; bl[1][0] = tl[2]; bl[1][1] = tl[3];
                ldsm4(t, sB + bo + (uint32_t)(16 * TROW) * 4);
#pragma unroll
                for (int q = 0; q < 4; q++) split2(t[q], th[q], tl[q]);
                bh[2][0] = th[0]; bh[2][1] = th[1]; bh[3][0] = th[2]; bh[3][1] = th[3];
                bl[2][0] = tl[0]; bl[2][1] = tl[1]; bl[3][0] = tl[2]; bl[3][1] = tl[3];
            }
#pragma unroll
            for (int mt = 0; mt < 4; mt++)
#pragma unroll
                for (int nt = 0; nt < 4; nt++) {
                    mma_tf32(c[mt][nt], ah[mt], bh[nt]);
                    mma_tf32(c[mt][nt], al[mt], bh[nt]);
                    mma_tf32(c[mt][nt], ah[mt], bl[nt]);
                }
        }
        __syncthreads();
    }

    const int g = lane >> 2, tq = lane & 3;
#pragma unroll
    for (int mt = 0; mt < 4; mt++) {
#pragma unroll
        for (int nt = 0; nt < 4; nt++) {
            int col = bn + wn * 32 + nt * 8 + tq * 2;
            float b0 = 0.f, b1 = 0.f;
            if (bias) { b0 = bias[col]; b1 = bias[col + 1]; }
#pragma unroll
            for (int half = 0; half < 2; half++) {
                int row = bm + wm * 64 + mt * 16 + g + half * 8;
                if (row >= M) continue;
                float v0 = c[mt][nt][half * 2 + 0] + b0;
                float v1 = c[mt][nt][half * 2 + 1] + b1;
                if (act == 1) {
                    v0 = v0 / (1.f + expf(1.f - v0));
                    v1 = v1 / (1.f + expf(1.f - v1));
                }
                if (res) {
                    const float2 r2 = *(const float2*)&res[(size_t)row * N + col];
                    v0 += r2.x; v1 += r2.y;
                }
                float2 o2; o2.x = v0; o2.y = v1;
                *(float2*)&C[(size_t)row * N + col] = o2;
            }
        }
    }
}

// ---------------- relative positional encoding ----------------
__global__ void pe_kernel() {
    int r = blockIdx.x;
    int d = threadIdx.x;
    float pos, sign;
    if (r < TT) { pos = (float)(TT - 1 - r); sign = 1.f; }
    else        { pos = (float)(r - TT + 1); sign = -1.f; }
    int j2 = (d >> 1) << 1;
    float div = expf(-(float)j2 * (logf(10000.f) / (float)DM));
    float ang = sign * pos * div;
    g_pe[r * DM + d] = (d & 1) ? cosf(ang) : sinf(ang);
}

// ---------------- fallback SGEMM (embed only) ----------------
__global__ __launch_bounds__(256) void gemm_kernel(
    const float* __restrict__ A, const float* __restrict__ W,
    const float* __restrict__ bias, const float* __restrict__ res,
    float* __restrict__ C, int M, int N, int K, int act)
{
    __shared__ float As[16][128];
    __shared__ float Bs[16][128];
    const int bm = blockIdx.y * 128;
    const int bn = blockIdx.x * 128;
    const int tid = threadIdx.x;
    const int tm = tid >> 4, tn = tid & 15;

    float acc[8][8];
#pragma unroll
    for (int i = 0; i < 8; i++)
#pragma unroll
        for (int j = 0; j < 8; j++) acc[i][j] = 0.f;

    for (int k0 = 0; k0 < K; k0 += 16) {
#pragma unroll
        for (int e = 0; e < 8; e++) {
            int flat = tid + e * 256;
            int row = flat >> 4, kk = flat & 15;
            int ar = bm + row;
            As[kk][row] = (ar < M) ? A[(size_t)ar * K + k0 + kk] : 0.f;
            int wr = bn + row;
            Bs[kk][row] = (wr < N) ? W[(size_t)wr * K + k0 + kk] : 0.f;
        }
        __syncthreads();
#pragma unroll
        for (int kk = 0; kk < 16; kk++) {
            float4 a0 = *(const float4*)&As[kk][tm * 8];
            float4 a1 = *(const float4*)&As[kk][tm * 8 + 4];
            float4 b0 = *(const float4*)&Bs[kk][tn * 8];
            float4 b1 = *(const float4*)&Bs[kk][tn * 8 + 4];
            float a[8] = {a0.x,a0.y,a0.z,a0.w,a1.x,a1.y,a1.z,a1.w};
            float b[8] = {b0.x,b0.y,b0.z,b0.w,b1.x,b1.y,b1.z,b1.w};
#pragma unroll
            for (int i = 0; i < 8; i++)
#pragma unroll
                for (int j = 0; j < 8; j++) acc[i][j] += a[i] * b[j];
        }
        __syncthreads();
    }
#pragma unroll
    for (int i = 0; i < 8; i++) {
        int row = bm + tm * 8 + i;
        if (row >= M) continue;
#pragma unroll
        for (int j = 0; j < 8; j++) {
            int col = bn + tn * 8 + j;
            float c = acc[i][j];
            if (bias) c += bias[col];
            if (act == 1) c = c / (1.f + expf(1.f - c));
            if (res) c += res[(size_t)row * N + col];
            C[(size_t)row * N + col] = c;
        }
    }
}

// ---------------- BasicNorm ----------------
__global__ __launch_bounds__(DM) void norm_kernel(float* __restrict__ x) {
    int row = blockIdx.x, tid = threadIdx.x;
    float v = x[(size_t)row * DM + tid];
    float s = v * v;
#pragma unroll
    for (int o = 16; o; o >>= 1) s += __shfl_xor_sync(0xffffffffu, s, o);
    __shared__ float sm[8];
    int warp = tid >> 5, lane = tid & 31;
    if (lane == 0) sm[warp] = s;
    __syncthreads();
    if (warp == 0) {
        float t = (lane < 8) ? sm[lane] : 0.f;
#pragma unroll
        for (int o = 4; o; o >>= 1) t += __shfl_xor_sync(0xffffffffu, t, o);
        if (lane == 0) sm[0] = t;
    }
    __syncthreads();
    float scale = rsqrtf(sm[0] / (float)DM + 0.25f);
    x[(size_t)row * DM + tid] = v * scale;
}

// ================= flash attention, tf32x3 mma scores, raw staging =================
#define FQU 0
#define FQV (FQU + 64*68)
#define FK  (FQV + 64*68)
#define FV  (FK + 64*68)
#define FP  (FV + 64*68)        // [128][68]
#define FQP (FP + 128*68)       // [64][128]
#define FS  (FQP + 64*128)      // [64][68]
#define FMR (FS + 64*68)
#define FLR (FMR + 64)
#define FFR (FLR + 64)
#define FL_SMEM ((FFR + 64) * 4)

__global__ __launch_bounds__(256) void flash_kernel(
    const float* __restrict__ qkv, const float* __restrict__ p,
    const float* __restrict__ ub, const float* __restrict__ vb,
    const int* __restrict__ lens, float* __restrict__ att)
{
    extern __shared__ float sm[];
    const uint32_t sb = smem_u32(sm);
    const int i0 = blockIdx.x * 64;
    const int h  = blockIdx.y;
    const int b  = blockIdx.z;
    const int tid = threadIdx.x;
    const int wid = tid >> 5, lane = tid & 31;
    const int len = lens[b];

    // ---- prologue: raw qu/qv ----
#pragma unroll
    for (int e = 0; e < 4; e++) {
        int f4 = tid + e * 256;
        int row = f4 >> 4, c = (f4 & 15) * 4;
        float4 q4 = *(const float4*)&qkv[((size_t)(b * TT + i0 + row)) * 768 + h * DKK + c];
        float4 u4 = *(const float4*)&ub[h * DKK + c];
        float4 v4 = *(const float4*)&vb[h * DKK + c];
        float4 qu, qv;
        qu.x = q4.x + u4.x; qu.y = q4.y + u4.y; qu.z = q4.z + u4.z; qu.w = q4.w + u4.w;
        qv.x = q4.x + v4.x; qv.y = q4.y + v4.y; qv.z = q4.z + v4.z; qv.w = q4.w + v4.w;
        uint32_t off = (uint32_t)(row * 68 + c) * 4;
        STS4(sb + FQU * 4 + off, qu);
        STS4(sb + FQV * 4 + off, qv);
    }
    if (tid < 64) { sm[FMR + tid] = -3.4e38f; sm[FLR + tid] = 0.f; }

    float o[16];
#pragma unroll
    for (int q = 0; q < 16; q++) o[q] = 0.f;

    const int wmS = wid & 3, wnS = wid >> 2;          // 4x2 warp grid
    const int quad = lane >> 3, r8 = lane & 7;
    const int a_row = wmS * 16 + r8 + (quad & 1) * 8;
    const int a_col = (quad >> 1) * 4;
    const int bS_row = wnS * 32 + r8 + (quad >> 1) * 8;
    const int bQ_row = wnS * 64 + r8 + (quad >> 1) * 8;
    const int b_col = (quad & 1) * 4;
    const int g = lane >> 2, tq = lane & 3;
    const int rg = tid >> 2, dg = tid & 3;

    for (int j0 = 0; j0 <= i0; j0 += 64) {
        __syncthreads();
        // ---- stage raw K, V, P ----
#pragma unroll
        for (int e = 0; e < 4; e++) {
            int f4 = tid + e * 256;
            int j = f4 >> 4, c = (f4 & 15) * 4;
            const float* base = &qkv[((size_t)(b * TT + j0 + j)) * 768 + h * DKK + c];
            float4 k4 = *(const float4*)(base + DM);
            float4 v4 = *(const float4*)(base + 2 * DM);
            uint32_t off = (uint32_t)(j * 68 + c) * 4;
            STS4(sb + FK * 4 + off, k4);
            STS4(sb + FV * 4 + off, v4);
        }
        const int pbase = TT - 1 - (i0 + 63) + j0;
#pragma unroll
        for (int e = 0; e < 8; e++) {
            int f4 = tid + e * 256;
            if (f4 < 127 * 16) {
                int r = f4 >> 4, c = (f4 & 15) * 4;
                float4 p4 = *(const float4*)&p[(size_t)(pbase + r) * DM + h * DKK + c];
                STS4(sb + FP * 4 + (uint32_t)(r * 68 + c) * 4, p4);
            }
        }
        __syncthreads();

        // ---- single-pass tf32x3 score GEMMs ----
        float cS[4][4], cQ[8][4];
#pragma unroll
        for (int nt = 0; nt < 4; nt++)
#pragma unroll
            for (int q = 0; q < 4; q++) cS[nt][q] = 0.f;
#pragma unroll
        for (int nt = 0; nt < 8; nt++)
#pragma unroll
            for (int q = 0; q < 4; q++) cQ[nt][q] = 0.f;

#pragma unroll
        for (int ks = 0; ks < 8; ks++) {
            uint32_t ao = (uint32_t)(a_row * 68 + ks * 8 + a_col) * 4;
            uint32_t raw[4], ah[4], al[4], t[4], th[4], tl[4];
            // S = qu . K^T
            ldsm4(raw, sb + FQU * 4 + ao);
#pragma unroll
            for (int q = 0; q < 4; q++) split2(raw[q], ah[q], al[q]);
            uint32_t bo = (uint32_t)(bS_row * 68 + ks * 8 + b_col) * 4;
#pragma unroll
            for (int half = 0; half < 2; half++) {
                ldsm4(t, sb + FK * 4 + bo + (uint32_t)(half * 16 * 68) * 4);
#pragma unroll
                for (int q = 0; q < 4; q++) split2(t[q], th[q], tl[q]);
                uint32_t bhp[2][2] = {{th[0], th[1]}, {th[2], th[3]}};
                uint32_t blp[2][2] = {{tl[0], tl[1]}, {tl[2], tl[3]}};
#pragma unroll
                for (int k2 = 0; k2 < 2; k2++) {
                    int nt = half * 2 + k2;
                    mma_tf32(cS[nt], ah, bhp[k2]);
                    mma_tf32(cS[nt], al, bhp[k2]);
                    mma_tf32(cS[nt], ah, blp[k2]);
                }
            }
            // QP = qv . P^T
            ldsm4(raw, sb + FQV * 4 + ao);
#pragma unroll
            for (int q = 0; q < 4; q++) split2(raw[q], ah[q], al[q]);
            uint32_t boq = (uint32_t)(bQ_row * 68 + ks * 8 + b_col) * 4;
#pragma unroll
            for (int pr = 0; pr < 4; pr++) {
                ldsm4(t, sb + FP * 4 + boq + (uint32_t)(pr * 16 * 68) * 4);
#pragma unroll
                for (int q = 0; q < 4; q++) split2(t[q], th[q], tl[q]);
                uint32_t bhp[2][2] = {{th[0], th[1]}, {th[2], th[3]}};
                uint32_t blp[2][2] = {{tl[0], tl[1]}, {tl[2], tl[3]}};
#pragma unroll
                for (int k2 = 0; k2 < 2; k2++) {
                    int nt = pr * 2 + k2;
                    mma_tf32(cQ[nt], ah, bhp[k2]);
                    mma_tf32(cQ[nt], al, bhp[k2]);
                    mma_tf32(cQ[nt], ah, blp[k2]);
                }
            }
        }
        // write QP
#pragma unroll
        for (int nt = 0; nt < 8; nt++) {
            int col = wnS * 64 + nt * 8 + tq * 2;
#pragma unroll
            for (int half = 0; half < 2; half++) {
                int row = wmS * 16 + g + half * 8;
                sm[FQP + row * 128 + col]     = cQ[nt][half * 2 + 0];
                sm[FQP + row * 128 + col + 1] = cQ[nt][half * 2 + 1];
            }
        }
        __syncthreads();

        // ---- S epilogue: (cS + QP-shift) * scale -> FS ----
#pragma unroll
        for (int nt = 0; nt < 4; nt++) {
            int col = wnS * 32 + nt * 8 + tq * 2;
#pragma unroll
            for (int half = 0; half < 2; half++) {
                int row = wmS * 16 + g + half * 8;
                int rsh = 63 - row + col;
                sm[FS + row * 68 + col]     = (cS[nt][half*2+0] + sm[FQP + row * 128 + rsh])     * 0.125f;
                sm[FS + row * 68 + col + 1] = (cS[nt][half*2+1] + sm[FQP + row * 128 + rsh + 1]) * 0.125f;
            }
        }
        __syncthreads();

        // ---- online softmax ----
        {
            const int i = i0 + rg;
            float mloc = -3.4e38f;
#pragma unroll
            for (int k = 0; k < 16; k++) {
                int jj = dg + k * 4;
                int j = j0 + jj;
                bool ok = (j <= i) && (j < len);
                float v = ok ? sm[FS + rg * 68 + jj] : -3.4e38f;
                mloc = fmaxf(mloc, v);
            }
            mloc = fmaxf(mloc, __shfl_xor_sync(0xffffffffu, mloc, 1));
            mloc = fmaxf(mloc, __shfl_xor_sync(0xffffffffu, mloc, 2));
            float mold = sm[FMR + rg];
            float mnew = fmaxf(mold, mloc);
            float fac = expf(mold - mnew);
            float ssum = 0.f;
#pragma unroll
            for (int k = 0; k < 16; k++) {
                int jj = dg + k * 4;
                int j = j0 + jj;
                bool ok = (j <= i) && (j < len);
                float e = ok ? expf(sm[FS + rg * 68 + jj] - mnew) : 0.f;
                sm[FS + rg * 68 + jj] = e;
                ssum += e;
            }
            ssum += __shfl_xor_sync(0xffffffffu, ssum, 1);
            ssum += __shfl_xor_sync(0xffffffffu, ssum, 2);
            if (dg == 0) {
                sm[FMR + rg] = mnew;
                sm[FLR + rg] = sm[FLR + rg] * fac + ssum;
                sm[FFR + rg] = fac;
            }
        }
        __syncthreads();

        // ---- AV accumulate (scalar) ----
        {
            float fac = sm[FFR + rg];
#pragma unroll
            for (int q = 0; q < 16; q++) o[q] *= fac;
            for (int j = 0; j < 64; j++) {
                float w = sm[FS + rg * 68 + j];
                float4 v0 = *(const float4*)&sm[FV + j * 68 + dg * 16 + 0];
                float4 v1 = *(const float4*)&sm[FV + j * 68 + dg * 16 + 4];
                float4 v2 = *(const float4*)&sm[FV + j * 68 + dg * 16 + 8];
                float4 v3 = *(const float4*)&sm[FV + j * 68 + dg * 16 + 12];
                o[0]  += w * v0.x; o[1]  += w * v0.y; o[2]  += w * v0.z; o[3]  += w * v0.w;
                o[4]  += w * v1.x; o[5]  += w * v1.y; o[6]  += w * v1.z; o[7]  += w * v1.w;
                o[8]  += w * v2.x; o[9]  += w * v2.y; o[10] += w * v2.z; o[11] += w * v2.w;
                o[12] += w * v3.x; o[13] += w * v3.y; o[14] += w * v3.z; o[15] += w * v3.w;
            }
        }
    }

    float inv = 1.f / sm[FLR + rg];
    float* dst = &att[((size_t)(b * TT + i0 + rg)) * DM + h * DKK + dg * 16];
#pragma unroll
    for (int q4 = 0; q4 < 4; q4++) {
        float4 w;
        w.x = o[q4 * 4 + 0] * inv; w.y = o[q4 * 4 + 1] * inv;
        w.z = o[q4 * 4 + 2] * inv; w.w = o[q4 * 4 + 3] * inv;
        *(float4*)(dst + q4 * 4) = w;
    }
}

// ---------------- final copy ----------------
__global__ void out_kernel(const float* __restrict__ x, const int* __restrict__ lens,
                           float* __restrict__ out, int out_size) {
    int idx = blockIdx.x * 256 + threadIdx.x;
    const int n = BB * TT * DM;
    if (idx < n) out[idx] = x[idx];
    if (idx < BB && out_size >= n + BB) out[n + idx] = (float)lens[idx];
}

extern "C" void kernel_launch(void* const* d_in, const int* in_sizes, int n_in,
                              void* d_out, int out_size) {
    const float* x        = (const float*)d_in[0];
    const int*   lens     = (const int*)  d_in[1];
    const float* embed_W  = (const float*)d_in[2];
    const float* embed_b  = (const float*)d_in[3];
    const float* in_projW = (const float*)d_in[4];
    const float* in_projb = (const float*)d_in[5];
    const float* pos_W    = (const float*)d_in[6];
    const float* pbu      = (const float*)d_in[7];
    const float* pbv      = (const float*)d_in[8];
    const float* out_W    = (const float*)d_in[9];
    const float* out_b    = (const float*)d_in[10];
    const float* ff1_W    = (const float*)d_in[11];
    const float* ff1_b    = (const float*)d_in[12];
    const float* ff2_W    = (const float*)d_in[13];
    const float* ff2_b    = (const float*)d_in[14];

    float *xbuf, *qkvb, *peb, *pbuf, *attb, *hbuf;
    cudaGetSymbolAddress((void**)&xbuf, g_x);
    cudaGetSymbolAddress((void**)&qkvb, g_qkv);
    cudaGetSymbolAddress((void**)&peb,  g_pe);
    cudaGetSymbolAddress((void**)&pbuf, g_p);
    cudaGetSymbolAddress((void**)&attb, g_att);
    cudaGetSymbolAddress((void**)&hbuf, g_h);

    cudaFuncSetAttribute(flash_kernel, cudaFuncAttributeMaxDynamicSharedMemorySize, FL_SMEM);
    cudaFuncSetAttribute(mma_gemm, cudaFuncAttributeMaxDynamicSharedMemorySize, MMA_SMEM);

    const int M = BB * TT;

    pe_kernel<<<PP, DM>>>();
    gemm_kernel<<<dim3(DM/128, M/128), 256>>>(x, embed_W, embed_b, nullptr, xbuf, M, DM, IND, 0);
    norm_kernel<<<M, DM>>>(xbuf);

    for (int l = 0; l < NL; l++) {
        mma_gemm<<<dim3(768/128, M/128), 256, MMA_SMEM>>>(
            xbuf, in_projW + (size_t)l*3*DM*DM, in_projb + (size_t)l*3*DM,
            nullptr, qkvb, M, 3*DM, DM, 0);
        mma_gemm<<<dim3(DM/128, 16), 256, MMA_SMEM>>>(
            peb, pos_W + (size_t)l*DM*DM, nullptr, nullptr, pbuf, PP, DM, DM, 0);
        flash_kernel<<<dim3(TT/64, NH, BB), 256, FL_SMEM>>>(
            qkvb, pbuf, pbu + (size_t)l*NH*DKK, pbv + (size_t)l*NH*DKK, lens, attb);
        mma_gemm<<<dim3(DM/128, M/128), 256, MMA_SMEM>>>(
            attb, out_W + (size_t)l*DM*DM, out_b + (size_t)l*DM, xbuf, xbuf, M, DM, DM, 0);
        mma_gemm<<<dim3(FFD/128, M/128), 256, MMA_SMEM>>>(
            xbuf, ff1_W + (size_t)l*FFD*DM, ff1_b + (size_t)l*FFD, nullptr, hbuf, M, FFD, DM, 1);
        mma_gemm<<<dim3(DM/128, M/128), 256, MMA_SMEM>>>(
            hbuf, ff2_W + (size_t)l*DM*FFD, ff2_b + (size_t)l*DM, xbuf, xbuf, M, DM, FFD, 0);
        norm_kernel<<<M, DM>>>(xbuf);
    }

    int n = BB * TT * DM;
    out_kernel<<<(n + 255)/256, 256>>>(xbuf, lens, (float*)d_out, out_size);
}

// round 13
// speedup vs baseline: 4.1900x; 1.3746x over previous
#include <cuda_runtime.h>
#include <math.h>
#include <stdint.h>

#define BB 8
#define TT 1024
#define IND 80
#define DM 256
#define NH 4
#define DKK 64
#define FFD 2048
#define NL 6
#define PP (2*TT-1)

// ---------------- device scratch (allocation-free) ----------------
__device__ float g_x[BB*TT*DM];
__device__ float g_qkv[BB*TT*3*DM];
__device__ float g_pe[PP*DM];
__device__ float g_p[PP*DM];
__device__ float g_att[BB*TT*DM];
__device__ float g_h[BB*TT*FFD];

// ================= helpers =================
__device__ __forceinline__ uint32_t smem_u32(const void* p) {
    uint32_t a;
    asm("{ .reg .u64 t; cvta.to.shared.u64 t, %1; cvt.u32.u64 %0, t; }" : "=r"(a) : "l"(p));
    return a;
}
// tf32 mma HW reads top 19 bits of the f32 register and ignores the low 13.
__device__ __forceinline__ void split2(uint32_t raw, uint32_t& h, uint32_t& l) {
    h = raw & 0xFFFFE000u;
    l = __float_as_uint(__uint_as_float(raw) - __uint_as_float(h));
}
__device__ __forceinline__ void ldsm4(uint32_t* r, uint32_t addr) {
    asm volatile("ldmatrix.sync.aligned.m8n8.x4.shared.b16 {%0,%1,%2,%3}, [%4];"
        : "=r"(r[0]), "=r"(r[1]), "=r"(r[2]), "=r"(r[3]) : "r"(addr));
}
__device__ __forceinline__ void mma_tf32(float* c, const uint32_t* a, const uint32_t* b) {
    asm volatile(
        "mma.sync.aligned.m16n8k8.row.col.f32.tf32.tf32.f32 "
        "{%0,%1,%2,%3}, {%4,%5,%6,%7}, {%8,%9}, {%0,%1,%2,%3};"
        : "+f"(c[0]), "+f"(c[1]), "+f"(c[2]), "+f"(c[3])
        : "r"(a[0]), "r"(a[1]), "r"(a[2]), "r"(a[3]), "r"(b[0]), "r"(b[1]));
}
__device__ __forceinline__ void cpasync16(uint32_t saddr, const void* g) {
    asm volatile("cp.async.cg.shared.global [%0], [%1], 16;" :: "r"(saddr), "l"(g) : "memory");
}
#define CP_COMMIT() asm volatile("cp.async.commit_group;" ::: "memory")
#define CP_WAIT2()  asm volatile("cp.async.wait_group 2;" ::: "memory")
#define CP_WAIT1()  asm volatile("cp.async.wait_group 1;" ::: "memory")
#define CP_WAIT0()  asm volatile("cp.async.wait_group 0;" ::: "memory")
#define STS4(addr, v) asm volatile("st.shared.v4.b32 [%0], {%1,%2,%3,%4};" :: "r"(addr), \
    "r"(__float_as_uint((v).x)), "r"(__float_as_uint((v).y)), \
    "r"(__float_as_uint((v).z)), "r"(__float_as_uint((v).w)) : "memory")

// ================= mma.sync tf32x3 GEMM (3-stage cp.async pipeline) =================
#define TROW 36
#define PSTAGE (128*TROW)
#define NSTG 3
#define MMA_SMEM (NSTG*2*PSTAGE*4)

__global__ __launch_bounds__(256) void mma_gemm(
    const float* __restrict__ A, const float* __restrict__ W,
    const float* __restrict__ bias, const float* __restrict__ res,
    float* __restrict__ C, int M, int N, int K, int act)
{
    extern __shared__ float dsm[];
    const uint32_t sb = smem_u32(dsm);
    const int tid = threadIdx.x;
    const int wid = tid >> 5, lane = tid & 31;
    const int wm = wid >> 2, wn = wid & 3;
    const int bm = blockIdx.y * 128, bn = blockIdx.x * 128;

    float c[4][4][4];
#pragma unroll
    for (int mt = 0; mt < 4; mt++)
#pragma unroll
        for (int nt = 0; nt < 4; nt++)
#pragma unroll
            for (int q = 0; q < 4; q++) c[mt][nt][q] = 0.f;

    const int quad = lane >> 3, r8 = lane & 7;
    const int a_row = wm * 64 + r8 + (quad & 1) * 8;
    const int a_col = (quad >> 1) * 4;
    const int b_row = wn * 32 + r8 + (quad >> 1) * 8;
    const int b_col = (quad & 1) * 4;

    const int srow = tid >> 3, skq = tid & 7;
    const int nchunk = K / 32;

    auto issue = [&](int cc) {
        const int s = cc % NSTG;
        const int k0 = cc * 32;
        const uint32_t sA = sb + (uint32_t)(s * 2 * PSTAGE) * 4;
        const uint32_t sB = sA + (uint32_t)PSTAGE * 4;
#pragma unroll
        for (int e = 0; e < 4; e++) {
            int row = srow + e * 32;
            int ar = bm + row; if (ar >= M) ar = M - 1;
            uint32_t off = (uint32_t)(row * TROW + skq * 4) * 4;
            cpasync16(sA + off, &A[(size_t)ar * K + k0 + skq * 4]);
            cpasync16(sB + off, &W[(size_t)(bn + row) * K + k0 + skq * 4]);
        }
        CP_COMMIT();
    };

    issue(0);
    if (nchunk > 1) issue(1);
    for (int cc = 0; cc < nchunk; cc++) {
        if (cc + 2 < nchunk) issue(cc + 2);
        int rem = ((cc + 3 < nchunk ? cc + 3 : nchunk)) - cc - 1;
        if (rem >= 2) CP_WAIT2(); else if (rem == 1) CP_WAIT1(); else CP_WAIT0();
        __syncthreads();
        const int s = cc % NSTG;
        const uint32_t sA = sb + (uint32_t)(s * 2 * PSTAGE) * 4;
        const uint32_t sB = sA + (uint32_t)PSTAGE * 4;
#pragma unroll
        for (int ks = 0; ks < 4; ks++) {
            uint32_t ah[4][4], al[4][4], bh[4][2], bl[4][2];
#pragma unroll
            for (int mt = 0; mt < 4; mt++) {
                uint32_t raw[4];
                ldsm4(raw, sA + (uint32_t)((a_row + mt * 16) * TROW + ks * 8 + a_col) * 4);
#pragma unroll
                for (int q = 0; q < 4; q++) split2(raw[q], ah[mt][q], al[mt][q]);
            }
            {
                uint32_t t[4], th[4], tl[4];
                uint32_t bo = (uint32_t)(b_row * TROW + ks * 8 + b_col) * 4;
                ldsm4(t, sB + bo);
#pragma unroll
                for (int q = 0; q < 4; q++) split2(t[q], th[q], tl[q]);
                bh[0][0] = th[0]; bh[0][1] = th[1]; bh[1][0] = th[2]; bh[1][1] = th[3];
                bl[0][0] = tl[0]; bl[0][1] = tl[1]; bl[1][0] = tl[2]; bl[1][1] = tl[3];
                ldsm4(t, sB + bo + (uint32_t)(16 * TROW) * 4);
#pragma unroll
                for (int q = 0; q < 4; q++) split2(t[q], th[q], tl[q]);
                bh[2][0] = th[0]; bh[2][1] = th[1]; bh[3][0] = th[2]; bh[3][1] = th[3];
                bl[2][0] = tl[0]; bl[2][1] = tl[1]; bl[3][0] = tl[2]; bl[3][1] = tl[3];
            }
#pragma unroll
            for (int mt = 0; mt < 4; mt++)
#pragma unroll
                for (int nt = 0; nt < 4; nt++) {
                    mma_tf32(c[mt][nt], ah[mt], bh[nt]);
                    mma_tf32(c[mt][nt], al[mt], bh[nt]);
                    mma_tf32(c[mt][nt], ah[mt], bl[nt]);
                }
        }
        __syncthreads();
    }

    const int g = lane >> 2, tq = lane & 3;
#pragma unroll
    for (int mt = 0; mt < 4; mt++) {
#pragma unroll
        for (int nt = 0; nt < 4; nt++) {
            int col = bn + wn * 32 + nt * 8 + tq * 2;
            float b0 = 0.f, b1 = 0.f;
            if (bias) { b0 = bias[col]; b1 = bias[col + 1]; }
#pragma unroll
            for (int half = 0; half < 2; half++) {
                int row = bm + wm * 64 + mt * 16 + g + half * 8;
                if (row >= M) continue;
                float v0 = c[mt][nt][half * 2 + 0] + b0;
                float v1 = c[mt][nt][half * 2 + 1] + b1;
                if (act == 1) {
                    v0 = v0 / (1.f + expf(1.f - v0));
                    v1 = v1 / (1.f + expf(1.f - v1));
                }
                if (res) {
                    const float2 r2 = *(const float2*)&res[(size_t)row * N + col];
                    v0 += r2.x; v1 += r2.y;
                }
                float2 o2; o2.x = v0; o2.y = v1;
                *(float2*)&C[(size_t)row * N + col] = o2;
            }
        }
    }
}

// ---------------- relative positional encoding ----------------
__global__ void pe_kernel() {
    int r = blockIdx.x;
    int d = threadIdx.x;
    float pos, sign;
    if (r < TT) { pos = (float)(TT - 1 - r); sign = 1.f; }
    else        { pos = (float)(r - TT + 1); sign = -1.f; }
    int j2 = (d >> 1) << 1;
    float div = expf(-(float)j2 * (logf(10000.f) / (float)DM));
    float ang = sign * pos * div;
    g_pe[r * DM + d] = (d & 1) ? cosf(ang) : sinf(ang);
}

// ---------------- fallback SGEMM (embed only) ----------------
__global__ __launch_bounds__(256) void gemm_kernel(
    const float* __restrict__ A, const float* __restrict__ W,
    const float* __restrict__ bias, const float* __restrict__ res,
    float* __restrict__ C, int M, int N, int K, int act)
{
    __shared__ float As[16][128];
    __shared__ float Bs[16][128];
    const int bm = blockIdx.y * 128;
    const int bn = blockIdx.x * 128;
    const int tid = threadIdx.x;
    const int tm = tid >> 4, tn = tid & 15;

    float acc[8][8];
#pragma unroll
    for (int i = 0; i < 8; i++)
#pragma unroll
        for (int j = 0; j < 8; j++) acc[i][j] = 0.f;

    for (int k0 = 0; k0 < K; k0 += 16) {
#pragma unroll
        for (int e = 0; e < 8; e++) {
            int flat = tid + e * 256;
            int row = flat >> 4, kk = flat & 15;
            int ar = bm + row;
            As[kk][row] = (ar < M) ? A[(size_t)ar * K + k0 + kk] : 0.f;
            int wr = bn + row;
            Bs[kk][row] = (wr < N) ? W[(size_t)wr * K + k0 + kk] : 0.f;
        }
        __syncthreads();
#pragma unroll
        for (int kk = 0; kk < 16; kk++) {
            float4 a0 = *(const float4*)&As[kk][tm * 8];
            float4 a1 = *(const float4*)&As[kk][tm * 8 + 4];
            float4 b0 = *(const float4*)&Bs[kk][tn * 8];
            float4 b1 = *(const float4*)&Bs[kk][tn * 8 + 4];
            float a[8] = {a0.x,a0.y,a0.z,a0.w,a1.x,a1.y,a1.z,a1.w};
            float b[8] = {b0.x,b0.y,b0.z,b0.w,b1.x,b1.y,b1.z,b1.w};
#pragma unroll
            for (int i = 0; i < 8; i++)
#pragma unroll
                for (int j = 0; j < 8; j++) acc[i][j] += a[i] * b[j];
        }
        __syncthreads();
    }
#pragma unroll
    for (int i = 0; i < 8; i++) {
        int row = bm + tm * 8 + i;
        if (row >= M) continue;
#pragma unroll
        for (int j = 0; j < 8; j++) {
            int col = bn + tn * 8 + j;
            float c = acc[i][j];
            if (bias) c += bias[col];
            if (act == 1) c = c / (1.f + expf(1.f - c));
            if (res) c += res[(size_t)row * N + col];
            C[(size_t)row * N + col] = c;
        }
    }
}

// ---------------- BasicNorm ----------------
__global__ __launch_bounds__(DM) void norm_kernel(float* __restrict__ x) {
    int row = blockIdx.x, tid = threadIdx.x;
    float v = x[(size_t)row * DM + tid];
    float s = v * v;
#pragma unroll
    for (int o = 16; o; o >>= 1) s += __shfl_xor_sync(0xffffffffu, s, o);
    __shared__ float sm[8];
    int warp = tid >> 5, lane = tid & 31;
    if (lane == 0) sm[warp] = s;
    __syncthreads();
    if (warp == 0) {
        float t = (lane < 8) ? sm[lane] : 0.f;
#pragma unroll
        for (int o = 4; o; o >>= 1) t += __shfl_xor_sync(0xffffffffu, t, o);
        if (lane == 0) sm[0] = t;
    }
    __syncthreads();
    float scale = rsqrtf(sm[0] / (float)DM + 0.25f);
    x[(size_t)row * DM + tid] = v * scale;
}

// ================= flash attention: tf32x3 mma scores AND mma AV =================
#define FQU 0
#define FQV (FQU + 64*68)
#define FK  (FQV + 64*68)
#define FV  (FK + 64*68)        // VT[d][68] (transposed V)
#define FP  (FV + 64*68)        // [128][68]
#define FQP (FP + 128*68)       // [64][128]
#define FS  (FQP + 64*128)      // [64][68]
#define FMR (FS + 64*68)
#define FLR (FMR + 64)
#define FFR (FLR + 64)
#define FL_SMEM ((FFR + 64) * 4)

__global__ __launch_bounds__(256) void flash_kernel(
    const float* __restrict__ qkv, const float* __restrict__ p,
    const float* __restrict__ ub, const float* __restrict__ vb,
    const int* __restrict__ lens, float* __restrict__ att)
{
    extern __shared__ float sm[];
    const uint32_t sb = smem_u32(sm);
    const int i0 = blockIdx.x * 64;
    const int h  = blockIdx.y;
    const int b  = blockIdx.z;
    const int tid = threadIdx.x;
    const int wid = tid >> 5, lane = tid & 31;
    const int len = lens[b];

    // ---- prologue: raw qu/qv ----
#pragma unroll
    for (int e = 0; e < 4; e++) {
        int f4 = tid + e * 256;
        int row = f4 >> 4, c = (f4 & 15) * 4;
        float4 q4 = *(const float4*)&qkv[((size_t)(b * TT + i0 + row)) * 768 + h * DKK + c];
        float4 u4 = *(const float4*)&ub[h * DKK + c];
        float4 v4 = *(const float4*)&vb[h * DKK + c];
        float4 qu, qv;
        qu.x = q4.x + u4.x; qu.y = q4.y + u4.y; qu.z = q4.z + u4.z; qu.w = q4.w + u4.w;
        qv.x = q4.x + v4.x; qv.y = q4.y + v4.y; qv.z = q4.z + v4.z; qv.w = q4.w + v4.w;
        uint32_t off = (uint32_t)(row * 68 + c) * 4;
        STS4(sb + FQU * 4 + off, qu);
        STS4(sb + FQV * 4 + off, qv);
    }
    if (tid < 64) { sm[FMR + tid] = -3.4e38f; sm[FLR + tid] = 0.f; }

    const int wmS = wid & 3, wnS = wid >> 2;          // 4x2 warp grid
    const int quad = lane >> 3, r8 = lane & 7;
    const int a_row = wmS * 16 + r8 + (quad & 1) * 8;
    const int a_col = (quad >> 1) * 4;
    const int bS_row = wnS * 32 + r8 + (quad >> 1) * 8;
    const int bQ_row = wnS * 64 + r8 + (quad >> 1) * 8;
    const int b_col = (quad & 1) * 4;
    const int g = lane >> 2, tq = lane & 3;
    const int rg = tid >> 2, dg = tid & 3;

    // O accumulator as mma C fragments: warp tile rows [wmS*16,+16), cols d [wnS*32,+32)
    float cO[4][4];
#pragma unroll
    for (int nt = 0; nt < 4; nt++)
#pragma unroll
        for (int q = 0; q < 4; q++) cO[nt][q] = 0.f;

    for (int j0 = 0; j0 <= i0; j0 += 64) {
        __syncthreads();
        // ---- stage raw K, VT (transposed), P ----
#pragma unroll
        for (int e = 0; e < 4; e++) {
            int f4 = tid + e * 256;
            int j = f4 >> 4, c = (f4 & 15) * 4;
            const float* base = &qkv[((size_t)(b * TT + j0 + j)) * 768 + h * DKK + c];
            float4 k4 = *(const float4*)(base + DM);
            float4 v4 = *(const float4*)(base + 2 * DM);
            STS4(sb + FK * 4 + (uint32_t)(j * 68 + c) * 4, k4);
            sm[FV + (c + 0) * 68 + j] = v4.x;
            sm[FV + (c + 1) * 68 + j] = v4.y;
            sm[FV + (c + 2) * 68 + j] = v4.z;
            sm[FV + (c + 3) * 68 + j] = v4.w;
        }
        const int pbase = TT - 1 - (i0 + 63) + j0;
#pragma unroll
        for (int e = 0; e < 8; e++) {
            int f4 = tid + e * 256;
            if (f4 < 127 * 16) {
                int r = f4 >> 4, c = (f4 & 15) * 4;
                float4 p4 = *(const float4*)&p[(size_t)(pbase + r) * DM + h * DKK + c];
                STS4(sb + FP * 4 + (uint32_t)(r * 68 + c) * 4, p4);
            }
        }
        __syncthreads();

        // ---- score GEMMs (tf32x3) ----
        float cS[4][4], cQ[8][4];
#pragma unroll
        for (int nt = 0; nt < 4; nt++)
#pragma unroll
            for (int q = 0; q < 4; q++) cS[nt][q] = 0.f;
#pragma unroll
        for (int nt = 0; nt < 8; nt++)
#pragma unroll
            for (int q = 0; q < 4; q++) cQ[nt][q] = 0.f;

#pragma unroll
        for (int ks = 0; ks < 8; ks++) {
            uint32_t ao = (uint32_t)(a_row * 68 + ks * 8 + a_col) * 4;
            uint32_t raw[4], ah[4], al[4], t[4], th[4], tl[4];
            ldsm4(raw, sb + FQU * 4 + ao);
#pragma unroll
            for (int q = 0; q < 4; q++) split2(raw[q], ah[q], al[q]);
            uint32_t bo = (uint32_t)(bS_row * 68 + ks * 8 + b_col) * 4;
#pragma unroll
            for (int half = 0; half < 2; half++) {
                ldsm4(t, sb + FK * 4 + bo + (uint32_t)(half * 16 * 68) * 4);
#pragma unroll
                for (int q = 0; q < 4; q++) split2(t[q], th[q], tl[q]);
                uint32_t bhp[2][2] = {{th[0], th[1]}, {th[2], th[3]}};
                uint32_t blp[2][2] = {{tl[0], tl[1]}, {tl[2], tl[3]}};
#pragma unroll
                for (int k2 = 0; k2 < 2; k2++) {
                    int nt = half * 2 + k2;
                    mma_tf32(cS[nt], ah, bhp[k2]);
                    mma_tf32(cS[nt], al, bhp[k2]);
                    mma_tf32(cS[nt], ah, blp[k2]);
                }
            }
            ldsm4(raw, sb + FQV * 4 + ao);
#pragma unroll
            for (int q = 0; q < 4; q++) split2(raw[q], ah[q], al[q]);
            uint32_t boq = (uint32_t)(bQ_row * 68 + ks * 8 + b_col) * 4;
#pragma unroll
            for (int pr = 0; pr < 4; pr++) {
                ldsm4(t, sb + FP * 4 + boq + (uint32_t)(pr * 16 * 68) * 4);
#pragma unroll
                for (int q = 0; q < 4; q++) split2(t[q], th[q], tl[q]);
                uint32_t bhp[2][2] = {{th[0], th[1]}, {th[2], th[3]}};
                uint32_t blp[2][2] = {{tl[0], tl[1]}, {tl[2], tl[3]}};
#pragma unroll
                for (int k2 = 0; k2 < 2; k2++) {
                    int nt = pr * 2 + k2;
                    mma_tf32(cQ[nt], ah, bhp[k2]);
                    mma_tf32(cQ[nt], al, bhp[k2]);
                    mma_tf32(cQ[nt], ah, blp[k2]);
                }
            }
        }
        // write QP
#pragma unroll
        for (int nt = 0; nt < 8; nt++) {
            int col = wnS * 64 + nt * 8 + tq * 2;
#pragma unroll
            for (int half = 0; half < 2; half++) {
                int row = wmS * 16 + g + half * 8;
                sm[FQP + row * 128 + col]     = cQ[nt][half * 2 + 0];
                sm[FQP + row * 128 + col + 1] = cQ[nt][half * 2 + 1];
            }
        }
        __syncthreads();

        // ---- S epilogue: (cS + QP-shift) * scale -> FS ----
#pragma unroll
        for (int nt = 0; nt < 4; nt++) {
            int col = wnS * 32 + nt * 8 + tq * 2;
#pragma unroll
            for (int half = 0; half < 2; half++) {
                int row = wmS * 16 + g + half * 8;
                int rsh = 63 - row + col;
                sm[FS + row * 68 + col]     = (cS[nt][half*2+0] + sm[FQP + row * 128 + rsh])     * 0.125f;
                sm[FS + row * 68 + col + 1] = (cS[nt][half*2+1] + sm[FQP + row * 128 + rsh + 1]) * 0.125f;
            }
        }
        __syncthreads();

        // ---- online softmax (writes exp to FS) ----
        {
            const int i = i0 + rg;
            float mloc = -3.4e38f;
#pragma unroll
            for (int k = 0; k < 16; k++) {
                int jj = dg + k * 4;
                int j = j0 + jj;
                bool ok = (j <= i) && (j < len);
                float v = ok ? sm[FS + rg * 68 + jj] : -3.4e38f;
                mloc = fmaxf(mloc, v);
            }
            mloc = fmaxf(mloc, __shfl_xor_sync(0xffffffffu, mloc, 1));
            mloc = fmaxf(mloc, __shfl_xor_sync(0xffffffffu, mloc, 2));
            float mold = sm[FMR + rg];
            float mnew = fmaxf(mold, mloc);
            float fac = expf(mold - mnew);
            float ssum = 0.f;
#pragma unroll
            for (int k = 0; k < 16; k++) {
                int jj = dg + k * 4;
                int j = j0 + jj;
                bool ok = (j <= i) && (j < len);
                float e = ok ? expf(sm[FS + rg * 68 + jj] - mnew) : 0.f;
                sm[FS + rg * 68 + jj] = e;
                ssum += e;
            }
            ssum += __shfl_xor_sync(0xffffffffu, ssum, 1);
            ssum += __shfl_xor_sync(0xffffffffu, ssum, 2);
            if (dg == 0) {
                sm[FMR + rg] = mnew;
                sm[FLR + rg] = sm[FLR + rg] * fac + ssum;
                sm[FFR + rg] = fac;
            }
        }
        __syncthreads();

        // ---- AV via tf32 mma: cO = cO*fac + exp(S) @ V ----
        {
            float fac0 = sm[FFR + wmS * 16 + g];
            float fac1 = sm[FFR + wmS * 16 + g + 8];
#pragma unroll
            for (int nt = 0; nt < 4; nt++) {
                cO[nt][0] *= fac0; cO[nt][1] *= fac0;
                cO[nt][2] *= fac1; cO[nt][3] *= fac1;
            }
#pragma unroll
            for (int ks = 0; ks < 8; ks++) {
                uint32_t ao = (uint32_t)(a_row * 68 + ks * 8 + a_col) * 4;
                uint32_t raw[4], ah[4], al[4], t[4], th[4], tl[4];
                ldsm4(raw, sb + FS * 4 + ao);
#pragma unroll
                for (int q = 0; q < 4; q++) split2(raw[q], ah[q], al[q]);
                uint32_t bo = (uint32_t)(bS_row * 68 + ks * 8 + b_col) * 4;   // rows = d
#pragma unroll
                for (int half = 0; half < 2; half++) {
                    ldsm4(t, sb + FV * 4 + bo + (uint32_t)(half * 16 * 68) * 4);
#pragma unroll
                    for (int q = 0; q < 4; q++) split2(t[q], th[q], tl[q]);
                    uint32_t bhp[2][2] = {{th[0], th[1]}, {th[2], th[3]}};
                    uint32_t blp[2][2] = {{tl[0], tl[1]}, {tl[2], tl[3]}};
#pragma unroll
                    for (int k2 = 0; k2 < 2; k2++) {
                        int nt = half * 2 + k2;
                        mma_tf32(cO[nt], ah, bhp[k2]);
                        mma_tf32(cO[nt], al, bhp[k2]);
                        mma_tf32(cO[nt], ah, blp[k2]);
                    }
                }
            }
        }
    }

    // ---- epilogue: O / l ----
#pragma unroll
    for (int nt = 0; nt < 4; nt++) {
        int col = wnS * 32 + nt * 8 + tq * 2;
#pragma unroll
        for (int half = 0; half < 2; half++) {
            int row = wmS * 16 + g + half * 8;
            float inv = 1.f / sm[FLR + row];
            float2 o2;
            o2.x = cO[nt][half * 2 + 0] * inv;
            o2.y = cO[nt][half * 2 + 1] * inv;
            *(float2*)&att[((size_t)(b * TT + i0 + row)) * DM + h * DKK + col] = o2;
        }
    }
}

// ---------------- final copy ----------------
__global__ void out_kernel(const float* __restrict__ x, const int* __restrict__ lens,
                           float* __restrict__ out, int out_size) {
    int idx = blockIdx.x * 256 + threadIdx.x;
    const int n = BB * TT * DM;
    if (idx < n) out[idx] = x[idx];
    if (idx < BB && out_size >= n + BB) out[n + idx] = (float)lens[idx];
}

extern "C" void kernel_launch(void* const* d_in, const int* in_sizes, int n_in,
                              void* d_out, int out_size) {
    const float* x        = (const float*)d_in[0];
    const int*   lens     = (const int*)  d_in[1];
    const float* embed_W  = (const float*)d_in[2];
    const float* embed_b  = (const float*)d_in[3];
    const float* in_projW = (const float*)d_in[4];
    const float* in_projb = (const float*)d_in[5];
    const float* pos_W    = (const float*)d_in[6];
    const float* pbu      = (const float*)d_in[7];
    const float* pbv      = (const float*)d_in[8];
    const float* out_W    = (const float*)d_in[9];
    const float* out_b    = (const float*)d_in[10];
    const float* ff1_W    = (const float*)d_in[11];
    const float* ff1_b    = (const float*)d_in[12];
    const float* ff2_W    = (const float*)d_in[13];
    const float* ff2_b    = (const float*)d_in[14];

    float *xbuf, *qkvb, *peb, *pbuf, *attb, *hbuf;
    cudaGetSymbolAddress((void**)&xbuf, g_x);
    cudaGetSymbolAddress((void**)&qkvb, g_qkv);
    cudaGetSymbolAddress((void**)&peb,  g_pe);
    cudaGetSymbolAddress((void**)&pbuf, g_p);
    cudaGetSymbolAddress((void**)&attb, g_att);
    cudaGetSymbolAddress((void**)&hbuf, g_h);

    cudaFuncSetAttribute(flash_kernel, cudaFuncAttributeMaxDynamicSharedMemorySize, FL_SMEM);
    cudaFuncSetAttribute(mma_gemm, cudaFuncAttributeMaxDynamicSharedMemorySize, MMA_SMEM);

    const int M = BB * TT;

    pe_kernel<<<PP, DM>>>();
    gemm_kernel<<<dim3(DM/128, M/128), 256>>>(x, embed_W, embed_b, nullptr, xbuf, M, DM, IND, 0);
    norm_kernel<<<M, DM>>>(xbuf);

    for (int l = 0; l < NL; l++) {
        mma_gemm<<<dim3(768/128, M/128), 256, MMA_SMEM>>>(
            xbuf, in_projW + (size_t)l*3*DM*DM, in_projb + (size_t)l*3*DM,
            nullptr, qkvb, M, 3*DM, DM, 0);
        mma_gemm<<<dim3(DM/128, 16), 256, MMA_SMEM>>>(
            peb, pos_W + (size_t)l*DM*DM, nullptr, nullptr, pbuf, PP, DM, DM, 0);
        flash_kernel<<<dim3(TT/64, NH, BB), 256, FL_SMEM>>>(
            qkvb, pbuf, pbu + (size_t)l*NH*DKK, pbv + (size_t)l*NH*DKK, lens, attb);
        mma_gemm<<<dim3(DM/128, M/128), 256, MMA_SMEM>>>(
            attb, out_W + (size_t)l*DM*DM, out_b + (size_t)l*DM, xbuf, xbuf, M, DM, DM, 0);
        mma_gemm<<<dim3(FFD/128, M/128), 256, MMA_SMEM>>>(
            xbuf, ff1_W + (size_t)l*FFD*DM, ff1_b + (size_t)l*FFD, nullptr, hbuf, M, FFD, DM, 1);
        mma_gemm<<<dim3(DM/128, M/128), 256, MMA_SMEM>>>(
            hbuf, ff2_W + (size_t)l*DM*FFD, ff2_b + (size_t)l*DM, xbuf, xbuf, M, DM, FFD, 0);
        norm_kernel<<<M, DM>>>(xbuf);
    }

    int n = BB * TT * DM;
    out_kernel<<<(n + 255)/256, 256>>>(xbuf, lens, (float*)d_out, out_size);
}

// round 14
// speedup vs baseline: 4.8579x; 1.1594x over previous
#include <cuda_runtime.h>
#include <math.h>
#include <stdint.h>

#define BB 8
#define TT 1024
#define IND 80
#define DM 256
#define NH 4
#define DKK 64
#define FFD 2048
#define NL 6
#define PP (2*TT-1)

// ---------------- device scratch (allocation-free) ----------------
__device__ float g_x[BB*TT*DM];
__device__ float g_qkv[BB*TT*3*DM];
__device__ float g_pe[PP*DM];
__device__ float g_p[PP*DM];
__device__ float g_att[BB*TT*DM];
__device__ float g_h[BB*TT*FFD];

// ================= helpers =================
__device__ __forceinline__ uint32_t smem_u32(const void* p) {
    uint32_t a;
    asm("{ .reg .u64 t; cvta.to.shared.u64 t, %1; cvt.u32.u64 %0, t; }" : "=r"(a) : "l"(p));
    return a;
}
// tf32 split (flash): hi = top-19-bit truncate (HW ignores low 13), lo = residual
__device__ __forceinline__ void split2(uint32_t raw, uint32_t& h, uint32_t& l) {
    h = raw & 0xFFFFE000u;
    l = __float_as_uint(__uint_as_float(raw) - __uint_as_float(h));
}
__device__ __forceinline__ uint32_t prmt7632(uint32_t a, uint32_t b) {
    uint32_t r;
    asm("prmt.b32 %0, %1, %2, 0x7632;" : "=r"(r) : "r"(a), "r"(b));
    return r;
}
__device__ __forceinline__ void ldsm4(uint32_t* r, uint32_t addr) {
    asm volatile("ldmatrix.sync.aligned.m8n8.x4.shared.b16 {%0,%1,%2,%3}, [%4];"
        : "=r"(r[0]), "=r"(r[1]), "=r"(r[2]), "=r"(r[3]) : "r"(addr));
}
__device__ __forceinline__ void mma_tf32(float* c, const uint32_t* a, const uint32_t* b) {
    asm volatile(
        "mma.sync.aligned.m16n8k8.row.col.f32.tf32.tf32.f32 "
        "{%0,%1,%2,%3}, {%4,%5,%6,%7}, {%8,%9}, {%0,%1,%2,%3};"
        : "+f"(c[0]), "+f"(c[1]), "+f"(c[2]), "+f"(c[3])
        : "r"(a[0]), "r"(a[1]), "r"(a[2]), "r"(a[3]), "r"(b[0]), "r"(b[1]));
}
__device__ __forceinline__ void mma_bf16(float* c, const uint32_t* a, const uint32_t* b) {
    asm volatile(
        "mma.sync.aligned.m16n8k16.row.col.f32.bf16.bf16.f32 "
        "{%0,%1,%2,%3}, {%4,%5,%6,%7}, {%8,%9}, {%0,%1,%2,%3};"
        : "+f"(c[0]), "+f"(c[1]), "+f"(c[2]), "+f"(c[3])
        : "r"(a[0]), "r"(a[1]), "r"(a[2]), "r"(a[3]), "r"(b[0]), "r"(b[1]));
}
#define STS4(addr, v) asm volatile("st.shared.v4.b32 [%0], {%1,%2,%3,%4};" :: "r"(addr), \
    "r"(__float_as_uint((v).x)), "r"(__float_as_uint((v).y)), \
    "r"(__float_as_uint((v).z)), "r"(__float_as_uint((v).w)) : "memory")
#define STS2(addr, v0, v1) asm volatile("st.shared.v2.b32 [%0], {%1,%2};" :: "r"(addr), \
    "r"(v0), "r"(v1) : "memory")

// ================= bf16x4 mma GEMM: C = A(MxK) @ W(NxK)^T =================
// N mult of 128, K mult of 32, M arbitrary (loads clamped, stores guarded).
// smem b16 tiles [128 rows][40 b16 stride]: AH, AL, BH, BL (40 KB total)
#define BSTRIDE 80                      // bytes per row (40 b16)
#define BTILE (128*BSTRIDE)             // 10240 B
#define MMA_SMEM (4*BTILE)

__global__ __launch_bounds__(256) void mma_gemm(
    const float* __restrict__ A, const float* __restrict__ W,
    const float* __restrict__ bias, const float* __restrict__ res,
    float* __restrict__ C, int M, int N, int K, int act)
{
    extern __shared__ float dsm[];
    const uint32_t sb = smem_u32(dsm);
    const uint32_t sAH = sb, sAL = sb + BTILE, sBH = sb + 2*BTILE, sBL = sb + 3*BTILE;
    const int tid = threadIdx.x;
    const int wid = tid >> 5, lane = tid & 31;
    const int wm = wid >> 2, wn = wid & 3;          // warp grid 2x4
    const int bm = blockIdx.y * 128, bn = blockIdx.x * 128;

    float c[4][4][4];
#pragma unroll
    for (int mt = 0; mt < 4; mt++)
#pragma unroll
        for (int nt = 0; nt < 4; nt++)
#pragma unroll
            for (int q = 0; q < 4; q++) c[mt][nt][q] = 0.f;

    const int quad = lane >> 3, r8 = lane & 7;
    const int srow = tid >> 3, skq = tid & 7;
    const int nchunk = K / 32;

    float4 a_reg[4], w_reg[4];
    // prologue load chunk 0
#pragma unroll
    for (int e = 0; e < 4; e++) {
        int row = srow + e * 32;
        int ar = bm + row; if (ar >= M) ar = M - 1;
        a_reg[e] = *(const float4*)&A[(size_t)ar * K + skq * 4];
        w_reg[e] = *(const float4*)&W[(size_t)(bn + row) * K + skq * 4];
    }

    for (int cc = 0; cc < nchunk; cc++) {
        __syncthreads();   // protect smem from previous iteration's readers
        // ---- convert + store bf16 hi/lo tiles ----
#pragma unroll
        for (int e = 0; e < 4; e++) {
            int row = srow + e * 32;
            uint32_t off = (uint32_t)(row * BSTRIDE + skq * 8);
            uint32_t r0 = __float_as_uint(a_reg[e].x), r1 = __float_as_uint(a_reg[e].y);
            uint32_t r2 = __float_as_uint(a_reg[e].z), r3 = __float_as_uint(a_reg[e].w);
            uint32_t h01 = prmt7632(r0, r1), h23 = prmt7632(r2, r3);
            uint32_t l0 = __float_as_uint(a_reg[e].x - __uint_as_float(r0 & 0xFFFF0000u));
            uint32_t l1 = __float_as_uint(a_reg[e].y - __uint_as_float(r1 & 0xFFFF0000u));
            uint32_t l2 = __float_as_uint(a_reg[e].z - __uint_as_float(r2 & 0xFFFF0000u));
            uint32_t l3 = __float_as_uint(a_reg[e].w - __uint_as_float(r3 & 0xFFFF0000u));
            STS2(sAH + off, h01, h23);
            STS2(sAL + off, prmt7632(l0, l1), prmt7632(l2, l3));
            r0 = __float_as_uint(w_reg[e].x); r1 = __float_as_uint(w_reg[e].y);
            r2 = __float_as_uint(w_reg[e].z); r3 = __float_as_uint(w_reg[e].w);
            h01 = prmt7632(r0, r1); h23 = prmt7632(r2, r3);
            l0 = __float_as_uint(w_reg[e].x - __uint_as_float(r0 & 0xFFFF0000u));
            l1 = __float_as_uint(w_reg[e].y - __uint_as_float(r1 & 0xFFFF0000u));
            l2 = __float_as_uint(w_reg[e].z - __uint_as_float(r2 & 0xFFFF0000u));
            l3 = __float_as_uint(w_reg[e].w - __uint_as_float(r3 & 0xFFFF0000u));
            STS2(sBH + off, h01, h23);
            STS2(sBL + off, prmt7632(l0, l1), prmt7632(l2, l3));
        }
        __syncthreads();
        // ---- prefetch next chunk (LDG latency hides under mmas) ----
        if (cc + 1 < nchunk) {
            const int k0 = (cc + 1) * 32;
#pragma unroll
            for (int e = 0; e < 4; e++) {
                int row = srow + e * 32;
                int ar = bm + row; if (ar >= M) ar = M - 1;
                a_reg[e] = *(const float4*)&A[(size_t)ar * K + k0 + skq * 4];
                w_reg[e] = *(const float4*)&W[(size_t)(bn + row) * K + k0 + skq * 4];
            }
        }
        // ---- mma over the chunk: 2 ks of K=16 ----
#pragma unroll
        for (int ks = 0; ks < 2; ks++) {
            uint32_t ah[4][4], al[4][4], bh[4][2], bl[4][2];
#pragma unroll
            for (int mt = 0; mt < 4; mt++) {
                uint32_t ao = (uint32_t)((wm * 64 + mt * 16 + r8 + (quad & 1) * 8) * BSTRIDE
                                         + ks * 32 + (quad >> 1) * 16);
                ldsm4(ah[mt], sAH + ao);
                ldsm4(al[mt], sAL + ao);
            }
#pragma unroll
            for (int ntp = 0; ntp < 2; ntp++) {
                uint32_t bo = (uint32_t)((wn * 32 + ntp * 16 + r8 + (quad >> 1) * 8) * BSTRIDE
                                         + ks * 32 + (quad & 1) * 16);
                uint32_t t[4];
                ldsm4(t, sBH + bo);
                bh[2*ntp][0] = t[0]; bh[2*ntp][1] = t[1];
                bh[2*ntp+1][0] = t[2]; bh[2*ntp+1][1] = t[3];
                ldsm4(t, sBL + bo);
                bl[2*ntp][0] = t[0]; bl[2*ntp][1] = t[1];
                bl[2*ntp+1][0] = t[2]; bl[2*ntp+1][1] = t[3];
            }
#pragma unroll
            for (int mt = 0; mt < 4; mt++)
#pragma unroll
                for (int nt = 0; nt < 4; nt++) {
                    mma_bf16(c[mt][nt], ah[mt], bh[nt]);
                    mma_bf16(c[mt][nt], ah[mt], bl[nt]);
                    mma_bf16(c[mt][nt], al[mt], bh[nt]);
                    mma_bf16(c[mt][nt], al[mt], bl[nt]);
                }
        }
    }

    const int g = lane >> 2, tq = lane & 3;
#pragma unroll
    for (int mt = 0; mt < 4; mt++) {
#pragma unroll
        for (int nt = 0; nt < 4; nt++) {
            int col = bn + wn * 32 + nt * 8 + tq * 2;
            float b0 = 0.f, b1 = 0.f;
            if (bias) { b0 = bias[col]; b1 = bias[col + 1]; }
#pragma unroll
            for (int half = 0; half < 2; half++) {
                int row = bm + wm * 64 + mt * 16 + g + half * 8;
                if (row >= M) continue;
                float v0 = c[mt][nt][half * 2 + 0] + b0;
                float v1 = c[mt][nt][half * 2 + 1] + b1;
                if (act == 1) {
                    v0 = v0 / (1.f + expf(1.f - v0));
                    v1 = v1 / (1.f + expf(1.f - v1));
                }
                if (res) {
                    const float2 r2 = *(const float2*)&res[(size_t)row * N + col];
                    v0 += r2.x; v1 += r2.y;
                }
                float2 o2; o2.x = v0; o2.y = v1;
                *(float2*)&C[(size_t)row * N + col] = o2;
            }
        }
    }
}

// ---------------- relative positional encoding ----------------
__global__ void pe_kernel() {
    int r = blockIdx.x;
    int d = threadIdx.x;
    float pos, sign;
    if (r < TT) { pos = (float)(TT - 1 - r); sign = 1.f; }
    else        { pos = (float)(r - TT + 1); sign = -1.f; }
    int j2 = (d >> 1) << 1;
    float div = expf(-(float)j2 * (logf(10000.f) / (float)DM));
    float ang = sign * pos * div;
    g_pe[r * DM + d] = (d & 1) ? cosf(ang) : sinf(ang);
}

// ---------------- fallback SGEMM (embed only) ----------------
__global__ __launch_bounds__(256) void gemm_kernel(
    const float* __restrict__ A, const float* __restrict__ W,
    const float* __restrict__ bias, const float* __restrict__ res,
    float* __restrict__ C, int M, int N, int K, int act)
{
    __shared__ float As[16][128];
    __shared__ float Bs[16][128];
    const int bm = blockIdx.y * 128;
    const int bn = blockIdx.x * 128;
    const int tid = threadIdx.x;
    const int tm = tid >> 4, tn = tid & 15;

    float acc[8][8];
#pragma unroll
    for (int i = 0; i < 8; i++)
#pragma unroll
        for (int j = 0; j < 8; j++) acc[i][j] = 0.f;

    for (int k0 = 0; k0 < K; k0 += 16) {
#pragma unroll
        for (int e = 0; e < 8; e++) {
            int flat = tid + e * 256;
            int row = flat >> 4, kk = flat & 15;
            int ar = bm + row;
            As[kk][row] = (ar < M) ? A[(size_t)ar * K + k0 + kk] : 0.f;
            int wr = bn + row;
            Bs[kk][row] = (wr < N) ? W[(size_t)wr * K + k0 + kk] : 0.f;
        }
        __syncthreads();
#pragma unroll
        for (int kk = 0; kk < 16; kk++) {
            float4 a0 = *(const float4*)&As[kk][tm * 8];
            float4 a1 = *(const float4*)&As[kk][tm * 8 + 4];
            float4 b0 = *(const float4*)&Bs[kk][tn * 8];
            float4 b1 = *(const float4*)&Bs[kk][tn * 8 + 4];
            float a[8] = {a0.x,a0.y,a0.z,a0.w,a1.x,a1.y,a1.z,a1.w};
            float b[8] = {b0.x,b0.y,b0.z,b0.w,b1.x,b1.y,b1.z,b1.w};
#pragma unroll
            for (int i = 0; i < 8; i++)
#pragma unroll
                for (int j = 0; j < 8; j++) acc[i][j] += a[i] * b[j];
        }
        __syncthreads();
    }
#pragma unroll
    for (int i = 0; i < 8; i++) {
        int row = bm + tm * 8 + i;
        if (row >= M) continue;
#pragma unroll
        for (int j = 0; j < 8; j++) {
            int col = bn + tn * 8 + j;
            float c = acc[i][j];
            if (bias) c += bias[col];
            if (act == 1) c = c / (1.f + expf(1.f - c));
            if (res) c += res[(size_t)row * N + col];
            C[(size_t)row * N + col] = c;
        }
    }
}

// ---------------- BasicNorm ----------------
__global__ __launch_bounds__(DM) void norm_kernel(float* __restrict__ x) {
    int row = blockIdx.x, tid = threadIdx.x;
    float v = x[(size_t)row * DM + tid];
    float s = v * v;
#pragma unroll
    for (int o = 16; o; o >>= 1) s += __shfl_xor_sync(0xffffffffu, s, o);
    __shared__ float sm[8];
    int warp = tid >> 5, lane = tid & 31;
    if (lane == 0) sm[warp] = s;
    __syncthreads();
    if (warp == 0) {
        float t = (lane < 8) ? sm[lane] : 0.f;
#pragma unroll
        for (int o = 4; o; o >>= 1) t += __shfl_xor_sync(0xffffffffu, t, o);
        if (lane == 0) sm[0] = t;
    }
    __syncthreads();
    float scale = rsqrtf(sm[0] / (float)DM + 0.25f);
    x[(size_t)row * DM + tid] = v * scale;
}

// ================= flash attention: tf32x3 mma scores AND mma AV =================
#define FQU 0
#define FQV (FQU + 64*68)
#define FK  (FQV + 64*68)
#define FV  (FK + 64*68)        // VT[d][68] (transposed V)
#define FP  (FV + 64*68)        // [128][68]
#define FQP (FP + 128*68)       // [64][128]
#define FS  (FQP + 64*128)      // [64][68]
#define FMR (FS + 64*68)
#define FLR (FMR + 64)
#define FFR (FLR + 64)
#define FL_SMEM ((FFR + 64) * 4)

__global__ __launch_bounds__(256) void flash_kernel(
    const float* __restrict__ qkv, const float* __restrict__ p,
    const float* __restrict__ ub, const float* __restrict__ vb,
    const int* __restrict__ lens, float* __restrict__ att)
{
    extern __shared__ float sm[];
    const uint32_t sb = smem_u32(sm);
    const int i0 = blockIdx.x * 64;
    const int h  = blockIdx.y;
    const int b  = blockIdx.z;
    const int tid = threadIdx.x;
    const int wid = tid >> 5, lane = tid & 31;
    const int len = lens[b];

#pragma unroll
    for (int e = 0; e < 4; e++) {
        int f4 = tid + e * 256;
        int row = f4 >> 4, c = (f4 & 15) * 4;
        float4 q4 = *(const float4*)&qkv[((size_t)(b * TT + i0 + row)) * 768 + h * DKK + c];
        float4 u4 = *(const float4*)&ub[h * DKK + c];
        float4 v4 = *(const float4*)&vb[h * DKK + c];
        float4 qu, qv;
        qu.x = q4.x + u4.x; qu.y = q4.y + u4.y; qu.z = q4.z + u4.z; qu.w = q4.w + u4.w;
        qv.x = q4.x + v4.x; qv.y = q4.y + v4.y; qv.z = q4.z + v4.z; qv.w = q4.w + v4.w;
        uint32_t off = (uint32_t)(row * 68 + c) * 4;
        STS4(sb + FQU * 4 + off, qu);
        STS4(sb + FQV * 4 + off, qv);
    }
    if (tid < 64) { sm[FMR + tid] = -3.4e38f; sm[FLR + tid] = 0.f; }

    const int wmS = wid & 3, wnS = wid >> 2;
    const int quad = lane >> 3, r8 = lane & 7;
    const int a_row = wmS * 16 + r8 + (quad & 1) * 8;
    const int a_col = (quad >> 1) * 4;
    const int bS_row = wnS * 32 + r8 + (quad >> 1) * 8;
    const int bQ_row = wnS * 64 + r8 + (quad >> 1) * 8;
    const int b_col = (quad & 1) * 4;
    const int g = lane >> 2, tq = lane & 3;
    const int rg = tid >> 2, dg = tid & 3;

    float cO[4][4];
#pragma unroll
    for (int nt = 0; nt < 4; nt++)
#pragma unroll
        for (int q = 0; q < 4; q++) cO[nt][q] = 0.f;

    for (int j0 = 0; j0 <= i0; j0 += 64) {
        __syncthreads();
#pragma unroll
        for (int e = 0; e < 4; e++) {
            int f4 = tid + e * 256;
            int j = f4 >> 4, c = (f4 & 15) * 4;
            const float* base = &qkv[((size_t)(b * TT + j0 + j)) * 768 + h * DKK + c];
            float4 k4 = *(const float4*)(base + DM);
            float4 v4 = *(const float4*)(base + 2 * DM);
            STS4(sb + FK * 4 + (uint32_t)(j * 68 + c) * 4, k4);
            sm[FV + (c + 0) * 68 + j] = v4.x;
            sm[FV + (c + 1) * 68 + j] = v4.y;
            sm[FV + (c + 2) * 68 + j] = v4.z;
            sm[FV + (c + 3) * 68 + j] = v4.w;
        }
        const int pbase = TT - 1 - (i0 + 63) + j0;
#pragma unroll
        for (int e = 0; e < 8; e++) {
            int f4 = tid + e * 256;
            if (f4 < 127 * 16) {
                int r = f4 >> 4, c = (f4 & 15) * 4;
                float4 p4 = *(const float4*)&p[(size_t)(pbase + r) * DM + h * DKK + c];
                STS4(sb + FP * 4 + (uint32_t)(r * 68 + c) * 4, p4);
            }
        }
        __syncthreads();

        float cS[4][4], cQ[8][4];
#pragma unroll
        for (int nt = 0; nt < 4; nt++)
#pragma unroll
            for (int q = 0; q < 4; q++) cS[nt][q] = 0.f;
#pragma unroll
        for (int nt = 0; nt < 8; nt++)
#pragma unroll
            for (int q = 0; q < 4; q++) cQ[nt][q] = 0.f;

#pragma unroll
        for (int ks = 0; ks < 8; ks++) {
            uint32_t ao = (uint32_t)(a_row * 68 + ks * 8 + a_col) * 4;
            uint32_t raw[4], ah[4], al[4], t[4], th[4], tl[4];
            ldsm4(raw, sb + FQU * 4 + ao);
#pragma unroll
            for (int q = 0; q < 4; q++) split2(raw[q], ah[q], al[q]);
            uint32_t bo = (uint32_t)(bS_row * 68 + ks * 8 + b_col) * 4;
#pragma unroll
            for (int half = 0; half < 2; half++) {
                ldsm4(t, sb + FK * 4 + bo + (uint32_t)(half * 16 * 68) * 4);
#pragma unroll
                for (int q = 0; q < 4; q++) split2(t[q], th[q], tl[q]);
                uint32_t bhp[2][2] = {{th[0], th[1]}, {th[2], th[3]}};
                uint32_t blp[2][2] = {{tl[0], tl[1]}, {tl[2], tl[3]}};
#pragma unroll
                for (int k2 = 0; k2 < 2; k2++) {
                    int nt = half * 2 + k2;
                    mma_tf32(cS[nt], ah, bhp[k2]);
                    mma_tf32(cS[nt], al, bhp[k2]);
                    mma_tf32(cS[nt], ah, blp[k2]);
                }
            }
            ldsm4(raw, sb + FQV * 4 + ao);
#pragma unroll
            for (int q = 0; q < 4; q++) split2(raw[q], ah[q], al[q]);
            uint32_t boq = (uint32_t)(bQ_row * 68 + ks * 8 + b_col) * 4;
#pragma unroll
            for (int pr = 0; pr < 4; pr++) {
                ldsm4(t, sb + FP * 4 + boq + (uint32_t)(pr * 16 * 68) * 4);
#pragma unroll
                for (int q = 0; q < 4; q++) split2(t[q], th[q], tl[q]);
                uint32_t bhp[2][2] = {{th[0], th[1]}, {th[2], th[3]}};
                uint32_t blp[2][2] = {{tl[0], tl[1]}, {tl[2], tl[3]}};
#pragma unroll
                for (int k2 = 0; k2 < 2; k2++) {
                    int nt = pr * 2 + k2;
                    mma_tf32(cQ[nt], ah, bhp[k2]);
                    mma_tf32(cQ[nt], al, bhp[k2]);
                    mma_tf32(cQ[nt], ah, blp[k2]);
                }
            }
        }
#pragma unroll
        for (int nt = 0; nt < 8; nt++) {
            int col = wnS * 64 + nt * 8 + tq * 2;
#pragma unroll
            for (int half = 0; half < 2; half++) {
                int row = wmS * 16 + g + half * 8;
                sm[FQP + row * 128 + col]     = cQ[nt][half * 2 + 0];
                sm[FQP + row * 128 + col + 1] = cQ[nt][half * 2 + 1];
            }
        }
        __syncthreads();

#pragma unroll
        for (int nt = 0; nt < 4; nt++) {
            int col = wnS * 32 + nt * 8 + tq * 2;
#pragma unroll
            for (int half = 0; half < 2; half++) {
                int row = wmS * 16 + g + half * 8;
                int rsh = 63 - row + col;
                sm[FS + row * 68 + col]     = (cS[nt][half*2+0] + sm[FQP + row * 128 + rsh])     * 0.125f;
                sm[FS + row * 68 + col + 1] = (cS[nt][half*2+1] + sm[FQP + row * 128 + rsh + 1]) * 0.125f;
            }
        }
        __syncthreads();

        {
            const int i = i0 + rg;
            float mloc = -3.4e38f;
#pragma unroll
            for (int k = 0; k < 16; k++) {
                int jj = dg + k * 4;
                int j = j0 + jj;
                bool ok = (j <= i) && (j < len);
                float v = ok ? sm[FS + rg * 68 + jj] : -3.4e38f;
                mloc = fmaxf(mloc, v);
            }
            mloc = fmaxf(mloc, __shfl_xor_sync(0xffffffffu, mloc, 1));
            mloc = fmaxf(mloc, __shfl_xor_sync(0xffffffffu, mloc, 2));
            float mold = sm[FMR + rg];
            float mnew = fmaxf(mold, mloc);
            float fac = expf(mold - mnew);
            float ssum = 0.f;
#pragma unroll
            for (int k = 0; k < 16; k++) {
                int jj = dg + k * 4;
                int j = j0 + jj;
                bool ok = (j <= i) && (j < len);
                float e = ok ? expf(sm[FS + rg * 68 + jj] - mnew) : 0.f;
                sm[FS + rg * 68 + jj] = e;
                ssum += e;
            }
            ssum += __shfl_xor_sync(0xffffffffu, ssum, 1);
            ssum += __shfl_xor_sync(0xffffffffu, ssum, 2);
            if (dg == 0) {
                sm[FMR + rg] = mnew;
                sm[FLR + rg] = sm[FLR + rg] * fac + ssum;
                sm[FFR + rg] = fac;
            }
        }
        __syncthreads();

        {
            float fac0 = sm[FFR + wmS * 16 + g];
            float fac1 = sm[FFR + wmS * 16 + g + 8];
#pragma unroll
            for (int nt = 0; nt < 4; nt++) {
                cO[nt][0] *= fac0; cO[nt][1] *= fac0;
                cO[nt][2] *= fac1; cO[nt][3] *= fac1;
            }
#pragma unroll
            for (int ks = 0; ks < 8; ks++) {
                uint32_t ao = (uint32_t)(a_row * 68 + ks * 8 + a_col) * 4;
                uint32_t raw[4], ah[4], al[4], t[4], th[4], tl[4];
                ldsm4(raw, sb + FS * 4 + ao);
#pragma unroll
                for (int q = 0; q < 4; q++) split2(raw[q], ah[q], al[q]);
                uint32_t bo = (uint32_t)(bS_row * 68 + ks * 8 + b_col) * 4;
#pragma unroll
                for (int half = 0; half < 2; half++) {
                    ldsm4(t, sb + FV * 4 + bo + (uint32_t)(half * 16 * 68) * 4);
#pragma unroll
                    for (int q = 0; q < 4; q++) split2(t[q], th[q], tl[q]);
                    uint32_t bhp[2][2] = {{th[0], th[1]}, {th[2], th[3]}};
                    uint32_t blp[2][2] = {{tl[0], tl[1]}, {tl[2], tl[3]}};
#pragma unroll
                    for (int k2 = 0; k2 < 2; k2++) {
                        int nt = half * 2 + k2;
                        mma_tf32(cO[nt], ah, bhp[k2]);
                        mma_tf32(cO[nt], al, bhp[k2]);
                        mma_tf32(cO[nt], ah, blp[k2]);
                    }
                }
            }
        }
    }

#pragma unroll
    for (int nt = 0; nt < 4; nt++) {
        int col = wnS * 32 + nt * 8 + tq * 2;
#pragma unroll
        for (int half = 0; half < 2; half++) {
            int row = wmS * 16 + g + half * 8;
            float inv = 1.f / sm[FLR + row];
            float2 o2;
            o2.x = cO[nt][half * 2 + 0] * inv;
            o2.y = cO[nt][half * 2 + 1] * inv;
            *(float2*)&att[((size_t)(b * TT + i0 + row)) * DM + h * DKK + col] = o2;
        }
    }
}

// ---------------- final copy ----------------
__global__ void out_kernel(const float* __restrict__ x, const int* __restrict__ lens,
                           float* __restrict__ out, int out_size) {
    int idx = blockIdx.x * 256 + threadIdx.x;
    const int n = BB * TT * DM;
    if (idx < n) out[idx] = x[idx];
    if (idx < BB && out_size >= n + BB) out[n + idx] = (float)lens[idx];
}

extern "C" void kernel_launch(void* const* d_in, const int* in_sizes, int n_in,
                              void* d_out, int out_size) {
    const float* x        = (const float*)d_in[0];
    const int*   lens     = (const int*)  d_in[1];
    const float* embed_W  = (const float*)d_in[2];
    const float* embed_b  = (const float*)d_in[3];
    const float* in_projW = (const float*)d_in[4];
    const float* in_projb = (const float*)d_in[5];
    const float* pos_W    = (const float*)d_in[6];
    const float* pbu      = (const float*)d_in[7];
    const float* pbv      = (const float*)d_in[8];
    const float* out_W    = (const float*)d_in[9];
    const float* out_b    = (const float*)d_in[10];
    const float* ff1_W    = (const float*)d_in[11];
    const float* ff1_b    = (const float*)d_in[12];
    const float* ff2_W    = (const float*)d_in[13];
    const float* ff2_b    = (const float*)d_in[14];

    float *xbuf, *qkvb, *peb, *pbuf, *attb, *hbuf;
    cudaGetSymbolAddress((void**)&xbuf, g_x);
    cudaGetSymbolAddress((void**)&qkvb, g_qkv);
    cudaGetSymbolAddress((void**)&peb,  g_pe);
    cudaGetSymbolAddress((void**)&pbuf, g_p);
    cudaGetSymbolAddress((void**)&attb, g_att);
    cudaGetSymbolAddress((void**)&hbuf, g_h);

    cudaFuncSetAttribute(flash_kernel, cudaFuncAttributeMaxDynamicSharedMemorySize, FL_SMEM);
    cudaFuncSetAttribute(mma_gemm, cudaFuncAttributeMaxDynamicSharedMemorySize, MMA_SMEM);

    const int M = BB * TT;

    pe_kernel<<<PP, DM>>>();
    gemm_kernel<<<dim3(DM/128, M/128), 256>>>(x, embed_W, embed_b, nullptr, xbuf, M, DM, IND, 0);
    norm_kernel<<<M, DM>>>(xbuf);

    for (int l = 0; l < NL; l++) {
        mma_gemm<<<dim3(768/128, M/128), 256, MMA_SMEM>>>(
            xbuf, in_projW + (size_t)l*3*DM*DM, in_projb + (size_t)l*3*DM,
            nullptr, qkvb, M, 3*DM, DM, 0);
        mma_gemm<<<dim3(DM/128, 16), 256, MMA_SMEM>>>(
            peb, pos_W + (size_t)l*DM*DM, nullptr, nullptr, pbuf, PP, DM, DM, 0);
        flash_kernel<<<dim3(TT/64, NH, BB), 256, FL_SMEM>>>(
            qkvb, pbuf, pbu + (size_t)l*NH*DKK, pbv + (size_t)l*NH*DKK, lens, attb);
        mma_gemm<<<dim3(DM/128, M/128), 256, MMA_SMEM>>>(
            attb, out_W + (size_t)l*DM*DM, out_b + (size_t)l*DM, xbuf, xbuf, M, DM, DM, 0);
        mma_gemm<<<dim3(FFD/128, M/128), 256, MMA_SMEM>>>(
            xbuf, ff1_W + (size_t)l*FFD*DM, ff1_b + (size_t)l*FFD, nullptr, hbuf, M, FFD, DM, 1);
        mma_gemm<<<dim3(DM/128, M/128), 256, MMA_SMEM>>>(
            hbuf, ff2_W + (size_t)l*DM*FFD, ff2_b + (size_t)l*DM, xbuf, xbuf, M, DM, FFD, 0);
        norm_kernel<<<M, DM>>>(xbuf);
    }

    int n = BB * TT * DM;
    out_kernel<<<(n + 255)/256, 256>>>(xbuf, lens, (float*)d_out, out_size);
}

// round 15
// speedup vs baseline: 5.8548x; 1.2052x over previous
#include <cuda_runtime.h>
#include <math.h>
#include <stdint.h>

#define BB 8
#define TT 1024
#define IND 80
#define DM 256
#define NH 4
#define DKK 64
#define FFD 2048
#define NL 6
#define PP (2*TT-1)

// ---------------- device scratch (allocation-free) ----------------
__device__ float g_x[BB*TT*DM];
__device__ float g_qkv[BB*TT*3*DM];
__device__ float g_pe[PP*DM];
__device__ float g_p[PP*DM];
__device__ float g_att[BB*TT*DM];
__device__ float g_h[BB*TT*FFD];

// ================= helpers =================
__device__ __forceinline__ uint32_t smem_u32(const void* p) {
    uint32_t a;
    asm("{ .reg .u64 t; cvta.to.shared.u64 t, %1; cvt.u32.u64 %0, t; }" : "=r"(a) : "l"(p));
    return a;
}
__device__ __forceinline__ uint32_t prmt7632(uint32_t a, uint32_t b) {
    uint32_t r;
    asm("prmt.b32 %0, %1, %2, 0x7632;" : "=r"(r) : "r"(a), "r"(b));
    return r;
}
// pack two f32 into bf16x2 word: lo half = first, hi half = second
__device__ __forceinline__ uint32_t packbf(float lo, float hi) {
    uint32_t r;
    asm("cvt.rn.bf16x2.f32 %0, %1, %2;" : "=r"(r) : "f"(hi), "f"(lo));
    return r;
}
__device__ __forceinline__ float truncbf(float x) {
    return __uint_as_float(__float_as_uint(x) & 0xFFFF0000u);
}
__device__ __forceinline__ void ldsm4(uint32_t* r, uint32_t addr) {
    asm volatile("ldmatrix.sync.aligned.m8n8.x4.shared.b16 {%0,%1,%2,%3}, [%4];"
        : "=r"(r[0]), "=r"(r[1]), "=r"(r[2]), "=r"(r[3]) : "r"(addr));
}
__device__ __forceinline__ void mma_bf16(float* c, const uint32_t* a, const uint32_t* b) {
    asm volatile(
        "mma.sync.aligned.m16n8k16.row.col.f32.bf16.bf16.f32 "
        "{%0,%1,%2,%3}, {%4,%5,%6,%7}, {%8,%9}, {%0,%1,%2,%3};"
        : "+f"(c[0]), "+f"(c[1]), "+f"(c[2]), "+f"(c[3])
        : "r"(a[0]), "r"(a[1]), "r"(a[2]), "r"(a[3]), "r"(b[0]), "r"(b[1]));
}
#define STS4(addr, v) asm volatile("st.shared.v4.b32 [%0], {%1,%2,%3,%4};" :: "r"(addr), \
    "r"(__float_as_uint((v).x)), "r"(__float_as_uint((v).y)), \
    "r"(__float_as_uint((v).z)), "r"(__float_as_uint((v).w)) : "memory")
#define STS2(addr, v0, v1) asm volatile("st.shared.v2.b32 [%0], {%1,%2};" :: "r"(addr), \
    "r"(v0), "r"(v1) : "memory")
#define STS1(addr, v0) asm volatile("st.shared.b32 [%0], %1;" :: "r"(addr), "r"(v0) : "memory")

// ================= bf16x3 mma GEMM: C = A(MxK) @ W(NxK)^T =================
#define BSTRIDE 80
#define BTILE (128*BSTRIDE)
#define MMA_SMEM (4*BTILE)

__global__ __launch_bounds__(256) void mma_gemm(
    const float* __restrict__ A, const float* __restrict__ W,
    const float* __restrict__ bias, const float* __restrict__ res,
    float* __restrict__ C, int M, int N, int K, int act)
{
    extern __shared__ float dsm[];
    const uint32_t sb = smem_u32(dsm);
    const uint32_t sAH = sb, sAL = sb + BTILE, sBH = sb + 2*BTILE, sBL = sb + 3*BTILE;
    const int tid = threadIdx.x;
    const int wid = tid >> 5, lane = tid & 31;
    const int wm = wid >> 2, wn = wid & 3;
    const int bm = blockIdx.y * 128, bn = blockIdx.x * 128;

    float c[4][4][4];
#pragma unroll
    for (int mt = 0; mt < 4; mt++)
#pragma unroll
        for (int nt = 0; nt < 4; nt++)
#pragma unroll
            for (int q = 0; q < 4; q++) c[mt][nt][q] = 0.f;

    const int quad = lane >> 3, r8 = lane & 7;
    const int srow = tid >> 3, skq = tid & 7;
    const int nchunk = K / 32;

    float4 a_reg[4], w_reg[4];
#pragma unroll
    for (int e = 0; e < 4; e++) {
        int row = srow + e * 32;
        int ar = bm + row; if (ar >= M) ar = M - 1;
        a_reg[e] = *(const float4*)&A[(size_t)ar * K + skq * 4];
        w_reg[e] = *(const float4*)&W[(size_t)(bn + row) * K + skq * 4];
    }

    for (int cc = 0; cc < nchunk; cc++) {
        __syncthreads();
#pragma unroll
        for (int e = 0; e < 4; e++) {
            int row = srow + e * 32;
            uint32_t off = (uint32_t)(row * BSTRIDE + skq * 8);
            uint32_t r0 = __float_as_uint(a_reg[e].x), r1 = __float_as_uint(a_reg[e].y);
            uint32_t r2 = __float_as_uint(a_reg[e].z), r3 = __float_as_uint(a_reg[e].w);
            STS2(sAH + off, prmt7632(r0, r1), prmt7632(r2, r3));
            STS2(sAL + off,
                 packbf(a_reg[e].x - truncbf(a_reg[e].x), a_reg[e].y - truncbf(a_reg[e].y)),
                 packbf(a_reg[e].z - truncbf(a_reg[e].z), a_reg[e].w - truncbf(a_reg[e].w)));
            r0 = __float_as_uint(w_reg[e].x); r1 = __float_as_uint(w_reg[e].y);
            r2 = __float_as_uint(w_reg[e].z); r3 = __float_as_uint(w_reg[e].w);
            STS2(sBH + off, prmt7632(r0, r1), prmt7632(r2, r3));
            STS2(sBL + off,
                 packbf(w_reg[e].x - truncbf(w_reg[e].x), w_reg[e].y - truncbf(w_reg[e].y)),
                 packbf(w_reg[e].z - truncbf(w_reg[e].z), w_reg[e].w - truncbf(w_reg[e].w)));
        }
        __syncthreads();
        if (cc + 1 < nchunk) {
            const int k0 = (cc + 1) * 32;
#pragma unroll
            for (int e = 0; e < 4; e++) {
                int row = srow + e * 32;
                int ar = bm + row; if (ar >= M) ar = M - 1;
                a_reg[e] = *(const float4*)&A[(size_t)ar * K + k0 + skq * 4];
                w_reg[e] = *(const float4*)&W[(size_t)(bn + row) * K + k0 + skq * 4];
            }
        }
#pragma unroll
        for (int ks = 0; ks < 2; ks++) {
            uint32_t ah[4][4], al[4][4], bh[4][2], bl[4][2];
#pragma unroll
            for (int mt = 0; mt < 4; mt++) {
                uint32_t ao = (uint32_t)((wm * 64 + mt * 16 + r8 + (quad & 1) * 8) * BSTRIDE
                                         + ks * 32 + (quad >> 1) * 16);
                ldsm4(ah[mt], sAH + ao);
                ldsm4(al[mt], sAL + ao);
            }
#pragma unroll
            for (int ntp = 0; ntp < 2; ntp++) {
                uint32_t bo = (uint32_t)((wn * 32 + ntp * 16 + r8 + (quad >> 1) * 8) * BSTRIDE
                                         + ks * 32 + (quad & 1) * 16);
                uint32_t t[4];
                ldsm4(t, sBH + bo);
                bh[2*ntp][0] = t[0]; bh[2*ntp][1] = t[1];
                bh[2*ntp+1][0] = t[2]; bh[2*ntp+1][1] = t[3];
                ldsm4(t, sBL + bo);
                bl[2*ntp][0] = t[0]; bl[2*ntp][1] = t[1];
                bl[2*ntp+1][0] = t[2]; bl[2*ntp+1][1] = t[3];
            }
#pragma unroll
            for (int mt = 0; mt < 4; mt++)
#pragma unroll
                for (int nt = 0; nt < 4; nt++) {
                    mma_bf16(c[mt][nt], ah[mt], bh[nt]);
                    mma_bf16(c[mt][nt], ah[mt], bl[nt]);
                    mma_bf16(c[mt][nt], al[mt], bh[nt]);
                }
        }
    }

    const int g = lane >> 2, tq = lane & 3;
#pragma unroll
    for (int mt = 0; mt < 4; mt++) {
#pragma unroll
        for (int nt = 0; nt < 4; nt++) {
            int col = bn + wn * 32 + nt * 8 + tq * 2;
            float b0 = 0.f, b1 = 0.f;
            if (bias) { b0 = bias[col]; b1 = bias[col + 1]; }
#pragma unroll
            for (int half = 0; half < 2; half++) {
                int row = bm + wm * 64 + mt * 16 + g + half * 8;
                if (row >= M) continue;
                float v0 = c[mt][nt][half * 2 + 0] + b0;
                float v1 = c[mt][nt][half * 2 + 1] + b1;
                if (act == 1) {
                    v0 = v0 / (1.f + expf(1.f - v0));
                    v1 = v1 / (1.f + expf(1.f - v1));
                }
                if (res) {
                    const float2 r2 = *(const float2*)&res[(size_t)row * N + col];
                    v0 += r2.x; v1 += r2.y;
                }
                float2 o2; o2.x = v0; o2.y = v1;
                *(float2*)&C[(size_t)row * N + col] = o2;
            }
        }
    }
}

// ---------------- relative positional encoding ----------------
__global__ void pe_kernel() {
    int r = blockIdx.x;
    int d = threadIdx.x;
    float pos, sign;
    if (r < TT) { pos = (float)(TT - 1 - r); sign = 1.f; }
    else        { pos = (float)(r - TT + 1); sign = -1.f; }
    int j2 = (d >> 1) << 1;
    float div = expf(-(float)j2 * (logf(10000.f) / (float)DM));
    float ang = sign * pos * div;
    g_pe[r * DM + d] = (d & 1) ? cosf(ang) : sinf(ang);
}

// ---------------- fallback SGEMM (embed only) ----------------
__global__ __launch_bounds__(256) void gemm_kernel(
    const float* __restrict__ A, const float* __restrict__ W,
    const float* __restrict__ bias, const float* __restrict__ res,
    float* __restrict__ C, int M, int N, int K, int act)
{
    __shared__ float As[16][128];
    __shared__ float Bs[16][128];
    const int bm = blockIdx.y * 128;
    const int bn = blockIdx.x * 128;
    const int tid = threadIdx.x;
    const int tm = tid >> 4, tn = tid & 15;

    float acc[8][8];
#pragma unroll
    for (int i = 0; i < 8; i++)
#pragma unroll
        for (int j = 0; j < 8; j++) acc[i][j] = 0.f;

    for (int k0 = 0; k0 < K; k0 += 16) {
#pragma unroll
        for (int e = 0; e < 8; e++) {
            int flat = tid + e * 256;
            int row = flat >> 4, kk = flat & 15;
            int ar = bm + row;
            As[kk][row] = (ar < M) ? A[(size_t)ar * K + k0 + kk] : 0.f;
            int wr = bn + row;
            Bs[kk][row] = (wr < N) ? W[(size_t)wr * K + k0 + kk] : 0.f;
        }
        __syncthreads();
#pragma unroll
        for (int kk = 0; kk < 16; kk++) {
            float4 a0 = *(const float4*)&As[kk][tm * 8];
            float4 a1 = *(const float4*)&As[kk][tm * 8 + 4];
            float4 b0 = *(const float4*)&Bs[kk][tn * 8];
            float4 b1 = *(const float4*)&Bs[kk][tn * 8 + 4];
            float a[8] = {a0.x,a0.y,a0.z,a0.w,a1.x,a1.y,a1.z,a1.w};
            float b[8] = {b0.x,b0.y,b0.z,b0.w,b1.x,b1.y,b1.z,b1.w};
#pragma unroll
            for (int i = 0; i < 8; i++)
#pragma unroll
                for (int j = 0; j < 8; j++) acc[i][j] += a[i] * b[j];
        }
        __syncthreads();
    }
#pragma unroll
    for (int i = 0; i < 8; i++) {
        int row = bm + tm * 8 + i;
        if (row >= M) continue;
#pragma unroll
        for (int j = 0; j < 8; j++) {
            int col = bn + tn * 8 + j;
            float c = acc[i][j];
            if (bias) c += bias[col];
            if (act == 1) c = c / (1.f + expf(1.f - c));
            if (res) c += res[(size_t)row * N + col];
            C[(size_t)row * N + col] = c;
        }
    }
}

// ---------------- BasicNorm ----------------
__global__ __launch_bounds__(DM) void norm_kernel(float* __restrict__ x) {
    int row = blockIdx.x, tid = threadIdx.x;
    float v = x[(size_t)row * DM + tid];
    float s = v * v;
#pragma unroll
    for (int o = 16; o; o >>= 1) s += __shfl_xor_sync(0xffffffffu, s, o);
    __shared__ float sm[8];
    int warp = tid >> 5, lane = tid & 31;
    if (lane == 0) sm[warp] = s;
    __syncthreads();
    if (warp == 0) {
        float t = (lane < 8) ? sm[lane] : 0.f;
#pragma unroll
        for (int o = 4; o; o >>= 1) t += __shfl_xor_sync(0xffffffffu, t, o);
        if (lane == 0) sm[0] = t;
    }
    __syncthreads();
    float scale = rsqrtf(sm[0] / (float)DM + 0.25f);
    x[(size_t)row * DM + tid] = v * scale;
}

// ================= flash attention: bf16x3 scores, QP, AV =================
// bf16 tiles, byte offsets, row stride 144 B (16-aligned, ldsm conflict-free)
#define FSTR 144
#define FQUH 0
#define FQUL 9216
#define FQVH 18432
#define FQVL 27648
#define FKH  36864
#define FKL  46080
#define FVTH 55296
#define FVTL 64512
#define FPH  73728
#define FPL  92160
#define FSH  110592
#define FSL  119808
// f32 regions (float indices)
#define FQPf 32256
#define FSf  40448
#define FMRf 44800
#define FLRf 44864
#define FFRf 44928
#define FL_SMEM 179968

__global__ __launch_bounds__(256) void flash_kernel(
    const float* __restrict__ qkv, const float* __restrict__ p,
    const float* __restrict__ ub, const float* __restrict__ vb,
    const int* __restrict__ lens, float* __restrict__ att)
{
    extern __shared__ float sm[];
    const uint32_t sb = smem_u32(sm);
    const int i0 = blockIdx.x * 64;
    const int h  = blockIdx.y;
    const int b  = blockIdx.z;
    const int tid = threadIdx.x;
    const int wid = tid >> 5, lane = tid & 31;
    const int len = lens[b];

    // ---- prologue: qu/qv -> bf16 hi/lo tiles ----
#pragma unroll
    for (int e = 0; e < 4; e++) {
        int f4 = tid + e * 256;
        int row = f4 >> 4, c = (f4 & 15) * 4;
        float4 q4 = *(const float4*)&qkv[((size_t)(b * TT + i0 + row)) * 768 + h * DKK + c];
        float4 u4 = *(const float4*)&ub[h * DKK + c];
        float4 v4 = *(const float4*)&vb[h * DKK + c];
        float qu[4] = {q4.x+u4.x, q4.y+u4.y, q4.z+u4.z, q4.w+u4.w};
        float qv[4] = {q4.x+v4.x, q4.y+v4.y, q4.z+v4.z, q4.w+v4.w};
        uint32_t off = (uint32_t)(row * FSTR + c * 2);
        STS2(sb + FQUH + off, prmt7632(__float_as_uint(qu[0]), __float_as_uint(qu[1])),
                              prmt7632(__float_as_uint(qu[2]), __float_as_uint(qu[3])));
        STS2(sb + FQUL + off, packbf(qu[0]-truncbf(qu[0]), qu[1]-truncbf(qu[1])),
                              packbf(qu[2]-truncbf(qu[2]), qu[3]-truncbf(qu[3])));
        STS2(sb + FQVH + off, prmt7632(__float_as_uint(qv[0]), __float_as_uint(qv[1])),
                              prmt7632(__float_as_uint(qv[2]), __float_as_uint(qv[3])));
        STS2(sb + FQVL + off, packbf(qv[0]-truncbf(qv[0]), qv[1]-truncbf(qv[1])),
                              packbf(qv[2]-truncbf(qv[2]), qv[3]-truncbf(qv[3])));
    }
    if (tid < 64) { sm[FMRf + tid] = -3.4e38f; sm[FLRf + tid] = 0.f; }

    const int wmS = wid & 3, wnS = wid >> 2;      // 4x2 warp grid
    const int quad = lane >> 3, r8 = lane & 7;
    const uint32_t a_off = (uint32_t)((wmS * 16 + r8 + (quad & 1) * 8) * FSTR + (quad >> 1) * 16);
    uint32_t boS[2], boQ[4];
#pragma unroll
    for (int ntp = 0; ntp < 2; ntp++)
        boS[ntp] = (uint32_t)((wnS * 32 + ntp * 16 + r8 + (quad >> 1) * 8) * FSTR + (quad & 1) * 16);
#pragma unroll
    for (int ntp = 0; ntp < 4; ntp++)
        boQ[ntp] = (uint32_t)((wnS * 64 + ntp * 16 + r8 + (quad >> 1) * 8) * FSTR + (quad & 1) * 16);
    const int g = lane >> 2, tq = lane & 3;
    const int rg = tid >> 2, dg = tid & 3;

    float cO[4][4];
#pragma unroll
    for (int nt = 0; nt < 4; nt++)
#pragma unroll
        for (int q = 0; q < 4; q++) cO[nt][q] = 0.f;

    for (int j0 = 0; j0 <= i0; j0 += 64) {
        __syncthreads();
        // ---- stage K (rows j, packed d) and VT (rows d, packed j-pairs) ----
#pragma unroll
        for (int e = 0; e < 2; e++) {
            int idx = tid + e * 256;                 // 0..511
            int jp = idx >> 4, c = (idx & 15) * 4;
            const float* basea = &qkv[((size_t)(b * TT + j0 + 2 * jp)) * 768 + DM + h * DKK + c];
            float4 ka = *(const float4*)(basea);
            float4 kb = *(const float4*)(basea + 768);
            float4 va = *(const float4*)(basea + DM);
            float4 vb2 = *(const float4*)(basea + 768 + DM);
            uint32_t offa = (uint32_t)((2 * jp) * FSTR + c * 2);
            STS2(sb + FKH + offa, prmt7632(__float_as_uint(ka.x), __float_as_uint(ka.y)),
                                  prmt7632(__float_as_uint(ka.z), __float_as_uint(ka.w)));
            STS2(sb + FKL + offa, packbf(ka.x-truncbf(ka.x), ka.y-truncbf(ka.y)),
                                  packbf(ka.z-truncbf(ka.z), ka.w-truncbf(ka.w)));
            uint32_t offb = offa + FSTR;
            STS2(sb + FKH + offb, prmt7632(__float_as_uint(kb.x), __float_as_uint(kb.y)),
                                  prmt7632(__float_as_uint(kb.z), __float_as_uint(kb.w)));
            STS2(sb + FKL + offb, packbf(kb.x-truncbf(kb.x), kb.y-truncbf(kb.y)),
                                  packbf(kb.z-truncbf(kb.z), kb.w-truncbf(kb.w)));
            float vaa[4] = {va.x, va.y, va.z, va.w};
            float vbb[4] = {vb2.x, vb2.y, vb2.z, vb2.w};
#pragma unroll
            for (int i = 0; i < 4; i++) {
                uint32_t offv = (uint32_t)((c + i) * FSTR + jp * 4);
                STS1(sb + FVTH + offv, prmt7632(__float_as_uint(vaa[i]), __float_as_uint(vbb[i])));
                STS1(sb + FVTL + offv, packbf(vaa[i]-truncbf(vaa[i]), vbb[i]-truncbf(vbb[i])));
            }
        }
        // ---- stage P (rows r, packed d) ----
        const int pbase = TT - 1 - (i0 + 63) + j0;
#pragma unroll
        for (int e = 0; e < 8; e++) {
            int f4 = tid + e * 256;
            if (f4 < 127 * 16) {
                int r = f4 >> 4, c = (f4 & 15) * 4;
                float4 p4 = *(const float4*)&p[(size_t)(pbase + r) * DM + h * DKK + c];
                uint32_t off = (uint32_t)(r * FSTR + c * 2);
                STS2(sb + FPH + off, prmt7632(__float_as_uint(p4.x), __float_as_uint(p4.y)),
                                     prmt7632(__float_as_uint(p4.z), __float_as_uint(p4.w)));
                STS2(sb + FPL + off, packbf(p4.x-truncbf(p4.x), p4.y-truncbf(p4.y)),
                                     packbf(p4.z-truncbf(p4.z), p4.w-truncbf(p4.w)));
            }
        }
        __syncthreads();

        // ---- scores + QP via bf16x3 ----
        float cS[4][4], cQ[8][4];
#pragma unroll
        for (int nt = 0; nt < 4; nt++)
#pragma unroll
            for (int q = 0; q < 4; q++) cS[nt][q] = 0.f;
#pragma unroll
        for (int nt = 0; nt < 8; nt++)
#pragma unroll
            for (int q = 0; q < 4; q++) cQ[nt][q] = 0.f;

#pragma unroll
        for (int ks = 0; ks < 4; ks++) {
            uint32_t ao = a_off + ks * 32;
            uint32_t ah[4], al[4], th[4], tl[4];
            // S = qu . K^T
            ldsm4(ah, sb + FQUH + ao);
            ldsm4(al, sb + FQUL + ao);
#pragma unroll
            for (int ntp = 0; ntp < 2; ntp++) {
                uint32_t bo = boS[ntp] + ks * 32;
                ldsm4(th, sb + FKH + bo);
                ldsm4(tl, sb + FKL + bo);
#pragma unroll
                for (int k2 = 0; k2 < 2; k2++) {
                    int nt = ntp * 2 + k2;
                    uint32_t bhp[2] = {th[2*k2], th[2*k2+1]};
                    uint32_t blp[2] = {tl[2*k2], tl[2*k2+1]};
                    mma_bf16(cS[nt], ah, bhp);
                    mma_bf16(cS[nt], al, bhp);
                    mma_bf16(cS[nt], ah, blp);
                }
            }
            // QP = qv . P^T
            ldsm4(ah, sb + FQVH + ao);
            ldsm4(al, sb + FQVL + ao);
#pragma unroll
            for (int ntp = 0; ntp < 4; ntp++) {
                uint32_t bo = boQ[ntp] + ks * 32;
                ldsm4(th, sb + FPH + bo);
                ldsm4(tl, sb + FPL + bo);
#pragma unroll
                for (int k2 = 0; k2 < 2; k2++) {
                    int nt = ntp * 2 + k2;
                    uint32_t bhp[2] = {th[2*k2], th[2*k2+1]};
                    uint32_t blp[2] = {tl[2*k2], tl[2*k2+1]};
                    mma_bf16(cQ[nt], ah, bhp);
                    mma_bf16(cQ[nt], al, bhp);
                    mma_bf16(cQ[nt], ah, blp);
                }
            }
        }
        // write QP (f32)
#pragma unroll
        for (int nt = 0; nt < 8; nt++) {
            int col = wnS * 64 + nt * 8 + tq * 2;
#pragma unroll
            for (int half = 0; half < 2; half++) {
                int row = wmS * 16 + g + half * 8;
                sm[FQPf + row * 128 + col]     = cQ[nt][half * 2 + 0];
                sm[FQPf + row * 128 + col + 1] = cQ[nt][half * 2 + 1];
            }
        }
        __syncthreads();

        // ---- S epilogue: (cS + QP-shift) * scale -> FSf ----
#pragma unroll
        for (int nt = 0; nt < 4; nt++) {
            int col = wnS * 32 + nt * 8 + tq * 2;
#pragma unroll
            for (int half = 0; half < 2; half++) {
                int row = wmS * 16 + g + half * 8;
                int rsh = 63 - row + col;
                sm[FSf + row * 68 + col]     = (cS[nt][half*2+0] + sm[FQPf + row * 128 + rsh])     * 0.125f;
                sm[FSf + row * 68 + col + 1] = (cS[nt][half*2+1] + sm[FQPf + row * 128 + rsh + 1]) * 0.125f;
            }
        }
        __syncthreads();

        // ---- online softmax: FSf -> packed bf16 SH/SL ----
        {
            const int i = i0 + rg;
            const int base = FSf + rg * 68 + dg * 16;
            float ev[16];
            float mloc = -3.4e38f;
#pragma unroll
            for (int k = 0; k < 16; k++) {
                int j = j0 + dg * 16 + k;
                bool ok = (j <= i) && (j < len);
                float v = ok ? sm[base + k] : -3.4e38f;
                ev[k] = v;
                mloc = fmaxf(mloc, v);
            }
            mloc = fmaxf(mloc, __shfl_xor_sync(0xffffffffu, mloc, 1));
            mloc = fmaxf(mloc, __shfl_xor_sync(0xffffffffu, mloc, 2));
            float mold = sm[FMRf + rg];
            float mnew = fmaxf(mold, mloc);
            float fac = expf(mold - mnew);
            float ssum = 0.f;
#pragma unroll
            for (int k = 0; k < 16; k++) {
                float e = (ev[k] > -1e37f) ? expf(ev[k] - mnew) : 0.f;
                ev[k] = e;
                ssum += e;
            }
            ssum += __shfl_xor_sync(0xffffffffu, ssum, 1);
            ssum += __shfl_xor_sync(0xffffffffu, ssum, 2);
            uint32_t soff = (uint32_t)(rg * FSTR + dg * 32);
#pragma unroll
            for (int kp = 0; kp < 8; kp++) {
                float e0 = ev[2*kp], e1 = ev[2*kp+1];
                STS1(sb + FSH + soff + kp * 4,
                     prmt7632(__float_as_uint(e0), __float_as_uint(e1)));
                STS1(sb + FSL + soff + kp * 4,
                     packbf(e0 - truncbf(e0), e1 - truncbf(e1)));
            }
            if (dg == 0) {
                sm[FMRf + rg] = mnew;
                sm[FLRf + rg] = sm[FLRf + rg] * fac + ssum;
                sm[FFRf + rg] = fac;
            }
        }
        __syncthreads();

        // ---- AV via bf16x3: cO = cO*fac + exp(S) @ V ----
        {
            float fac0 = sm[FFRf + wmS * 16 + g];
            float fac1 = sm[FFRf + wmS * 16 + g + 8];
#pragma unroll
            for (int nt = 0; nt < 4; nt++) {
                cO[nt][0] *= fac0; cO[nt][1] *= fac0;
                cO[nt][2] *= fac1; cO[nt][3] *= fac1;
            }
#pragma unroll
            for (int ks = 0; ks < 4; ks++) {
                uint32_t ao = a_off + ks * 32;
                uint32_t ah[4], al[4], th[4], tl[4];
                ldsm4(ah, sb + FSH + ao);
                ldsm4(al, sb + FSL + ao);
#pragma unroll
                for (int ntp = 0; ntp < 2; ntp++) {
                    uint32_t bo = boS[ntp] + ks * 32;
                    ldsm4(th, sb + FVTH + bo);
                    ldsm4(tl, sb + FVTL + bo);
#pragma unroll
                    for (int k2 = 0; k2 < 2; k2++) {
                        int nt = ntp * 2 + k2;
                        uint32_t bhp[2] = {th[2*k2], th[2*k2+1]};
                        uint32_t blp[2] = {tl[2*k2], tl[2*k2+1]};
                        mma_bf16(cO[nt], ah, bhp);
                        mma_bf16(cO[nt], al, bhp);
                        mma_bf16(cO[nt], ah, blp);
                    }
                }
            }
        }
    }

    // ---- epilogue: O / l ----
#pragma unroll
    for (int nt = 0; nt < 4; nt++) {
        int col = wnS * 32 + nt * 8 + tq * 2;
#pragma unroll
        for (int half = 0; half < 2; half++) {
            int row = wmS * 16 + g + half * 8;
            float inv = 1.f / sm[FLRf + row];
            float2 o2;
            o2.x = cO[nt][half * 2 + 0] * inv;
            o2.y = cO[nt][half * 2 + 1] * inv;
            *(float2*)&att[((size_t)(b * TT + i0 + row)) * DM + h * DKK + col] = o2;
        }
    }
}

// ---------------- final copy ----------------
__global__ void out_kernel(const float* __restrict__ x, const int* __restrict__ lens,
                           float* __restrict__ out, int out_size) {
    int idx = blockIdx.x * 256 + threadIdx.x;
    const int n = BB * TT * DM;
    if (idx < n) out[idx] = x[idx];
    if (idx < BB && out_size >= n + BB) out[n + idx] = (float)lens[idx];
}

extern "C" void kernel_launch(void* const* d_in, const int* in_sizes, int n_in,
                              void* d_out, int out_size) {
    const float* x        = (const float*)d_in[0];
    const int*   lens     = (const int*)  d_in[1];
    const float* embed_W  = (const float*)d_in[2];
    const float* embed_b  = (const float*)d_in[3];
    const float* in_projW = (const float*)d_in[4];
    const float* in_projb = (const float*)d_in[5];
    const float* pos_W    = (const float*)d_in[6];
    const float* pbu      = (const float*)d_in[7];
    const float* pbv      = (const float*)d_in[8];
    const float* out_W    = (const float*)d_in[9];
    const float* out_b    = (const float*)d_in[10];
    const float* ff1_W    = (const float*)d_in[11];
    const float* ff1_b    = (const float*)d_in[12];
    const float* ff2_W    = (const float*)d_in[13];
    const float* ff2_b    = (const float*)d_in[14];

    float *xbuf, *qkvb, *peb, *pbuf, *attb, *hbuf;
    cudaGetSymbolAddress((void**)&xbuf, g_x);
    cudaGetSymbolAddress((void**)&qkvb, g_qkv);
    cudaGetSymbolAddress((void**)&peb,  g_pe);
    cudaGetSymbolAddress((void**)&pbuf, g_p);
    cudaGetSymbolAddress((void**)&attb, g_att);
    cudaGetSymbolAddress((void**)&hbuf, g_h);

    cudaFuncSetAttribute(flash_kernel, cudaFuncAttributeMaxDynamicSharedMemorySize, FL_SMEM);
    cudaFuncSetAttribute(mma_gemm, cudaFuncAttributeMaxDynamicSharedMemorySize, MMA_SMEM);

    const int M = BB * TT;

    pe_kernel<<<PP, DM>>>();
    gemm_kernel<<<dim3(DM/128, M/128), 256>>>(x, embed_W, embed_b, nullptr, xbuf, M, DM, IND, 0);
    norm_kernel<<<M, DM>>>(xbuf);

    for (int l = 0; l < NL; l++) {
        mma_gemm<<<dim3(768/128, M/128), 256, MMA_SMEM>>>(
            xbuf, in_projW + (size_t)l*3*DM*DM, in_projb + (size_t)l*3*DM,
            nullptr, qkvb, M, 3*DM, DM, 0);
        mma_gemm<<<dim3(DM/128, 16), 256, MMA_SMEM>>>(
            peb, pos_W + (size_t)l*DM*DM, nullptr, nullptr, pbuf, PP, DM, DM, 0);
        flash_kernel<<<dim3(TT/64, NH, BB), 256, FL_SMEM>>>(
            qkvb, pbuf, pbu + (size_t)l*NH*DKK, pbv + (size_t)l*NH*DKK, lens, attb);
        mma_gemm<<<dim3(DM/128, M/128), 256, MMA_SMEM>>>(
            attb, out_W + (size_t)l*DM*DM, out_b + (size_t)l*DM, xbuf, xbuf, M, DM, DM, 0);
        mma_gemm<<<dim3(FFD/128, M/128), 256, MMA_SMEM>>>(
            xbuf, ff1_W + (size_t)l*FFD*DM, ff1_b + (size_t)l*FFD, nullptr, hbuf, M, FFD, DM, 1);
        mma_gemm<<<dim3(DM/128, M/128), 256, MMA_SMEM>>>(
            hbuf, ff2_W + (size_t)l*DM*FFD, ff2_b + (size_t)l*DM, xbuf, xbuf, M, DM, FFD, 0);
        norm_kernel<<<M, DM>>>(xbuf);
    }

    int n = BB * TT * DM;
    out_kernel<<<(n + 255)/256, 256>>>(xbuf, lens, (float*)d_out, out_size);
}